// round 11
// baseline (speedup 1.0000x reference)
#include <cuda_runtime.h>
#include <cuda_bf16.h>
#include <cstdint>

// ---------------- problem constants ----------------
#define BATCH   4
#define LSEQ    4096
#define NTOK    (BATCH*LSEQ)       // 16384
#define DM      512
#define DI      512
#define DS      8
#define DTRANK  32
#define DBCW    48                 // DT_RANK + 2*D_STATE

// chunked scan config
#define NCH     64
#define TCH     (LSEQ/NCH)         // 64
#define NCHAN   (BATCH*DI)         // 2048
#define CHTOT   (NCHAN*NCH)        // 131072

// ---------------- scratch (device globals; no runtime alloc) ----------------
__device__ __nv_bfloat16 g_lnh[NTOK*DM];
__device__ __nv_bfloat16 g_lnl[NTOK*DM];
__device__ __nv_bfloat16 g_wih[2*DI*DM];
__device__ __nv_bfloat16 g_wil[2*DI*DM];
__device__ __nv_bfloat16 g_woh[DM*DI];
__device__ __nv_bfloat16 g_wol[DM*DI];
__device__ __nv_bfloat16 g_xwh0[DBCW*DI];
__device__ __nv_bfloat16 g_xwl0[DBCW*DI];
__device__ __nv_bfloat16 g_xwh1[DBCW*DI];
__device__ __nv_bfloat16 g_xwl1[DBCW*DI];
__device__ __nv_bfloat16 g_ynh[NTOK*DI];
__device__ __nv_bfloat16 g_ynl[NTOK*DI];
__device__ float g_xz  [NTOK*2*DI];
__device__ float g_dbc0[NTOK*DBCW];
__device__ float g_dbc1[NTOK*DBCW];
__device__ float g_y0  [NTOK*DI];
__device__ float g_y1  [NTOK*DI];
__device__ float g_P0  [DS*CHTOT];
__device__ float g_Q0  [DS*CHTOT];
__device__ float g_P1  [DS*CHTOT];
__device__ float g_Q1  [DS*CHTOT];
__device__ int   g_flags[2048];

// ---------------- helpers ----------------
__device__ __forceinline__ uint32_t smem_u32(const void* p) {
    uint32_t a;
    asm("{ .reg .u64 t; cvta.to.shared.u64 t, %1; cvt.u32.u64 %0, t; }" : "=r"(a) : "l"(p));
    return a;
}
__device__ __forceinline__ void ldsm4(uint32_t* r, uint32_t addr) {
    asm volatile("ldmatrix.sync.aligned.m8n8.x4.shared.b16 {%0,%1,%2,%3}, [%4];"
        : "=r"(r[0]), "=r"(r[1]), "=r"(r[2]), "=r"(r[3]) : "r"(addr));
}
__device__ __forceinline__ void mma16816(float* c, const uint32_t* a, const uint32_t* b) {
    asm volatile("mma.sync.aligned.m16n8k16.row.col.f32.bf16.bf16.f32 "
        "{%0,%1,%2,%3},{%4,%5,%6,%7},{%8,%9},{%0,%1,%2,%3};"
        : "+f"(c[0]), "+f"(c[1]), "+f"(c[2]), "+f"(c[3])
        : "r"(a[0]), "r"(a[1]), "r"(a[2]), "r"(a[3]), "r"(b[0]), "r"(b[1]));
}
__device__ __forceinline__ float silu(float v) { return v / (1.f + __expf(-v)); }

// ---------------- mma.sync split-bf16 GEMM, 256x128 tile, 2-stage -----------
#define KCH     64
#define NKCH    (512/KCH)          // 8
#define A_TILEB 32768              // 256x64 bf16
#define B_TILEB 16384              // 128x64 bf16
#define STG_SZ  (2*A_TILEB + 2*B_TILEB)   // 98304
#define MMA_SMEM (2*STG_SZ)               // 196608

__device__ __forceinline__ void mma_load_chunk(
    const __nv_bfloat16* __restrict__ Ah, const __nv_bfloat16* __restrict__ Al,
    const __nv_bfloat16* __restrict__ Bh, const __nv_bfloat16* __restrict__ Bl,
    int m0, int n0, int kc, uint32_t stage)
{
    const int t = threadIdx.x;
#pragma unroll
    for (int it = 0; it < 12; it++) {
        int idx = it * 512 + t;            // 0..6143 16B-chunks
        const __nv_bfloat16* gb;
        uint32_t toff;
        int local, base;
        if (idx < 4096) {
            int which = idx >> 11;
            local = idx & 2047;
            gb = which ? Al : Ah;
            toff = which ? A_TILEB : 0u;
            base = m0;
        } else {
            int idx2 = idx - 4096;
            int which = idx2 >> 10;
            local = idx2 & 1023;
            gb = which ? Bl : Bh;
            toff = 2 * A_TILEB + (which ? B_TILEB : 0);
            base = n0;
        }
        int row = local >> 3;
        int c   = local & 7;
        const void* ga = gb + (size_t)(base + row) * 512 + kc * KCH + c * 8;
        uint32_t sa = stage + toff + row * 128 + ((c ^ (row & 7)) << 4);
        asm volatile("cp.async.cg.shared.global [%0], [%1], 16;" :: "r"(sa), "l"(ga));
    }
}

template<bool RESID>
__global__ __launch_bounds__(512)
void k_mma(const __nv_bfloat16* __restrict__ Ah, const __nv_bfloat16* __restrict__ Al,
           const __nv_bfloat16* __restrict__ Bh, const __nv_bfloat16* __restrict__ Bl,
           float* __restrict__ C, int N, const float* __restrict__ resid)
{
    extern __shared__ __align__(128) char smem[];
    const uint32_t sb = smem_u32(smem);
    const int m0 = blockIdx.y * 256;
    const int n0 = blockIdx.x * 128;
    const int w  = threadIdx.x >> 5;
    const int lane = threadIdx.x & 31;
    const int wm = (w >> 2) * 64;
    const int wn = (w & 3) * 32;

    float acc[4][4][4];
#pragma unroll
    for (int i = 0; i < 4; i++)
#pragma unroll
        for (int j = 0; j < 4; j++)
#pragma unroll
            for (int q = 0; q < 4; q++) acc[i][j][q] = 0.f;

    const int ar  = lane & 15;
    const int ach = lane >> 4;
    const int bt8 = lane & 7;
    const int bn8 = (lane >> 4) << 3;
    const int bch = (lane >> 3) & 1;

    mma_load_chunk(Ah, Al, Bh, Bl, m0, n0, 0, sb);
    asm volatile("cp.async.commit_group;");
    mma_load_chunk(Ah, Al, Bh, Bl, m0, n0, 1, sb + STG_SZ);
    asm volatile("cp.async.commit_group;");

    for (int i = 0; i < NKCH; i++) {
        if (i < NKCH - 1) asm volatile("cp.async.wait_group 1;");
        else              asm volatile("cp.async.wait_group 0;");
        __syncthreads();

        const uint32_t stg = sb + (i & 1) * STG_SZ;
        const uint32_t sAh = stg, sAl = stg + A_TILEB;
        const uint32_t sBh = stg + 2 * A_TILEB, sBl = stg + 2 * A_TILEB + B_TILEB;

#pragma unroll
        for (int ks = 0; ks < 4; ks++) {
            uint32_t bh[2][4], bl[2][4];
#pragma unroll
            for (int ni = 0; ni < 2; ni++) {
                int n = wn + ni * 16 + bn8 + bt8;
                int c = ks * 2 + bch;
                uint32_t off = n * 128 + (((uint32_t)(c ^ (n & 7))) << 4);
                ldsm4(bh[ni], sBh + off);
                ldsm4(bl[ni], sBl + off);
            }
#pragma unroll
            for (int mih = 0; mih < 2; mih++) {
                uint32_t ah2[2][4], al2[2][4];
#pragma unroll
                for (int m2 = 0; m2 < 2; m2++) {
                    int r = wm + (mih * 2 + m2) * 16 + ar;
                    int c = ks * 2 + ach;
                    uint32_t off = r * 128 + (((uint32_t)(c ^ (r & 7))) << 4);
                    ldsm4(ah2[m2], sAh + off);
                    ldsm4(al2[m2], sAl + off);
                }
#pragma unroll
                for (int m2 = 0; m2 < 2; m2++)
#pragma unroll
                    for (int nj = 0; nj < 4; nj++) {
                        const uint32_t* bhp = &bh[nj >> 1][(nj & 1) * 2];
                        const uint32_t* blp = &bl[nj >> 1][(nj & 1) * 2];
                        float* ac = acc[mih * 2 + m2][nj];
                        mma16816(ac, ah2[m2], bhp);
                        mma16816(ac, ah2[m2], blp);
                        mma16816(ac, al2[m2], bhp);
                    }
            }
        }

        if (i < NKCH - 2) {
            __syncthreads();
            mma_load_chunk(Ah, Al, Bh, Bl, m0, n0, i + 2, stg);
            asm volatile("cp.async.commit_group;");
        }
    }

#pragma unroll
    for (int mi = 0; mi < 4; mi++) {
        int m = m0 + wm + mi * 16 + (lane >> 2);
#pragma unroll
        for (int nj = 0; nj < 4; nj++) {
            int n = n0 + wn + nj * 8 + ((lane & 3) << 1);
            float2 v0 = make_float2(acc[mi][nj][0], acc[mi][nj][1]);
            float2 v1 = make_float2(acc[mi][nj][2], acc[mi][nj][3]);
            if (RESID) {
                float2 r0 = *(const float2*)(resid + (size_t)m * N + n);
                float2 r1 = *(const float2*)(resid + (size_t)(m + 8) * N + n);
                v0.x += r0.x; v0.y += r0.y; v1.x += r1.x; v1.y += r1.y;
            }
            *(float2*)(C + (size_t)m * N + n)       = v0;
            *(float2*)(C + (size_t)(m + 8) * N + n) = v1;
        }
    }
}

// ---------------- x_proj: fused conv+silu A-build + split-bf16 mma ----------
// Tile 128(M) x 64(N, 48 valid), K-chunk 64, A built in-kernel, B cp.async x2.
#define XP_A    16384              // 128x64 bf16
#define XP_B    8192               // 64x64 bf16
#define XP_STG  (2*XP_A + 2*XP_B)  // 49152
#define XP_SMEM (2*XP_STG)         // 98304

__device__ __forceinline__ void xp_load_B(
    const __nv_bfloat16* __restrict__ Wh, const __nv_bfloat16* __restrict__ Wl,
    int kc, uint32_t stage)
{
    const int t = threadIdx.x;
#pragma unroll
    for (int it = 0; it < 3; it++) {
        int idx = it * 256 + t;            // 0..767
        int which = idx >= 384;
        int local = idx - which * 384;
        int row = local >> 3;              // 0..47
        int c   = local & 7;
        const void* ga = (which ? Wl : Wh) + (size_t)row * 512 + kc * KCH + c * 8;
        uint32_t sa = stage + 2 * XP_A + which * XP_B + row * 128 + ((c ^ (row & 7)) << 4);
        asm volatile("cp.async.cg.shared.global [%0], [%1], 16;" :: "r"(sa), "l"(ga));
    }
}

__global__ __launch_bounds__(256)
void k_xproj(const float* __restrict__ xz,
             const float* __restrict__ cw0, const float* __restrict__ cb0,
             const float* __restrict__ cw1, const float* __restrict__ cb1,
             const __nv_bfloat16* __restrict__ xwh0, const __nv_bfloat16* __restrict__ xwl0,
             const __nv_bfloat16* __restrict__ xwh1, const __nv_bfloat16* __restrict__ xwl1,
             float* __restrict__ C0, float* __restrict__ C1)
{
    extern __shared__ __align__(128) char smem[];
    const uint32_t sb = smem_u32(smem);
    const int br = blockIdx.y;
    const int m0 = blockIdx.x * 128;
    const int t  = threadIdx.x;
    const int w  = t >> 5;
    const int lane = t & 31;

    const float* cw = br ? cw1 : cw0;
    const float* cb = br ? cb1 : cb0;
    const __nv_bfloat16* Wh = br ? xwh1 : xwh0;
    const __nv_bfloat16* Wl = br ? xwl1 : xwl0;
    float* C = br ? C1 : C0;

    const int s0  = m0 & (LSEQ - 1);
    const int bb  = m0 >> 12;
    const int g0  = br ? (bb * LSEQ + LSEQ - 1 - s0) : m0;  // gmem row of scan row 0
    const int dir = br ? -1 : 1;

    // zero B pad rows (48..63) of both stages/tiles once
    for (int i = t; i < 2048; i += 256) {
        int region = i >> 9;               // 0..3: stage0(hi),(lo),stage1(hi),(lo)
        uint32_t off = (region >> 1) * XP_STG + 2 * XP_A + (region & 1) * XP_B
                     + 6144 + (i & 511) * 4;
        *(uint32_t*)(smem + off) = 0u;
    }

    xp_load_B(Wh, Wl, 0, sb);
    asm volatile("cp.async.commit_group;");
    xp_load_B(Wh, Wl, 1, sb + XP_STG);
    asm volatile("cp.async.commit_group;");

    // convert-thread mapping: 16 d-quads x 16 row-groups of 8
    const int dq = t & 15;
    const int rg = t >> 4;
    const int d  = dq * 4;
    const int r_lo = rg * 8;

    // mma thread constants
    const int wm = (w >> 1) * 32;
    const int wn = (w & 1) * 32;
    const int ar  = lane & 15;
    const int ach = lane >> 4;
    const int bt8 = lane & 7;
    const int bn8 = (lane >> 4) << 3;
    const int bch = (lane >> 3) & 1;

    float acc[2][4][4];
#pragma unroll
    for (int i = 0; i < 2; i++)
#pragma unroll
        for (int j = 0; j < 4; j++)
#pragma unroll
            for (int q = 0; q < 4; q++) acc[i][j][q] = 0.f;

    for (int i = 0; i < NKCH; i++) {
        const uint32_t stg = sb + (i & 1) * XP_STG;
        // ---- build A tile (conv + silu + hi/lo split), direct gmem loads ----
        {
            const int ch = i * KCH + d;          // GLOBAL channel for this chunk
            // conv weights/bias for channels ch..ch+3 (bug fix: was chunk-0 only)
            float4 cwa  = *(const float4*)(cw + ch * 2);       // w0,w1 [ch], [ch+1]
            float4 cwb2 = *(const float4*)(cw + ch * 2 + 4);   // w0,w1 [ch+2], [ch+3]
            float4 cbv  = *(const float4*)(cb + ch);

            const bool hasprev = (s0 + r_lo) > 0;
            const float* basep = xz + ch;
            float4 xprev = hasprev
                ? *(const float4*)(basep + (size_t)(g0 + dir * (r_lo - 1)) * (2 * DI))
                : make_float4(0.f, 0.f, 0.f, 0.f);
#pragma unroll
            for (int j = 0; j < 8; j++) {
                const int r = r_lo + j;
                float4 xc = *(const float4*)(basep + (size_t)(g0 + dir * r) * (2 * DI));
                float u0 = silu(fmaf(cwa.x,  xprev.x, fmaf(cwa.y,  xc.x, cbv.x)));
                float u1 = silu(fmaf(cwa.z,  xprev.y, fmaf(cwa.w,  xc.y, cbv.y)));
                float u2 = silu(fmaf(cwb2.x, xprev.z, fmaf(cwb2.y, xc.z, cbv.z)));
                float u3 = silu(fmaf(cwb2.z, xprev.w, fmaf(cwb2.w, xc.w, cbv.w)));
                xprev = xc;
                __nv_bfloat16 h0 = __float2bfloat16(u0), h1 = __float2bfloat16(u1);
                __nv_bfloat16 h2 = __float2bfloat16(u2), h3 = __float2bfloat16(u3);
                __nv_bfloat16 l0 = __float2bfloat16(u0 - __bfloat162float(h0));
                __nv_bfloat16 l1 = __float2bfloat16(u1 - __bfloat162float(h1));
                __nv_bfloat16 l2 = __float2bfloat16(u2 - __bfloat162float(h2));
                __nv_bfloat16 l3 = __float2bfloat16(u3 - __bfloat162float(h3));
                const int c16 = d >> 3;
                uint32_t off = (i & 1) * XP_STG + r * 128
                             + ((uint32_t)(c16 ^ (r & 7)) << 4) + (d & 7) * 2;
                uint2 hv, lv;
                __nv_bfloat162 p;
                p = __nv_bfloat162(h0, h1); hv.x = *(uint32_t*)&p;
                p = __nv_bfloat162(h2, h3); hv.y = *(uint32_t*)&p;
                p = __nv_bfloat162(l0, l1); lv.x = *(uint32_t*)&p;
                p = __nv_bfloat162(l2, l3); lv.y = *(uint32_t*)&p;
                *(uint2*)(smem + off)        = hv;
                *(uint2*)(smem + off + XP_A) = lv;
            }
        }
        // ---- wait B[i], sync (also publishes A tile) ----
        if (i < NKCH - 1) asm volatile("cp.async.wait_group 1;");
        else              asm volatile("cp.async.wait_group 0;");
        __syncthreads();

        const uint32_t sAh = stg, sAl = stg + XP_A;
        const uint32_t sBh = stg + 2 * XP_A, sBl = stg + 2 * XP_A + XP_B;
#pragma unroll
        for (int ks = 0; ks < 4; ks++) {
            uint32_t ah[2][4], al[2][4], bh[2][4], bl[2][4];
#pragma unroll
            for (int mi = 0; mi < 2; mi++) {
                int r = wm + mi * 16 + ar;
                int c = ks * 2 + ach;
                uint32_t off = r * 128 + (((uint32_t)(c ^ (r & 7))) << 4);
                ldsm4(ah[mi], sAh + off);
                ldsm4(al[mi], sAl + off);
            }
#pragma unroll
            for (int ni = 0; ni < 2; ni++) {
                int n = wn + ni * 16 + bn8 + bt8;
                int c = ks * 2 + bch;
                uint32_t off = n * 128 + (((uint32_t)(c ^ (n & 7))) << 4);
                ldsm4(bh[ni], sBh + off);
                ldsm4(bl[ni], sBl + off);
            }
#pragma unroll
            for (int mi = 0; mi < 2; mi++)
#pragma unroll
                for (int nj = 0; nj < 4; nj++) {
                    const uint32_t* bhp = &bh[nj >> 1][(nj & 1) * 2];
                    const uint32_t* blp = &bl[nj >> 1][(nj & 1) * 2];
                    mma16816(acc[mi][nj], ah[mi], bhp);
                    mma16816(acc[mi][nj], ah[mi], blp);
                    mma16816(acc[mi][nj], al[mi], bhp);
                }
        }

        if (i < NKCH - 2) {
            __syncthreads();   // B[stage s] reads done in all warps
            xp_load_B(Wh, Wl, i + 2, stg);
            asm volatile("cp.async.commit_group;");
        }
    }

    // epilogue: C is [NTOK][48]
#pragma unroll
    for (int mi = 0; mi < 2; mi++) {
        int m = m0 + wm + mi * 16 + (lane >> 2);
#pragma unroll
        for (int nj = 0; nj < 4; nj++) {
            int n = wn + nj * 8 + ((lane & 3) << 1);
            if (n < DBCW) {
                *(float2*)(C + (size_t)m * DBCW + n) =
                    make_float2(acc[mi][nj][0], acc[mi][nj][1]);
                *(float2*)(C + (size_t)(m + 8) * DBCW + n) =
                    make_float2(acc[mi][nj][2], acc[mi][nj][3]);
            }
        }
    }
}

// ---------------- fp32 -> bf16 hi/lo weight convert (4 weights, 1 launch) ----
__global__ void k_cvt4(const float* __restrict__ w1, __nv_bfloat16* __restrict__ h1,
                       __nv_bfloat16* __restrict__ l1, int n1,
                       const float* __restrict__ w2, __nv_bfloat16* __restrict__ h2,
                       __nv_bfloat16* __restrict__ l2, int n2,
                       const float* __restrict__ w3, __nv_bfloat16* __restrict__ h3,
                       __nv_bfloat16* __restrict__ l3, int n3,
                       const float* __restrict__ w4, __nv_bfloat16* __restrict__ h4,
                       __nv_bfloat16* __restrict__ l4, int n4)
{
    int i = blockIdx.x * blockDim.x + threadIdx.x;
    const float* w; __nv_bfloat16 *hh, *ll; int j;
    if (i < n1)                     { w = w1; hh = h1; ll = l1; j = i; }
    else if (i < n1+n2)             { w = w2; hh = h2; ll = l2; j = i-n1; }
    else if (i < n1+n2+n3)          { w = w3; hh = h3; ll = l3; j = i-n1-n2; }
    else if (i < n1+n2+n3+n4)       { w = w4; hh = h4; ll = l4; j = i-n1-n2-n3; }
    else return;
    float v = w[j];
    __nv_bfloat16 h = __float2bfloat16(v);
    hh[j] = h;
    ll[j] = __float2bfloat16(v - __bfloat162float(h));
}

// ---------------- LayerNorm -> bf16 hi/lo ----------------
__global__ void k_layernorm(const float* __restrict__ x,
                            const float* __restrict__ w,
                            const float* __restrict__ b,
                            __nv_bfloat16* __restrict__ oh,
                            __nv_bfloat16* __restrict__ ol)
{
    int tok  = blockIdx.x * 8 + (threadIdx.x >> 5);
    int lane = threadIdx.x & 31;
    const float* row = x + (size_t)tok * DM;

    float4 v[4];
    float s = 0.f, s2 = 0.f;
#pragma unroll
    for (int i = 0; i < 4; i++) {
        v[i] = *(const float4*)(row + i * 128 + lane * 4);
        s  += v[i].x + v[i].y + v[i].z + v[i].w;
        s2 += v[i].x*v[i].x + v[i].y*v[i].y + v[i].z*v[i].z + v[i].w*v[i].w;
    }
#pragma unroll
    for (int o = 16; o; o >>= 1) {
        s  += __shfl_xor_sync(0xffffffffu, s,  o);
        s2 += __shfl_xor_sync(0xffffffffu, s2, o);
    }
    float mu   = s * (1.f / DM);
    float var  = s2 * (1.f / DM) - mu * mu;
    float rinv = rsqrtf(var + 1e-5f);

#pragma unroll
    for (int i = 0; i < 4; i++) {
        int d = i * 128 + lane * 4;
        float4 w4 = *(const float4*)(w + d);
        float4 b4 = *(const float4*)(b + d);
        float o4[4];
        o4[0] = (v[i].x - mu) * rinv * w4.x + b4.x;
        o4[1] = (v[i].y - mu) * rinv * w4.y + b4.y;
        o4[2] = (v[i].z - mu) * rinv * w4.z + b4.z;
        o4[3] = (v[i].w - mu) * rinv * w4.w + b4.w;
        __nv_bfloat16 hh[4], ll[4];
#pragma unroll
        for (int q = 0; q < 4; q++) {
            hh[q] = __float2bfloat16(o4[q]);
            ll[q] = __float2bfloat16(o4[q] - __bfloat162float(hh[q]));
        }
        *(uint2*)(oh + (size_t)tok * DM + d) = *(uint2*)hh;
        *(uint2*)(ol + (size_t)tok * DM + d) = *(uint2*)ll;
    }
}

// ---------------- zero lookback flags ----------------
__global__ void k_zero(int* __restrict__ flags) {
    flags[blockIdx.x * 1024 + threadIdx.x] = 0;
}

// ---------------- fused conv + dt_proj + softplus + lookback scan -----------
#define SCAN_SMEM (TCH*128*4 + TCH*49*4)   // 32768 + 12544 = 45312

__global__ __launch_bounds__(128)
void k_scan(const float* __restrict__ xz,
            const float* __restrict__ dbc0, const float* __restrict__ dbc1,
            const float* __restrict__ cw0,  const float* __restrict__ cb0,
            const float* __restrict__ cw1,  const float* __restrict__ cb1,
            const float* __restrict__ Alog0, const float* __restrict__ Alog1,
            const float* __restrict__ dtw0, const float* __restrict__ dtw1,
            const float* __restrict__ dtb0, const float* __restrict__ dtb1,
            const float* __restrict__ Dp0,  const float* __restrict__ Dp1,
            float* __restrict__ y0g, float* __restrict__ y1g,
            float* __restrict__ P0g, float* __restrict__ Q0g,
            float* __restrict__ P1g, float* __restrict__ Q1g,
            int* __restrict__ flags)
{
    extern __shared__ float sm[];
    float* delta_s = sm;                 // [TCH][128]
    float* dbc_s   = sm + TCH * 128;     // [TCH][49]

    const int t  = threadIdx.x;
    const int dg = blockIdx.x;
    const int b  = blockIdx.y;
    const int br = blockIdx.z & 1;
    const int chunk = blockIdx.z >> 1;
    const int d  = dg * 128 + t;

    const float* dbc = br ? dbc1 : dbc0;
    const float* Alg = br ? Alog1 : Alog0;
    const float* Wdt = br ? dtw1 : dtw0;
    const float* Bdt = br ? dtb1 : dtb0;
    const float* Dpp = br ? Dp1  : Dp0;
    const float* cwp = br ? cw1 : cw0;
    const float* cbp = br ? cb1 : cb0;
    float* y  = br ? y1g : y0g;
    float* Pg = br ? P1g : P0g;
    float* Qg = br ? Q1g : Q0g;

    for (int i = t; i < 128 * 32; i += 128) {
        int rw_ = i >> 5, k = i & 31;
        sm[rw_ * 33 + k] = Wdt[(size_t)(dg * 128) * 32 + i];
    }
    const int tok0 = b * LSEQ + chunk * TCH;
    for (int i = t; i < TCH * 48; i += 128)
        dbc_s[(i / 48) * 49 + (i % 48)] = dbc[(size_t)tok0 * 48 + i];
    __syncthreads();
    float w[32];
#pragma unroll
    for (int k = 0; k < 32; k++) w[k] = sm[t * 33 + k];
    __syncthreads();

    float Av[DS];
    {
        float4 a0 = *(const float4*)(Alg + d * DS);
        float4 a1 = *(const float4*)(Alg + d * DS + 4);
        Av[0] = -__expf(a0.x); Av[1] = -__expf(a0.y); Av[2] = -__expf(a0.z); Av[3] = -__expf(a0.w);
        Av[4] = -__expf(a1.x); Av[5] = -__expf(a1.y); Av[6] = -__expf(a1.z); Av[7] = -__expf(a1.w);
    }
    const float Av0 = Av[0];
    bool uni = true;
#pragma unroll
    for (int n = 1; n < DS; n++)
        uni = uni && (fabsf(Av[n] - (n + 1) * Av0) <= 2e-5f * (n + 1));

    const float bias = Bdt[d];
    const float Dd   = Dpp[d];
    const float cwd0 = cwp[d * 2], cwd1 = cwp[d * 2 + 1], cbd = cbp[d];

    const int s0  = chunk * TCH;
    const int r0  = br ? (b * LSEQ + LSEQ - 1 - s0) : tok0;
    const int dir = br ? -1 : 1;

    float h[DS], P[DS], S = 0.f;
#pragma unroll
    for (int n = 0; n < DS; n++) { h[n] = 0.f; P[n] = 1.f; }

    float xprev = (s0 > 0) ? xz[(size_t)(r0 - dir) * (2 * DI) + d] : 0.f;
    for (int tt = 0; tt < TCH; tt++) {
        float xcur = xz[(size_t)(r0 + dir * tt) * (2 * DI) + d];
        float u = silu(fmaf(cwd0, xprev, fmaf(cwd1, xcur, cbd)));
        xprev = xcur;

        const float* row = &dbc_s[tt * 49];
        float a0 = bias, a1 = 0.f, a2 = 0.f, a3 = 0.f;
#pragma unroll
        for (int k = 0; k < 32; k += 4) {
            a0 = fmaf(row[k + 0], w[k + 0], a0);
            a1 = fmaf(row[k + 1], w[k + 1], a1);
            a2 = fmaf(row[k + 2], w[k + 2], a2);
            a3 = fmaf(row[k + 3], w[k + 3], a3);
        }
        float v = (a0 + a1) + (a2 + a3);
        float dl = (v > 20.f) ? v : log1pf(__expf(v));
        delta_s[tt * 128 + t] = dl;
        float du = dl * u;
        if (uni) {
            S += dl;
            float e1 = __expf(dl * Av0);
            float an = 1.f;
#pragma unroll
            for (int n = 0; n < DS; n++) {
                an *= e1;
                h[n] = fmaf(an, h[n], du * row[32 + n]);
            }
        } else {
#pragma unroll
            for (int n = 0; n < DS; n++) {
                float a = __expf(dl * Av[n]);
                P[n] *= a;
                h[n] = fmaf(a, h[n], du * row[32 + n]);
            }
        }
    }
    if (uni) {
#pragma unroll
        for (int n = 0; n < DS; n++) P[n] = __expf(S * Av[n]);
    }

    const int cidx = chunk * NCHAN + b * DI + d;
    {
        *(float4*)(Pg + (size_t)cidx * 8)     = make_float4(P[0], P[1], P[2], P[3]);
        *(float4*)(Pg + (size_t)cidx * 8 + 4) = make_float4(P[4], P[5], P[6], P[7]);
        *(float4*)(Qg + (size_t)cidx * 8)     = make_float4(h[0], h[1], h[2], h[3]);
        *(float4*)(Qg + (size_t)cidx * 8 + 4) = make_float4(h[4], h[5], h[6], h[7]);
    }
    __threadfence();
    __syncthreads();
    if (t == 0) {
        int fi = blockIdx.z * 16 + b * 4 + dg;
        asm volatile("st.global.release.gpu.b32 [%0], %1;" :: "l"(flags + fi), "r"(1) : "memory");
    }

    float h0[DS], pref[DS];
#pragma unroll
    for (int n = 0; n < DS; n++) { h0[n] = 0.f; pref[n] = 1.f; }
    for (int j = chunk - 1; j >= 0; j--) {
        const int fj = (j * 2 + br) * 16 + b * 4 + dg;
        int f;
        do {
            asm volatile("ld.global.acquire.gpu.b32 %0, [%1];" : "=r"(f) : "l"(flags + fj) : "memory");
            if (!f) __nanosleep(64);
        } while (!f);
        const size_t idxj = (size_t)(j * NCHAN + b * DI + d) * 8;
        float4 qa = *(const float4*)(Qg + idxj);
        float4 qb = *(const float4*)(Qg + idxj + 4);
        float4 pa = *(const float4*)(Pg + idxj);
        float4 pb = *(const float4*)(Pg + idxj + 4);
        float qv[DS] = { qa.x, qa.y, qa.z, qa.w, qb.x, qb.y, qb.z, qb.w };
        float pv2[DS] = { pa.x, pa.y, pa.z, pa.w, pb.x, pb.y, pb.z, pb.w };
#pragma unroll
        for (int n = 0; n < DS; n++) {
            h0[n] = fmaf(pref[n], qv[n], h0[n]);
            pref[n] *= pv2[n];
        }
    }

#pragma unroll
    for (int n = 0; n < DS; n++) h[n] = h0[n];
    xprev = (s0 > 0) ? xz[(size_t)(r0 - dir) * (2 * DI) + d] : 0.f;
    for (int tt = 0; tt < TCH; tt++) {
        float xcur = xz[(size_t)(r0 + dir * tt) * (2 * DI) + d];
        float u = silu(fmaf(cwd0, xprev, fmaf(cwd1, xcur, cbd)));
        xprev = xcur;

        float dl = delta_s[tt * 128 + t];
        float du = dl * u;
        const float* row = &dbc_s[tt * 49];
        float yv = 0.f;
        if (uni) {
            float e1 = __expf(dl * Av0);
            float an = 1.f;
#pragma unroll
            for (int n = 0; n < DS; n++) {
                an *= e1;
                h[n] = fmaf(an, h[n], du * row[32 + n]);
                yv = fmaf(h[n], row[40 + n], yv);
            }
        } else {
#pragma unroll
            for (int n = 0; n < DS; n++) {
                float a = __expf(dl * Av[n]);
                h[n] = fmaf(a, h[n], du * row[32 + n]);
                yv = fmaf(h[n], row[40 + n], yv);
            }
        }
        y[(size_t)(tok0 + tt) * DI + d] = fmaf(u, Dd, yv);
    }
}

// ---------------- combine branches, gate, RMSNorm -> bf16 hi/lo ---------------
__global__ void k_rms(const float* __restrict__ yf, const float* __restrict__ yb,
                      const float* __restrict__ xz, const float* __restrict__ rw,
                      __nv_bfloat16* __restrict__ oh, __nv_bfloat16* __restrict__ ol)
{
    int tok  = blockIdx.x * 8 + (threadIdx.x >> 5);
    int lane = threadIdx.x & 31;
    int s    = tok & (LSEQ - 1);
    int rtok = tok - s + (LSEQ - 1 - s);

    float4 v[4];
    float ss = 0.f;
#pragma unroll
    for (int i = 0; i < 4; i++) {
        int d = i * 128 + lane * 4;
        float4 a = *(const float4*)(yf + (size_t)tok * DI + d);
        float4 c = *(const float4*)(yb + (size_t)rtok * DI + d);
        float4 z = *(const float4*)(xz + (size_t)tok * (2 * DI) + DI + d);
        float4 o;
        o.x = 0.5f * (a.x + c.x) * silu(z.x);
        o.y = 0.5f * (a.y + c.y) * silu(z.y);
        o.z = 0.5f * (a.z + c.z) * silu(z.z);
        o.w = 0.5f * (a.w + c.w) * silu(z.w);
        ss += o.x*o.x + o.y*o.y + o.z*o.z + o.w*o.w;
        v[i] = o;
    }
#pragma unroll
    for (int o = 16; o; o >>= 1) ss += __shfl_xor_sync(0xffffffffu, ss, o);
    float sc = rsqrtf(ss * (1.f / DI) + 1e-5f);

#pragma unroll
    for (int i = 0; i < 4; i++) {
        int d = i * 128 + lane * 4;
        float4 w4 = *(const float4*)(rw + d);
        float o4[4];
        o4[0] = v[i].x * sc * w4.x;
        o4[1] = v[i].y * sc * w4.y;
        o4[2] = v[i].z * sc * w4.z;
        o4[3] = v[i].w * sc * w4.w;
        __nv_bfloat16 hh[4], ll[4];
#pragma unroll
        for (int q = 0; q < 4; q++) {
            hh[q] = __float2bfloat16(o4[q]);
            ll[q] = __float2bfloat16(o4[q] - __bfloat162float(hh[q]));
        }
        *(uint2*)(oh + (size_t)tok * DI + d) = *(uint2*)hh;
        *(uint2*)(ol + (size_t)tok * DI + d) = *(uint2*)ll;
    }
}

// ---------------- host launch ----------------
extern "C" void kernel_launch(void* const* d_in, const int* in_sizes, int n_in,
                              void* d_out, int out_size)
{
    const float* x          = (const float*)d_in[0];
    const float* ln_w       = (const float*)d_in[1];
    const float* ln_b       = (const float*)d_in[2];
    const float* in_proj_w  = (const float*)d_in[3];
    const float* conv_w     = (const float*)d_in[4];
    const float* conv_b     = (const float*)d_in[5];
    const float* x_proj_w   = (const float*)d_in[6];
    const float* dt_proj_w  = (const float*)d_in[7];
    const float* dt_proj_b  = (const float*)d_in[8];
    const float* A_log      = (const float*)d_in[9];
    const float* Dp         = (const float*)d_in[10];
    const float* conv_w_b   = (const float*)d_in[11];
    const float* conv_b_b   = (const float*)d_in[12];
    const float* x_proj_w_b = (const float*)d_in[13];
    const float* dt_proj_w_b= (const float*)d_in[14];
    const float* dt_proj_b_b= (const float*)d_in[15];
    const float* A_log_b    = (const float*)d_in[16];
    const float* D_b        = (const float*)d_in[17];
    const float* rms_w      = (const float*)d_in[18];
    const float* out_proj_w = (const float*)d_in[19];
    float* out = (float*)d_out;

    __nv_bfloat16 *lnh, *lnl, *wih, *wil, *woh, *wol, *ynh, *ynl;
    __nv_bfloat16 *xwh0, *xwl0, *xwh1, *xwl1;
    float *xz, *dbc0, *dbc1, *y0, *y1;
    float *P0, *Q0, *P1, *Q1;
    int* flags;
    cudaGetSymbolAddress((void**)&lnh,  g_lnh);
    cudaGetSymbolAddress((void**)&lnl,  g_lnl);
    cudaGetSymbolAddress((void**)&wih,  g_wih);
    cudaGetSymbolAddress((void**)&wil,  g_wil);
    cudaGetSymbolAddress((void**)&woh,  g_woh);
    cudaGetSymbolAddress((void**)&wol,  g_wol);
    cudaGetSymbolAddress((void**)&xwh0, g_xwh0);
    cudaGetSymbolAddress((void**)&xwl0, g_xwl0);
    cudaGetSymbolAddress((void**)&xwh1, g_xwh1);
    cudaGetSymbolAddress((void**)&xwl1, g_xwl1);
    cudaGetSymbolAddress((void**)&ynh,  g_ynh);
    cudaGetSymbolAddress((void**)&ynl,  g_ynl);
    cudaGetSymbolAddress((void**)&xz,   g_xz);
    cudaGetSymbolAddress((void**)&dbc0, g_dbc0);
    cudaGetSymbolAddress((void**)&dbc1, g_dbc1);
    cudaGetSymbolAddress((void**)&y0,   g_y0);
    cudaGetSymbolAddress((void**)&y1,   g_y1);
    cudaGetSymbolAddress((void**)&P0,   g_P0);
    cudaGetSymbolAddress((void**)&Q0,   g_Q0);
    cudaGetSymbolAddress((void**)&P1,   g_P1);
    cudaGetSymbolAddress((void**)&Q1,   g_Q1);
    cudaGetSymbolAddress((void**)&flags, g_flags);

    cudaFuncSetAttribute(k_mma<false>, cudaFuncAttributeMaxDynamicSharedMemorySize, MMA_SMEM);
    cudaFuncSetAttribute(k_mma<true>,  cudaFuncAttributeMaxDynamicSharedMemorySize, MMA_SMEM);
    cudaFuncSetAttribute(k_xproj, cudaFuncAttributeMaxDynamicSharedMemorySize, XP_SMEM);
    cudaFuncSetAttribute(k_scan, cudaFuncAttributeMaxDynamicSharedMemorySize, SCAN_SMEM);

    // 0. convert weights to bf16 hi/lo (single launch)
    int ncvt = 2*DI*DM + DM*DI + DBCW*DI + DBCW*DI;
    k_cvt4<<<(ncvt + 255)/256, 256>>>(
        in_proj_w, wih, wil, 2*DI*DM,
        out_proj_w, woh, wol, DM*DI,
        x_proj_w,  xwh0, xwl0, DBCW*DI,
        x_proj_w_b, xwh1, xwl1, DBCW*DI);

    // 1. LayerNorm -> bf16 hi/lo
    k_layernorm<<<NTOK / 8, 256>>>(x, ln_w, ln_b, lnh, lnl);

    // 2. in_proj (mma.sync split-bf16, 256x128 tile): -> xz fp32
    k_mma<false><<<dim3(2*DI/128, NTOK/256), 512, MMA_SMEM>>>(lnh, lnl, wih, wil, xz, 2*DI, nullptr);

    // 3. x_proj: fused conv+silu + tensor-core split-bf16, both branches
    k_xproj<<<dim3(NTOK/128, 2), 256, XP_SMEM>>>(
        xz, conv_w, conv_b, conv_w_b, conv_b_b,
        xwh0, xwl0, xwh1, xwl1, dbc0, dbc1);

    // 4. fused conv + dt_proj + selective scan (single pass, decoupled lookback)
    k_zero<<<2, 1024>>>(flags);
    k_scan<<<dim3(DI/128, BATCH, NCH*2), 128, SCAN_SMEM>>>(
        xz, dbc0, dbc1, conv_w, conv_b, conv_w_b, conv_b_b,
        A_log, A_log_b, dt_proj_w, dt_proj_w_b, dt_proj_b, dt_proj_b_b,
        Dp, D_b, y0, y1, P0, Q0, P1, Q1, flags);

    // 5. combine + silu(z) gate + RMSNorm -> bf16 hi/lo
    k_rms<<<NTOK / 8, 256>>>(y0, y1, xz, rms_w, ynh, ynl);

    // 6. out_proj (mma.sync split-bf16) + residual -> d_out
    k_mma<true><<<dim3(DM/128, NTOK/256), 512, MMA_SMEM>>>(ynh, ynl, woh, wol, out, DM, x);
}

// round 12
// speedup vs baseline: 1.0215x; 1.0215x over previous
#include <cuda_runtime.h>
#include <cuda_bf16.h>
#include <cstdint>

// ---------------- problem constants ----------------
#define BATCH   4
#define LSEQ    4096
#define NTOK    (BATCH*LSEQ)       // 16384
#define DM      512
#define DI      512
#define DS      8
#define DTRANK  32
#define DBCW    48                 // DT_RANK + 2*D_STATE

// chunked scan config
#define NCH     64
#define TCH     (LSEQ/NCH)         // 64
#define NCHAN   (BATCH*DI)         // 2048
#define CHTOT   (NCHAN*NCH)        // 131072

// ---------------- scratch (device globals; no runtime alloc) ----------------
__device__ __nv_bfloat16 g_lnh[NTOK*DM];
__device__ __nv_bfloat16 g_lnl[NTOK*DM];
__device__ __nv_bfloat16 g_wih[2*DI*DM];
__device__ __nv_bfloat16 g_wil[2*DI*DM];
__device__ __nv_bfloat16 g_woh[DM*DI];
__device__ __nv_bfloat16 g_wol[DM*DI];
__device__ __nv_bfloat16 g_xwh0[DBCW*DI];
__device__ __nv_bfloat16 g_xwl0[DBCW*DI];
__device__ __nv_bfloat16 g_xwh1[DBCW*DI];
__device__ __nv_bfloat16 g_xwl1[DBCW*DI];
__device__ __nv_bfloat16 g_ynh[NTOK*DI];
__device__ __nv_bfloat16 g_ynl[NTOK*DI];
__device__ float g_xz  [NTOK*2*DI];
__device__ float g_dbc0[NTOK*DBCW];
__device__ float g_dbc1[NTOK*DBCW];
__device__ float g_y0  [NTOK*DI];
__device__ float g_y1  [NTOK*DI];
__device__ float g_P0  [DS*CHTOT];
__device__ float g_Q0  [DS*CHTOT];
__device__ float g_P1  [DS*CHTOT];
__device__ float g_Q1  [DS*CHTOT];
__device__ int   g_flags[2048];

// ---------------- helpers ----------------
__device__ __forceinline__ uint32_t smem_u32(const void* p) {
    uint32_t a;
    asm("{ .reg .u64 t; cvta.to.shared.u64 t, %1; cvt.u32.u64 %0, t; }" : "=r"(a) : "l"(p));
    return a;
}
__device__ __forceinline__ void ldsm4(uint32_t* r, uint32_t addr) {
    asm volatile("ldmatrix.sync.aligned.m8n8.x4.shared.b16 {%0,%1,%2,%3}, [%4];"
        : "=r"(r[0]), "=r"(r[1]), "=r"(r[2]), "=r"(r[3]) : "r"(addr));
}
__device__ __forceinline__ void mma16816(float* c, const uint32_t* a, const uint32_t* b) {
    asm volatile("mma.sync.aligned.m16n8k16.row.col.f32.bf16.bf16.f32 "
        "{%0,%1,%2,%3},{%4,%5,%6,%7},{%8,%9},{%0,%1,%2,%3};"
        : "+f"(c[0]), "+f"(c[1]), "+f"(c[2]), "+f"(c[3])
        : "r"(a[0]), "r"(a[1]), "r"(a[2]), "r"(a[3]), "r"(b[0]), "r"(b[1]));
}
__device__ __forceinline__ float silu(float v) { return v / (1.f + __expf(-v)); }

// ---------------- mma.sync split-bf16 GEMM, 256x128 tile, 2-stage -----------
#define KCH     64
#define NKCH    (512/KCH)          // 8
#define A_TILEB 32768              // 256x64 bf16
#define B_TILEB 16384              // 128x64 bf16
#define STG_SZ  (2*A_TILEB + 2*B_TILEB)   // 98304
#define MMA_SMEM (2*STG_SZ)               // 196608

__device__ __forceinline__ void mma_load_chunk(
    const __nv_bfloat16* __restrict__ Ah, const __nv_bfloat16* __restrict__ Al,
    const __nv_bfloat16* __restrict__ Bh, const __nv_bfloat16* __restrict__ Bl,
    int m0, int n0, int kc, uint32_t stage)
{
    const int t = threadIdx.x;
#pragma unroll
    for (int it = 0; it < 12; it++) {
        int idx = it * 512 + t;            // 0..6143 16B-chunks
        const __nv_bfloat16* gb;
        uint32_t toff;
        int local, base;
        if (idx < 4096) {
            int which = idx >> 11;
            local = idx & 2047;
            gb = which ? Al : Ah;
            toff = which ? A_TILEB : 0u;
            base = m0;
        } else {
            int idx2 = idx - 4096;
            int which = idx2 >> 10;
            local = idx2 & 1023;
            gb = which ? Bl : Bh;
            toff = 2 * A_TILEB + (which ? B_TILEB : 0);
            base = n0;
        }
        int row = local >> 3;
        int c   = local & 7;
        const void* ga = gb + (size_t)(base + row) * 512 + kc * KCH + c * 8;
        uint32_t sa = stage + toff + row * 128 + ((c ^ (row & 7)) << 4);
        asm volatile("cp.async.cg.shared.global [%0], [%1], 16;" :: "r"(sa), "l"(ga));
    }
}

template<bool RESID>
__global__ __launch_bounds__(512)
void k_mma(const __nv_bfloat16* __restrict__ Ah, const __nv_bfloat16* __restrict__ Al,
           const __nv_bfloat16* __restrict__ Bh, const __nv_bfloat16* __restrict__ Bl,
           float* __restrict__ C, int N, const float* __restrict__ resid)
{
    extern __shared__ __align__(128) char smem[];
    const uint32_t sb = smem_u32(smem);
    const int m0 = blockIdx.y * 256;
    const int n0 = blockIdx.x * 128;
    const int w  = threadIdx.x >> 5;
    const int lane = threadIdx.x & 31;
    const int wm = (w >> 2) * 64;
    const int wn = (w & 3) * 32;

    float acc[4][4][4];
#pragma unroll
    for (int i = 0; i < 4; i++)
#pragma unroll
        for (int j = 0; j < 4; j++)
#pragma unroll
            for (int q = 0; q < 4; q++) acc[i][j][q] = 0.f;

    const int ar  = lane & 15;
    const int ach = lane >> 4;
    const int bt8 = lane & 7;
    const int bn8 = (lane >> 4) << 3;
    const int bch = (lane >> 3) & 1;

    mma_load_chunk(Ah, Al, Bh, Bl, m0, n0, 0, sb);
    asm volatile("cp.async.commit_group;");
    mma_load_chunk(Ah, Al, Bh, Bl, m0, n0, 1, sb + STG_SZ);
    asm volatile("cp.async.commit_group;");

    for (int i = 0; i < NKCH; i++) {
        if (i < NKCH - 1) asm volatile("cp.async.wait_group 1;");
        else              asm volatile("cp.async.wait_group 0;");
        __syncthreads();

        const uint32_t stg = sb + (i & 1) * STG_SZ;
        const uint32_t sAh = stg, sAl = stg + A_TILEB;
        const uint32_t sBh = stg + 2 * A_TILEB, sBl = stg + 2 * A_TILEB + B_TILEB;

#pragma unroll
        for (int ks = 0; ks < 4; ks++) {
            uint32_t bh[2][4], bl[2][4];
#pragma unroll
            for (int ni = 0; ni < 2; ni++) {
                int n = wn + ni * 16 + bn8 + bt8;
                int c = ks * 2 + bch;
                uint32_t off = n * 128 + (((uint32_t)(c ^ (n & 7))) << 4);
                ldsm4(bh[ni], sBh + off);
                ldsm4(bl[ni], sBl + off);
            }
#pragma unroll
            for (int mih = 0; mih < 2; mih++) {
                uint32_t ah2[2][4], al2[2][4];
#pragma unroll
                for (int m2 = 0; m2 < 2; m2++) {
                    int r = wm + (mih * 2 + m2) * 16 + ar;
                    int c = ks * 2 + ach;
                    uint32_t off = r * 128 + (((uint32_t)(c ^ (r & 7))) << 4);
                    ldsm4(ah2[m2], sAh + off);
                    ldsm4(al2[m2], sAl + off);
                }
#pragma unroll
                for (int m2 = 0; m2 < 2; m2++)
#pragma unroll
                    for (int nj = 0; nj < 4; nj++) {
                        const uint32_t* bhp = &bh[nj >> 1][(nj & 1) * 2];
                        const uint32_t* blp = &bl[nj >> 1][(nj & 1) * 2];
                        float* ac = acc[mih * 2 + m2][nj];
                        mma16816(ac, ah2[m2], bhp);
                        mma16816(ac, ah2[m2], blp);
                        mma16816(ac, al2[m2], bhp);
                    }
            }
        }

        if (i < NKCH - 2) {
            __syncthreads();
            mma_load_chunk(Ah, Al, Bh, Bl, m0, n0, i + 2, stg);
            asm volatile("cp.async.commit_group;");
        }
    }

#pragma unroll
    for (int mi = 0; mi < 4; mi++) {
        int m = m0 + wm + mi * 16 + (lane >> 2);
#pragma unroll
        for (int nj = 0; nj < 4; nj++) {
            int n = n0 + wn + nj * 8 + ((lane & 3) << 1);
            float2 v0 = make_float2(acc[mi][nj][0], acc[mi][nj][1]);
            float2 v1 = make_float2(acc[mi][nj][2], acc[mi][nj][3]);
            if (RESID) {
                float2 r0 = *(const float2*)(resid + (size_t)m * N + n);
                float2 r1 = *(const float2*)(resid + (size_t)(m + 8) * N + n);
                v0.x += r0.x; v0.y += r0.y; v1.x += r1.x; v1.y += r1.y;
            }
            *(float2*)(C + (size_t)m * N + n)       = v0;
            *(float2*)(C + (size_t)(m + 8) * N + n) = v1;
        }
    }
}

// ---------------- x_proj: fused conv+silu A-build + split-bf16 mma ----------
// Tile 128(M) x 64(N, 48 valid), K-chunk 64, A built in-kernel from
// register-prefetched xz (one chunk ahead), B cp.async double-buffered.
#define XP_A    16384              // 128x64 bf16
#define XP_B    8192               // 64x64 bf16
#define XP_STG  (2*XP_A + 2*XP_B)  // 49152
#define XP_SMEM (2*XP_STG)         // 98304

struct XpRegs { float4 v[9]; };    // xprev + 8 rows

__device__ __forceinline__ void xp_load_B(
    const __nv_bfloat16* __restrict__ Wh, const __nv_bfloat16* __restrict__ Wl,
    int kc, uint32_t stage)
{
    const int t = threadIdx.x;
#pragma unroll
    for (int it = 0; it < 3; it++) {
        int idx = it * 256 + t;            // 0..767
        int which = idx >= 384;
        int local = idx - which * 384;
        int row = local >> 3;              // 0..47
        int c   = local & 7;
        const void* ga = (which ? Wl : Wh) + (size_t)row * 512 + kc * KCH + c * 8;
        uint32_t sa = stage + 2 * XP_A + which * XP_B + row * 128 + ((c ^ (row & 7)) << 4);
        asm volatile("cp.async.cg.shared.global [%0], [%1], 16;" :: "r"(sa), "l"(ga));
    }
}

__device__ __forceinline__ void xp_loadregs(
    XpRegs& R, const float* __restrict__ xz, int i,
    int d, int s0, int r_lo, int g0, int dir)
{
    const float* basep = xz + i * KCH + d;
    R.v[0] = (s0 + r_lo) > 0
        ? *(const float4*)(basep + (size_t)(g0 + dir * (r_lo - 1)) * (2 * DI))
        : make_float4(0.f, 0.f, 0.f, 0.f);
#pragma unroll
    for (int j = 0; j < 8; j++)
        R.v[1 + j] = *(const float4*)(basep + (size_t)(g0 + dir * (r_lo + j)) * (2 * DI));
}

__device__ __forceinline__ void xp_convert(
    const XpRegs& R, char* smem, int i,
    int d, int r_lo, const float* __restrict__ cw, const float* __restrict__ cb)
{
    const int ch = i * KCH + d;
    float4 cwa  = *(const float4*)(cw + ch * 2);       // w0,w1 [ch], [ch+1]
    float4 cwb2 = *(const float4*)(cw + ch * 2 + 4);   // w0,w1 [ch+2], [ch+3]
    float4 cbv  = *(const float4*)(cb + ch);
    float4 xprev = R.v[0];
    const uint32_t sbase = (i & 1) * XP_STG;
#pragma unroll
    for (int j = 0; j < 8; j++) {
        const int r = r_lo + j;
        float4 xc = R.v[1 + j];
        float u0 = silu(fmaf(cwa.x,  xprev.x, fmaf(cwa.y,  xc.x, cbv.x)));
        float u1 = silu(fmaf(cwa.z,  xprev.y, fmaf(cwa.w,  xc.y, cbv.y)));
        float u2 = silu(fmaf(cwb2.x, xprev.z, fmaf(cwb2.y, xc.z, cbv.z)));
        float u3 = silu(fmaf(cwb2.z, xprev.w, fmaf(cwb2.w, xc.w, cbv.w)));
        xprev = xc;
        __nv_bfloat16 h0 = __float2bfloat16(u0), h1 = __float2bfloat16(u1);
        __nv_bfloat16 h2 = __float2bfloat16(u2), h3 = __float2bfloat16(u3);
        __nv_bfloat16 l0 = __float2bfloat16(u0 - __bfloat162float(h0));
        __nv_bfloat16 l1 = __float2bfloat16(u1 - __bfloat162float(h1));
        __nv_bfloat16 l2 = __float2bfloat16(u2 - __bfloat162float(h2));
        __nv_bfloat16 l3 = __float2bfloat16(u3 - __bfloat162float(h3));
        const int c16 = d >> 3;
        uint32_t off = sbase + r * 128
                     + ((uint32_t)(c16 ^ (r & 7)) << 4) + (d & 7) * 2;
        uint2 hv, lv;
        __nv_bfloat162 p;
        p = __nv_bfloat162(h0, h1); hv.x = *(uint32_t*)&p;
        p = __nv_bfloat162(h2, h3); hv.y = *(uint32_t*)&p;
        p = __nv_bfloat162(l0, l1); lv.x = *(uint32_t*)&p;
        p = __nv_bfloat162(l2, l3); lv.y = *(uint32_t*)&p;
        *(uint2*)(smem + off)        = hv;
        *(uint2*)(smem + off + XP_A) = lv;
    }
}

__global__ __launch_bounds__(256)
void k_xproj(const float* __restrict__ xz,
             const float* __restrict__ cw0, const float* __restrict__ cb0,
             const float* __restrict__ cw1, const float* __restrict__ cb1,
             const __nv_bfloat16* __restrict__ xwh0, const __nv_bfloat16* __restrict__ xwl0,
             const __nv_bfloat16* __restrict__ xwh1, const __nv_bfloat16* __restrict__ xwl1,
             float* __restrict__ C0, float* __restrict__ C1)
{
    extern __shared__ __align__(128) char smem[];
    const uint32_t sb = smem_u32(smem);
    const int br = blockIdx.y;
    const int m0 = blockIdx.x * 128;
    const int t  = threadIdx.x;
    const int w  = t >> 5;
    const int lane = t & 31;

    const float* cw = br ? cw1 : cw0;
    const float* cb = br ? cb1 : cb0;
    const __nv_bfloat16* Wh = br ? xwh1 : xwh0;
    const __nv_bfloat16* Wl = br ? xwl1 : xwl0;
    float* C = br ? C1 : C0;

    const int s0  = m0 & (LSEQ - 1);
    const int bb  = m0 >> 12;
    const int g0  = br ? (bb * LSEQ + LSEQ - 1 - s0) : m0;  // gmem row of scan row 0
    const int dir = br ? -1 : 1;

    // zero B pad rows (48..63) of both stages/tiles once
    for (int i = t; i < 2048; i += 256) {
        int region = i >> 9;               // 0..3: stage0(hi),(lo),stage1(hi),(lo)
        uint32_t off = (region >> 1) * XP_STG + 2 * XP_A + (region & 1) * XP_B
                     + 6144 + (i & 511) * 4;
        *(uint32_t*)(smem + off) = 0u;
    }

    // convert-thread mapping: 16 d-quads x 16 row-groups of 8
    const int dq = t & 15;
    const int rg = t >> 4;
    const int d  = dq * 4;
    const int r_lo = rg * 8;

    // mma thread constants
    const int wm = (w >> 1) * 32;
    const int wn = (w & 1) * 32;
    const int ar  = lane & 15;
    const int ach = lane >> 4;
    const int bt8 = lane & 7;
    const int bn8 = (lane >> 4) << 3;
    const int bch = (lane >> 3) & 1;

    float acc[2][4][4];
#pragma unroll
    for (int i = 0; i < 2; i++)
#pragma unroll
        for (int j = 0; j < 4; j++)
#pragma unroll
            for (int q = 0; q < 4; q++) acc[i][j][q] = 0.f;

    // prologue: regs(0) -> convert(0); B(0), B(1) in flight; regs(1) prefetched
    XpRegs R;
    xp_loadregs(R, xz, 0, d, s0, r_lo, g0, dir);
    xp_load_B(Wh, Wl, 0, sb);
    asm volatile("cp.async.commit_group;");
    xp_load_B(Wh, Wl, 1, sb + XP_STG);
    asm volatile("cp.async.commit_group;");
    xp_convert(R, smem, 0, d, r_lo, cw, cb);
    xp_loadregs(R, xz, 1, d, s0, r_lo, g0, dir);

    for (int i = 0; i < NKCH; i++) {
        if (i < NKCH - 1) asm volatile("cp.async.wait_group 1;");
        else              asm volatile("cp.async.wait_group 0;");
        __syncthreads();

        const uint32_t stg = sb + (i & 1) * XP_STG;
        const uint32_t sAh = stg, sAl = stg + XP_A;
        const uint32_t sBh = stg + 2 * XP_A, sBl = stg + 2 * XP_A + XP_B;
#pragma unroll
        for (int ks = 0; ks < 4; ks++) {
            uint32_t ah[2][4], al[2][4], bh[2][4], bl[2][4];
#pragma unroll
            for (int mi = 0; mi < 2; mi++) {
                int r = wm + mi * 16 + ar;
                int c = ks * 2 + ach;
                uint32_t off = r * 128 + (((uint32_t)(c ^ (r & 7))) << 4);
                ldsm4(ah[mi], sAh + off);
                ldsm4(al[mi], sAl + off);
            }
#pragma unroll
            for (int ni = 0; ni < 2; ni++) {
                int n = wn + ni * 16 + bn8 + bt8;
                int c = ks * 2 + bch;
                uint32_t off = n * 128 + (((uint32_t)(c ^ (n & 7))) << 4);
                ldsm4(bh[ni], sBh + off);
                ldsm4(bl[ni], sBl + off);
            }
#pragma unroll
            for (int mi = 0; mi < 2; mi++)
#pragma unroll
                for (int nj = 0; nj < 4; nj++) {
                    const uint32_t* bhp = &bh[nj >> 1][(nj & 1) * 2];
                    const uint32_t* blp = &bl[nj >> 1][(nj & 1) * 2];
                    mma16816(acc[mi][nj], ah[mi], bhp);
                    mma16816(acc[mi][nj], ah[mi], blp);
                    mma16816(acc[mi][nj], al[mi], bhp);
                }
        }

        if (i < NKCH - 1) {
            __syncthreads();   // all MMA(i) reads done: stage i&1 B free, stage (i+1)&1 A free
            xp_convert(R, smem, i + 1, d, r_lo, cw, cb);   // A for chunk i+1
            if (i < NKCH - 2) {
                xp_load_B(Wh, Wl, i + 2, stg);              // B into stage i&1
                asm volatile("cp.async.commit_group;");
                xp_loadregs(R, xz, i + 2, d, s0, r_lo, g0, dir);
            }
        }
    }

    // epilogue: C is [NTOK][48]
#pragma unroll
    for (int mi = 0; mi < 2; mi++) {
        int m = m0 + wm + mi * 16 + (lane >> 2);
#pragma unroll
        for (int nj = 0; nj < 4; nj++) {
            int n = wn + nj * 8 + ((lane & 3) << 1);
            if (n < DBCW) {
                *(float2*)(C + (size_t)m * DBCW + n) =
                    make_float2(acc[mi][nj][0], acc[mi][nj][1]);
                *(float2*)(C + (size_t)(m + 8) * DBCW + n) =
                    make_float2(acc[mi][nj][2], acc[mi][nj][3]);
            }
        }
    }
}

// ---------------- fp32 -> bf16 hi/lo weight convert (4 weights, 1 launch) ----
__global__ void k_cvt4(const float* __restrict__ w1, __nv_bfloat16* __restrict__ h1,
                       __nv_bfloat16* __restrict__ l1, int n1,
                       const float* __restrict__ w2, __nv_bfloat16* __restrict__ h2,
                       __nv_bfloat16* __restrict__ l2, int n2,
                       const float* __restrict__ w3, __nv_bfloat16* __restrict__ h3,
                       __nv_bfloat16* __restrict__ l3, int n3,
                       const float* __restrict__ w4, __nv_bfloat16* __restrict__ h4,
                       __nv_bfloat16* __restrict__ l4, int n4)
{
    int i = blockIdx.x * blockDim.x + threadIdx.x;
    const float* w; __nv_bfloat16 *hh, *ll; int j;
    if (i < n1)                     { w = w1; hh = h1; ll = l1; j = i; }
    else if (i < n1+n2)             { w = w2; hh = h2; ll = l2; j = i-n1; }
    else if (i < n1+n2+n3)          { w = w3; hh = h3; ll = l3; j = i-n1-n2; }
    else if (i < n1+n2+n3+n4)       { w = w4; hh = h4; ll = l4; j = i-n1-n2-n3; }
    else return;
    float v = w[j];
    __nv_bfloat16 h = __float2bfloat16(v);
    hh[j] = h;
    ll[j] = __float2bfloat16(v - __bfloat162float(h));
}

// ---------------- LayerNorm -> bf16 hi/lo ----------------
__global__ void k_layernorm(const float* __restrict__ x,
                            const float* __restrict__ w,
                            const float* __restrict__ b,
                            __nv_bfloat16* __restrict__ oh,
                            __nv_bfloat16* __restrict__ ol)
{
    int tok  = blockIdx.x * 8 + (threadIdx.x >> 5);
    int lane = threadIdx.x & 31;
    const float* row = x + (size_t)tok * DM;

    float4 v[4];
    float s = 0.f, s2 = 0.f;
#pragma unroll
    for (int i = 0; i < 4; i++) {
        v[i] = *(const float4*)(row + i * 128 + lane * 4);
        s  += v[i].x + v[i].y + v[i].z + v[i].w;
        s2 += v[i].x*v[i].x + v[i].y*v[i].y + v[i].z*v[i].z + v[i].w*v[i].w;
    }
#pragma unroll
    for (int o = 16; o; o >>= 1) {
        s  += __shfl_xor_sync(0xffffffffu, s,  o);
        s2 += __shfl_xor_sync(0xffffffffu, s2, o);
    }
    float mu   = s * (1.f / DM);
    float var  = s2 * (1.f / DM) - mu * mu;
    float rinv = rsqrtf(var + 1e-5f);

#pragma unroll
    for (int i = 0; i < 4; i++) {
        int d = i * 128 + lane * 4;
        float4 w4 = *(const float4*)(w + d);
        float4 b4 = *(const float4*)(b + d);
        float o4[4];
        o4[0] = (v[i].x - mu) * rinv * w4.x + b4.x;
        o4[1] = (v[i].y - mu) * rinv * w4.y + b4.y;
        o4[2] = (v[i].z - mu) * rinv * w4.z + b4.z;
        o4[3] = (v[i].w - mu) * rinv * w4.w + b4.w;
        __nv_bfloat16 hh[4], ll[4];
#pragma unroll
        for (int q = 0; q < 4; q++) {
            hh[q] = __float2bfloat16(o4[q]);
            ll[q] = __float2bfloat16(o4[q] - __bfloat162float(hh[q]));
        }
        *(uint2*)(oh + (size_t)tok * DM + d) = *(uint2*)hh;
        *(uint2*)(ol + (size_t)tok * DM + d) = *(uint2*)ll;
    }
}

// ---------------- zero lookback flags ----------------
__global__ void k_zero(int* __restrict__ flags) {
    flags[blockIdx.x * 1024 + threadIdx.x] = 0;
}

// ---------------- fused conv + dt_proj + softplus + lookback scan -----------
#define SCAN_SMEM (TCH*128*4 + TCH*49*4)   // 32768 + 12544 = 45312

__global__ __launch_bounds__(128)
void k_scan(const float* __restrict__ xz,
            const float* __restrict__ dbc0, const float* __restrict__ dbc1,
            const float* __restrict__ cw0,  const float* __restrict__ cb0,
            const float* __restrict__ cw1,  const float* __restrict__ cb1,
            const float* __restrict__ Alog0, const float* __restrict__ Alog1,
            const float* __restrict__ dtw0, const float* __restrict__ dtw1,
            const float* __restrict__ dtb0, const float* __restrict__ dtb1,
            const float* __restrict__ Dp0,  const float* __restrict__ Dp1,
            float* __restrict__ y0g, float* __restrict__ y1g,
            float* __restrict__ P0g, float* __restrict__ Q0g,
            float* __restrict__ P1g, float* __restrict__ Q1g,
            int* __restrict__ flags)
{
    extern __shared__ float sm[];
    float* delta_s = sm;                 // [TCH][128]
    float* dbc_s   = sm + TCH * 128;     // [TCH][49]

    const int t  = threadIdx.x;
    const int dg = blockIdx.x;
    const int b  = blockIdx.y;
    const int br = blockIdx.z & 1;
    const int chunk = blockIdx.z >> 1;
    const int d  = dg * 128 + t;

    const float* dbc = br ? dbc1 : dbc0;
    const float* Alg = br ? Alog1 : Alog0;
    const float* Wdt = br ? dtw1 : dtw0;
    const float* Bdt = br ? dtb1 : dtb0;
    const float* Dpp = br ? Dp1  : Dp0;
    const float* cwp = br ? cw1 : cw0;
    const float* cbp = br ? cb1 : cb0;
    float* y  = br ? y1g : y0g;
    float* Pg = br ? P1g : P0g;
    float* Qg = br ? Q1g : Q0g;

    for (int i = t; i < 128 * 32; i += 128) {
        int rw_ = i >> 5, k = i & 31;
        sm[rw_ * 33 + k] = Wdt[(size_t)(dg * 128) * 32 + i];
    }
    const int tok0 = b * LSEQ + chunk * TCH;
    for (int i = t; i < TCH * 48; i += 128)
        dbc_s[(i / 48) * 49 + (i % 48)] = dbc[(size_t)tok0 * 48 + i];
    __syncthreads();
    float w[32];
#pragma unroll
    for (int k = 0; k < 32; k++) w[k] = sm[t * 33 + k];
    __syncthreads();

    float Av[DS];
    {
        float4 a0 = *(const float4*)(Alg + d * DS);
        float4 a1 = *(const float4*)(Alg + d * DS + 4);
        Av[0] = -__expf(a0.x); Av[1] = -__expf(a0.y); Av[2] = -__expf(a0.z); Av[3] = -__expf(a0.w);
        Av[4] = -__expf(a1.x); Av[5] = -__expf(a1.y); Av[6] = -__expf(a1.z); Av[7] = -__expf(a1.w);
    }
    const float Av0 = Av[0];
    bool uni = true;
#pragma unroll
    for (int n = 1; n < DS; n++)
        uni = uni && (fabsf(Av[n] - (n + 1) * Av0) <= 2e-5f * (n + 1));

    const float bias = Bdt[d];
    const float Dd   = Dpp[d];
    const float cwd0 = cwp[d * 2], cwd1 = cwp[d * 2 + 1], cbd = cbp[d];

    const int s0  = chunk * TCH;
    const int r0  = br ? (b * LSEQ + LSEQ - 1 - s0) : tok0;
    const int dir = br ? -1 : 1;

    float h[DS], P[DS], S = 0.f;
#pragma unroll
    for (int n = 0; n < DS; n++) { h[n] = 0.f; P[n] = 1.f; }

    float xprev = (s0 > 0) ? xz[(size_t)(r0 - dir) * (2 * DI) + d] : 0.f;
    for (int tt = 0; tt < TCH; tt++) {
        float xcur = xz[(size_t)(r0 + dir * tt) * (2 * DI) + d];
        float u = silu(fmaf(cwd0, xprev, fmaf(cwd1, xcur, cbd)));
        xprev = xcur;

        const float* row = &dbc_s[tt * 49];
        float a0 = bias, a1 = 0.f, a2 = 0.f, a3 = 0.f;
#pragma unroll
        for (int k = 0; k < 32; k += 4) {
            a0 = fmaf(row[k + 0], w[k + 0], a0);
            a1 = fmaf(row[k + 1], w[k + 1], a1);
            a2 = fmaf(row[k + 2], w[k + 2], a2);
            a3 = fmaf(row[k + 3], w[k + 3], a3);
        }
        float v = (a0 + a1) + (a2 + a3);
        float dl = (v > 20.f) ? v : log1pf(__expf(v));
        delta_s[tt * 128 + t] = dl;
        float du = dl * u;
        if (uni) {
            S += dl;
            float e1 = __expf(dl * Av0);
            float an = 1.f;
#pragma unroll
            for (int n = 0; n < DS; n++) {
                an *= e1;
                h[n] = fmaf(an, h[n], du * row[32 + n]);
            }
        } else {
#pragma unroll
            for (int n = 0; n < DS; n++) {
                float a = __expf(dl * Av[n]);
                P[n] *= a;
                h[n] = fmaf(a, h[n], du * row[32 + n]);
            }
        }
    }
    if (uni) {
#pragma unroll
        for (int n = 0; n < DS; n++) P[n] = __expf(S * Av[n]);
    }

    const int cidx = chunk * NCHAN + b * DI + d;
    {
        *(float4*)(Pg + (size_t)cidx * 8)     = make_float4(P[0], P[1], P[2], P[3]);
        *(float4*)(Pg + (size_t)cidx * 8 + 4) = make_float4(P[4], P[5], P[6], P[7]);
        *(float4*)(Qg + (size_t)cidx * 8)     = make_float4(h[0], h[1], h[2], h[3]);
        *(float4*)(Qg + (size_t)cidx * 8 + 4) = make_float4(h[4], h[5], h[6], h[7]);
    }
    __threadfence();
    __syncthreads();
    if (t == 0) {
        int fi = blockIdx.z * 16 + b * 4 + dg;
        asm volatile("st.global.release.gpu.b32 [%0], %1;" :: "l"(flags + fi), "r"(1) : "memory");
    }

    float h0[DS], pref[DS];
#pragma unroll
    for (int n = 0; n < DS; n++) { h0[n] = 0.f; pref[n] = 1.f; }
    for (int j = chunk - 1; j >= 0; j--) {
        const int fj = (j * 2 + br) * 16 + b * 4 + dg;
        int f;
        do {
            asm volatile("ld.global.acquire.gpu.b32 %0, [%1];" : "=r"(f) : "l"(flags + fj) : "memory");
            if (!f) __nanosleep(64);
        } while (!f);
        const size_t idxj = (size_t)(j * NCHAN + b * DI + d) * 8;
        float4 qa = *(const float4*)(Qg + idxj);
        float4 qb = *(const float4*)(Qg + idxj + 4);
        float4 pa = *(const float4*)(Pg + idxj);
        float4 pb = *(const float4*)(Pg + idxj + 4);
        float qv[DS] = { qa.x, qa.y, qa.z, qa.w, qb.x, qb.y, qb.z, qb.w };
        float pv2[DS] = { pa.x, pa.y, pa.z, pa.w, pb.x, pb.y, pb.z, pb.w };
#pragma unroll
        for (int n = 0; n < DS; n++) {
            h0[n] = fmaf(pref[n], qv[n], h0[n]);
            pref[n] *= pv2[n];
        }
    }

#pragma unroll
    for (int n = 0; n < DS; n++) h[n] = h0[n];
    xprev = (s0 > 0) ? xz[(size_t)(r0 - dir) * (2 * DI) + d] : 0.f;
    for (int tt = 0; tt < TCH; tt++) {
        float xcur = xz[(size_t)(r0 + dir * tt) * (2 * DI) + d];
        float u = silu(fmaf(cwd0, xprev, fmaf(cwd1, xcur, cbd)));
        xprev = xcur;

        float dl = delta_s[tt * 128 + t];
        float du = dl * u;
        const float* row = &dbc_s[tt * 49];
        float yv = 0.f;
        if (uni) {
            float e1 = __expf(dl * Av0);
            float an = 1.f;
#pragma unroll
            for (int n = 0; n < DS; n++) {
                an *= e1;
                h[n] = fmaf(an, h[n], du * row[32 + n]);
                yv = fmaf(h[n], row[40 + n], yv);
            }
        } else {
#pragma unroll
            for (int n = 0; n < DS; n++) {
                float a = __expf(dl * Av[n]);
                h[n] = fmaf(a, h[n], du * row[32 + n]);
                yv = fmaf(h[n], row[40 + n], yv);
            }
        }
        y[(size_t)(tok0 + tt) * DI + d] = fmaf(u, Dd, yv);
    }
}

// ---------------- combine branches, gate, RMSNorm -> bf16 hi/lo ---------------
__global__ void k_rms(const float* __restrict__ yf, const float* __restrict__ yb,
                      const float* __restrict__ xz, const float* __restrict__ rw,
                      __nv_bfloat16* __restrict__ oh, __nv_bfloat16* __restrict__ ol)
{
    int tok  = blockIdx.x * 8 + (threadIdx.x >> 5);
    int lane = threadIdx.x & 31;
    int s    = tok & (LSEQ - 1);
    int rtok = tok - s + (LSEQ - 1 - s);

    float4 v[4];
    float ss = 0.f;
#pragma unroll
    for (int i = 0; i < 4; i++) {
        int d = i * 128 + lane * 4;
        float4 a = *(const float4*)(yf + (size_t)tok * DI + d);
        float4 c = *(const float4*)(yb + (size_t)rtok * DI + d);
        float4 z = *(const float4*)(xz + (size_t)tok * (2 * DI) + DI + d);
        float4 o;
        o.x = 0.5f * (a.x + c.x) * silu(z.x);
        o.y = 0.5f * (a.y + c.y) * silu(z.y);
        o.z = 0.5f * (a.z + c.z) * silu(z.z);
        o.w = 0.5f * (a.w + c.w) * silu(z.w);
        ss += o.x*o.x + o.y*o.y + o.z*o.z + o.w*o.w;
        v[i] = o;
    }
#pragma unroll
    for (int o = 16; o; o >>= 1) ss += __shfl_xor_sync(0xffffffffu, ss, o);
    float sc = rsqrtf(ss * (1.f / DI) + 1e-5f);

#pragma unroll
    for (int i = 0; i < 4; i++) {
        int d = i * 128 + lane * 4;
        float4 w4 = *(const float4*)(rw + d);
        float o4[4];
        o4[0] = v[i].x * sc * w4.x;
        o4[1] = v[i].y * sc * w4.y;
        o4[2] = v[i].z * sc * w4.z;
        o4[3] = v[i].w * sc * w4.w;
        __nv_bfloat16 hh[4], ll[4];
#pragma unroll
        for (int q = 0; q < 4; q++) {
            hh[q] = __float2bfloat16(o4[q]);
            ll[q] = __float2bfloat16(o4[q] - __bfloat162float(hh[q]));
        }
        *(uint2*)(oh + (size_t)tok * DI + d) = *(uint2*)hh;
        *(uint2*)(ol + (size_t)tok * DI + d) = *(uint2*)ll;
    }
}

// ---------------- host launch ----------------
extern "C" void kernel_launch(void* const* d_in, const int* in_sizes, int n_in,
                              void* d_out, int out_size)
{
    const float* x          = (const float*)d_in[0];
    const float* ln_w       = (const float*)d_in[1];
    const float* ln_b       = (const float*)d_in[2];
    const float* in_proj_w  = (const float*)d_in[3];
    const float* conv_w     = (const float*)d_in[4];
    const float* conv_b     = (const float*)d_in[5];
    const float* x_proj_w   = (const float*)d_in[6];
    const float* dt_proj_w  = (const float*)d_in[7];
    const float* dt_proj_b  = (const float*)d_in[8];
    const float* A_log      = (const float*)d_in[9];
    const float* Dp         = (const float*)d_in[10];
    const float* conv_w_b   = (const float*)d_in[11];
    const float* conv_b_b   = (const float*)d_in[12];
    const float* x_proj_w_b = (const float*)d_in[13];
    const float* dt_proj_w_b= (const float*)d_in[14];
    const float* dt_proj_b_b= (const float*)d_in[15];
    const float* A_log_b    = (const float*)d_in[16];
    const float* D_b        = (const float*)d_in[17];
    const float* rms_w      = (const float*)d_in[18];
    const float* out_proj_w = (const float*)d_in[19];
    float* out = (float*)d_out;

    __nv_bfloat16 *lnh, *lnl, *wih, *wil, *woh, *wol, *ynh, *ynl;
    __nv_bfloat16 *xwh0, *xwl0, *xwh1, *xwl1;
    float *xz, *dbc0, *dbc1, *y0, *y1;
    float *P0, *Q0, *P1, *Q1;
    int* flags;
    cudaGetSymbolAddress((void**)&lnh,  g_lnh);
    cudaGetSymbolAddress((void**)&lnl,  g_lnl);
    cudaGetSymbolAddress((void**)&wih,  g_wih);
    cudaGetSymbolAddress((void**)&wil,  g_wil);
    cudaGetSymbolAddress((void**)&woh,  g_woh);
    cudaGetSymbolAddress((void**)&wol,  g_wol);
    cudaGetSymbolAddress((void**)&xwh0, g_xwh0);
    cudaGetSymbolAddress((void**)&xwl0, g_xwl0);
    cudaGetSymbolAddress((void**)&xwh1, g_xwh1);
    cudaGetSymbolAddress((void**)&xwl1, g_xwl1);
    cudaGetSymbolAddress((void**)&ynh,  g_ynh);
    cudaGetSymbolAddress((void**)&ynl,  g_ynl);
    cudaGetSymbolAddress((void**)&xz,   g_xz);
    cudaGetSymbolAddress((void**)&dbc0, g_dbc0);
    cudaGetSymbolAddress((void**)&dbc1, g_dbc1);
    cudaGetSymbolAddress((void**)&y0,   g_y0);
    cudaGetSymbolAddress((void**)&y1,   g_y1);
    cudaGetSymbolAddress((void**)&P0,   g_P0);
    cudaGetSymbolAddress((void**)&Q0,   g_Q0);
    cudaGetSymbolAddress((void**)&P1,   g_P1);
    cudaGetSymbolAddress((void**)&Q1,   g_Q1);
    cudaGetSymbolAddress((void**)&flags, g_flags);

    cudaFuncSetAttribute(k_mma<false>, cudaFuncAttributeMaxDynamicSharedMemorySize, MMA_SMEM);
    cudaFuncSetAttribute(k_mma<true>,  cudaFuncAttributeMaxDynamicSharedMemorySize, MMA_SMEM);
    cudaFuncSetAttribute(k_xproj, cudaFuncAttributeMaxDynamicSharedMemorySize, XP_SMEM);
    cudaFuncSetAttribute(k_scan, cudaFuncAttributeMaxDynamicSharedMemorySize, SCAN_SMEM);

    // 0. convert weights to bf16 hi/lo (single launch)
    int ncvt = 2*DI*DM + DM*DI + DBCW*DI + DBCW*DI;
    k_cvt4<<<(ncvt + 255)/256, 256>>>(
        in_proj_w, wih, wil, 2*DI*DM,
        out_proj_w, woh, wol, DM*DI,
        x_proj_w,  xwh0, xwl0, DBCW*DI,
        x_proj_w_b, xwh1, xwl1, DBCW*DI);

    // 1. LayerNorm -> bf16 hi/lo
    k_layernorm<<<NTOK / 8, 256>>>(x, ln_w, ln_b, lnh, lnl);

    // 2. in_proj (mma.sync split-bf16, 256x128 tile): -> xz fp32
    k_mma<false><<<dim3(2*DI/128, NTOK/256), 512, MMA_SMEM>>>(lnh, lnl, wih, wil, xz, 2*DI, nullptr);

    // 3. x_proj: fused conv+silu + tensor-core split-bf16, reg-pipelined A
    k_xproj<<<dim3(NTOK/128, 2), 256, XP_SMEM>>>(
        xz, conv_w, conv_b, conv_w_b, conv_b_b,
        xwh0, xwl0, xwh1, xwl1, dbc0, dbc1);

    // 4. fused conv + dt_proj + selective scan (single pass, decoupled lookback)
    k_zero<<<2, 1024>>>(flags);
    k_scan<<<dim3(DI/128, BATCH, NCH*2), 128, SCAN_SMEM>>>(
        xz, dbc0, dbc1, conv_w, conv_b, conv_w_b, conv_b_b,
        A_log, A_log_b, dt_proj_w, dt_proj_w_b, dt_proj_b, dt_proj_b_b,
        Dp, D_b, y0, y1, P0, Q0, P1, Q1, flags);

    // 5. combine + silu(z) gate + RMSNorm -> bf16 hi/lo
    k_rms<<<NTOK / 8, 256>>>(y0, y1, xz, rms_w, ynh, ynl);

    // 6. out_proj (mma.sync split-bf16) + residual -> d_out
    k_mma<true><<<dim3(DM/128, NTOK/256), 512, MMA_SMEM>>>(ynh, ynl, woh, wol, out, DM, x);
}

// round 13
// speedup vs baseline: 1.1331x; 1.1092x over previous
#include <cuda_runtime.h>
#include <cuda_bf16.h>
#include <cstdint>

// ---------------- problem constants ----------------
#define BATCH   4
#define LSEQ    4096
#define NTOK    (BATCH*LSEQ)       // 16384
#define DM      512
#define DI      512
#define DS      8
#define DTRANK  32
#define DBCW    48                 // DT_RANK + 2*D_STATE

// chunked scan config
#define NCH     64
#define TCH     (LSEQ/NCH)         // 64
#define NCHAN   (BATCH*DI)         // 2048
#define CHTOT   (NCHAN*NCH)        // 131072

// ---------------- scratch (device globals; no runtime alloc) ----------------
__device__ __nv_bfloat16 g_lnh[NTOK*DM];
__device__ __nv_bfloat16 g_lnl[NTOK*DM];
__device__ __nv_bfloat16 g_wih[2*DI*DM];
__device__ __nv_bfloat16 g_wil[2*DI*DM];
__device__ __nv_bfloat16 g_woh[DM*DI];
__device__ __nv_bfloat16 g_wol[DM*DI];
__device__ __nv_bfloat16 g_xwh0[DBCW*DI];
__device__ __nv_bfloat16 g_xwl0[DBCW*DI];
__device__ __nv_bfloat16 g_xwh1[DBCW*DI];
__device__ __nv_bfloat16 g_xwl1[DBCW*DI];
__device__ __nv_bfloat16 g_ynh[NTOK*DI];
__device__ __nv_bfloat16 g_ynl[NTOK*DI];
__device__ float g_xz  [NTOK*2*DI];
__device__ float g_dbc0[NTOK*DBCW];
__device__ float g_dbc1[NTOK*DBCW];
__device__ float g_y0  [NTOK*DI];
__device__ float g_y1  [NTOK*DI];
__device__ float g_P0  [DS*CHTOT];
__device__ float g_Q0  [DS*CHTOT];
__device__ float g_Hp0 [DS*CHTOT];
__device__ float g_P1  [DS*CHTOT];
__device__ float g_Q1  [DS*CHTOT];
__device__ float g_Hp1 [DS*CHTOT];
__device__ int   g_flags[2048];

// ---------------- helpers ----------------
__device__ __forceinline__ uint32_t smem_u32(const void* p) {
    uint32_t a;
    asm("{ .reg .u64 t; cvta.to.shared.u64 t, %1; cvt.u32.u64 %0, t; }" : "=r"(a) : "l"(p));
    return a;
}
__device__ __forceinline__ void ldsm4(uint32_t* r, uint32_t addr) {
    asm volatile("ldmatrix.sync.aligned.m8n8.x4.shared.b16 {%0,%1,%2,%3}, [%4];"
        : "=r"(r[0]), "=r"(r[1]), "=r"(r[2]), "=r"(r[3]) : "r"(addr));
}
__device__ __forceinline__ void mma16816(float* c, const uint32_t* a, const uint32_t* b) {
    asm volatile("mma.sync.aligned.m16n8k16.row.col.f32.bf16.bf16.f32 "
        "{%0,%1,%2,%3},{%4,%5,%6,%7},{%8,%9},{%0,%1,%2,%3};"
        : "+f"(c[0]), "+f"(c[1]), "+f"(c[2]), "+f"(c[3])
        : "r"(a[0]), "r"(a[1]), "r"(a[2]), "r"(a[3]), "r"(b[0]), "r"(b[1]));
}
__device__ __forceinline__ float silu(float v) { return v / (1.f + __expf(-v)); }

// ---------------- mma.sync split-bf16 GEMM, 256x128 tile, 2-stage -----------
#define KCH     64
#define NKCH    (512/KCH)          // 8
#define A_TILEB 32768              // 256x64 bf16
#define B_TILEB 16384              // 128x64 bf16
#define STG_SZ  (2*A_TILEB + 2*B_TILEB)   // 98304
#define MMA_SMEM (2*STG_SZ)               // 196608

__device__ __forceinline__ void mma_load_chunk(
    const __nv_bfloat16* __restrict__ Ah, const __nv_bfloat16* __restrict__ Al,
    const __nv_bfloat16* __restrict__ Bh, const __nv_bfloat16* __restrict__ Bl,
    int m0, int n0, int kc, uint32_t stage)
{
    const int t = threadIdx.x;
#pragma unroll
    for (int it = 0; it < 12; it++) {
        int idx = it * 512 + t;            // 0..6143 16B-chunks
        const __nv_bfloat16* gb;
        uint32_t toff;
        int local, base;
        if (idx < 4096) {
            int which = idx >> 11;
            local = idx & 2047;
            gb = which ? Al : Ah;
            toff = which ? A_TILEB : 0u;
            base = m0;
        } else {
            int idx2 = idx - 4096;
            int which = idx2 >> 10;
            local = idx2 & 1023;
            gb = which ? Bl : Bh;
            toff = 2 * A_TILEB + (which ? B_TILEB : 0);
            base = n0;
        }
        int row = local >> 3;
        int c   = local & 7;
        const void* ga = gb + (size_t)(base + row) * 512 + kc * KCH + c * 8;
        uint32_t sa = stage + toff + row * 128 + ((c ^ (row & 7)) << 4);
        asm volatile("cp.async.cg.shared.global [%0], [%1], 16;" :: "r"(sa), "l"(ga));
    }
}

template<bool RESID>
__global__ __launch_bounds__(512)
void k_mma(const __nv_bfloat16* __restrict__ Ah, const __nv_bfloat16* __restrict__ Al,
           const __nv_bfloat16* __restrict__ Bh, const __nv_bfloat16* __restrict__ Bl,
           float* __restrict__ C, int N, const float* __restrict__ resid)
{
    extern __shared__ __align__(128) char smem[];
    const uint32_t sb = smem_u32(smem);
    const int m0 = blockIdx.y * 256;
    const int n0 = blockIdx.x * 128;
    const int w  = threadIdx.x >> 5;
    const int lane = threadIdx.x & 31;
    const int wm = (w >> 2) * 64;
    const int wn = (w & 3) * 32;

    float acc[4][4][4];
#pragma unroll
    for (int i = 0; i < 4; i++)
#pragma unroll
        for (int j = 0; j < 4; j++)
#pragma unroll
            for (int q = 0; q < 4; q++) acc[i][j][q] = 0.f;

    const int ar  = lane & 15;
    const int ach = lane >> 4;
    const int bt8 = lane & 7;
    const int bn8 = (lane >> 4) << 3;
    const int bch = (lane >> 3) & 1;

    mma_load_chunk(Ah, Al, Bh, Bl, m0, n0, 0, sb);
    asm volatile("cp.async.commit_group;");
    mma_load_chunk(Ah, Al, Bh, Bl, m0, n0, 1, sb + STG_SZ);
    asm volatile("cp.async.commit_group;");

    for (int i = 0; i < NKCH; i++) {
        if (i < NKCH - 1) asm volatile("cp.async.wait_group 1;");
        else              asm volatile("cp.async.wait_group 0;");
        __syncthreads();

        const uint32_t stg = sb + (i & 1) * STG_SZ;
        const uint32_t sAh = stg, sAl = stg + A_TILEB;
        const uint32_t sBh = stg + 2 * A_TILEB, sBl = stg + 2 * A_TILEB + B_TILEB;

#pragma unroll
        for (int ks = 0; ks < 4; ks++) {
            uint32_t bh[2][4], bl[2][4];
#pragma unroll
            for (int ni = 0; ni < 2; ni++) {
                int n = wn + ni * 16 + bn8 + bt8;
                int c = ks * 2 + bch;
                uint32_t off = n * 128 + (((uint32_t)(c ^ (n & 7))) << 4);
                ldsm4(bh[ni], sBh + off);
                ldsm4(bl[ni], sBl + off);
            }
#pragma unroll
            for (int mih = 0; mih < 2; mih++) {
                uint32_t ah2[2][4], al2[2][4];
#pragma unroll
                for (int m2 = 0; m2 < 2; m2++) {
                    int r = wm + (mih * 2 + m2) * 16 + ar;
                    int c = ks * 2 + ach;
                    uint32_t off = r * 128 + (((uint32_t)(c ^ (r & 7))) << 4);
                    ldsm4(ah2[m2], sAh + off);
                    ldsm4(al2[m2], sAl + off);
                }
#pragma unroll
                for (int m2 = 0; m2 < 2; m2++)
#pragma unroll
                    for (int nj = 0; nj < 4; nj++) {
                        const uint32_t* bhp = &bh[nj >> 1][(nj & 1) * 2];
                        const uint32_t* blp = &bl[nj >> 1][(nj & 1) * 2];
                        float* ac = acc[mih * 2 + m2][nj];
                        mma16816(ac, ah2[m2], bhp);
                        mma16816(ac, ah2[m2], blp);
                        mma16816(ac, al2[m2], bhp);
                    }
            }
        }

        if (i < NKCH - 2) {
            __syncthreads();
            mma_load_chunk(Ah, Al, Bh, Bl, m0, n0, i + 2, stg);
            asm volatile("cp.async.commit_group;");
        }
    }

#pragma unroll
    for (int mi = 0; mi < 4; mi++) {
        int m = m0 + wm + mi * 16 + (lane >> 2);
#pragma unroll
        for (int nj = 0; nj < 4; nj++) {
            int n = n0 + wn + nj * 8 + ((lane & 3) << 1);
            float2 v0 = make_float2(acc[mi][nj][0], acc[mi][nj][1]);
            float2 v1 = make_float2(acc[mi][nj][2], acc[mi][nj][3]);
            if (RESID) {
                float2 r0 = *(const float2*)(resid + (size_t)m * N + n);
                float2 r1 = *(const float2*)(resid + (size_t)(m + 8) * N + n);
                v0.x += r0.x; v0.y += r0.y; v1.x += r1.x; v1.y += r1.y;
            }
            *(float2*)(C + (size_t)m * N + n)       = v0;
            *(float2*)(C + (size_t)(m + 8) * N + n) = v1;
        }
    }
}

// ---------------- x_proj: fused conv+silu A-build + split-bf16 mma ----------
// Tile 128(M) x 64(N, 48 valid), K-chunk 64, A built in-kernel from
// register-prefetched xz (one chunk ahead), B cp.async double-buffered.
#define XP_A    16384              // 128x64 bf16
#define XP_B    8192               // 64x64 bf16
#define XP_STG  (2*XP_A + 2*XP_B)  // 49152
#define XP_SMEM (2*XP_STG)         // 98304

struct XpRegs { float4 v[9]; };    // xprev + 8 rows

__device__ __forceinline__ void xp_load_B(
    const __nv_bfloat16* __restrict__ Wh, const __nv_bfloat16* __restrict__ Wl,
    int kc, uint32_t stage)
{
    const int t = threadIdx.x;
#pragma unroll
    for (int it = 0; it < 3; it++) {
        int idx = it * 256 + t;            // 0..767
        int which = idx >= 384;
        int local = idx - which * 384;
        int row = local >> 3;              // 0..47
        int c   = local & 7;
        const void* ga = (which ? Wl : Wh) + (size_t)row * 512 + kc * KCH + c * 8;
        uint32_t sa = stage + 2 * XP_A + which * XP_B + row * 128 + ((c ^ (row & 7)) << 4);
        asm volatile("cp.async.cg.shared.global [%0], [%1], 16;" :: "r"(sa), "l"(ga));
    }
}

__device__ __forceinline__ void xp_loadregs(
    XpRegs& R, const float* __restrict__ xz, int i,
    int d, int s0, int r_lo, int g0, int dir)
{
    const float* basep = xz + i * KCH + d;
    R.v[0] = (s0 + r_lo) > 0
        ? *(const float4*)(basep + (size_t)(g0 + dir * (r_lo - 1)) * (2 * DI))
        : make_float4(0.f, 0.f, 0.f, 0.f);
#pragma unroll
    for (int j = 0; j < 8; j++)
        R.v[1 + j] = *(const float4*)(basep + (size_t)(g0 + dir * (r_lo + j)) * (2 * DI));
}

__device__ __forceinline__ void xp_convert(
    const XpRegs& R, char* smem, int i,
    int d, int r_lo, const float* __restrict__ cw, const float* __restrict__ cb)
{
    const int ch = i * KCH + d;
    float4 cwa  = *(const float4*)(cw + ch * 2);       // w0,w1 [ch], [ch+1]
    float4 cwb2 = *(const float4*)(cw + ch * 2 + 4);   // w0,w1 [ch+2], [ch+3]
    float4 cbv  = *(const float4*)(cb + ch);
    float4 xprev = R.v[0];
    const uint32_t sbase = (i & 1) * XP_STG;
#pragma unroll
    for (int j = 0; j < 8; j++) {
        const int r = r_lo + j;
        float4 xc = R.v[1 + j];
        float u0 = silu(fmaf(cwa.x,  xprev.x, fmaf(cwa.y,  xc.x, cbv.x)));
        float u1 = silu(fmaf(cwa.z,  xprev.y, fmaf(cwa.w,  xc.y, cbv.y)));
        float u2 = silu(fmaf(cwb2.x, xprev.z, fmaf(cwb2.y, xc.z, cbv.z)));
        float u3 = silu(fmaf(cwb2.z, xprev.w, fmaf(cwb2.w, xc.w, cbv.w)));
        xprev = xc;
        __nv_bfloat16 h0 = __float2bfloat16(u0), h1 = __float2bfloat16(u1);
        __nv_bfloat16 h2 = __float2bfloat16(u2), h3 = __float2bfloat16(u3);
        __nv_bfloat16 l0 = __float2bfloat16(u0 - __bfloat162float(h0));
        __nv_bfloat16 l1 = __float2bfloat16(u1 - __bfloat162float(h1));
        __nv_bfloat16 l2 = __float2bfloat16(u2 - __bfloat162float(h2));
        __nv_bfloat16 l3 = __float2bfloat16(u3 - __bfloat162float(h3));
        const int c16 = d >> 3;
        uint32_t off = sbase + r * 128
                     + ((uint32_t)(c16 ^ (r & 7)) << 4) + (d & 7) * 2;
        uint2 hv, lv;
        __nv_bfloat162 p;
        p = __nv_bfloat162(h0, h1); hv.x = *(uint32_t*)&p;
        p = __nv_bfloat162(h2, h3); hv.y = *(uint32_t*)&p;
        p = __nv_bfloat162(l0, l1); lv.x = *(uint32_t*)&p;
        p = __nv_bfloat162(l2, l3); lv.y = *(uint32_t*)&p;
        *(uint2*)(smem + off)        = hv;
        *(uint2*)(smem + off + XP_A) = lv;
    }
}

__global__ __launch_bounds__(256, 2)
void k_xproj(const float* __restrict__ xz,
             const float* __restrict__ cw0, const float* __restrict__ cb0,
             const float* __restrict__ cw1, const float* __restrict__ cb1,
             const __nv_bfloat16* __restrict__ xwh0, const __nv_bfloat16* __restrict__ xwl0,
             const __nv_bfloat16* __restrict__ xwh1, const __nv_bfloat16* __restrict__ xwl1,
             float* __restrict__ C0, float* __restrict__ C1)
{
    extern __shared__ __align__(128) char smem[];
    const uint32_t sb = smem_u32(smem);
    const int br = blockIdx.y;
    const int m0 = blockIdx.x * 128;
    const int t  = threadIdx.x;
    const int w  = t >> 5;
    const int lane = t & 31;

    const float* cw = br ? cw1 : cw0;
    const float* cb = br ? cb1 : cb0;
    const __nv_bfloat16* Wh = br ? xwh1 : xwh0;
    const __nv_bfloat16* Wl = br ? xwl1 : xwl0;
    float* C = br ? C1 : C0;

    const int s0  = m0 & (LSEQ - 1);
    const int bb  = m0 >> 12;
    const int g0  = br ? (bb * LSEQ + LSEQ - 1 - s0) : m0;  // gmem row of scan row 0
    const int dir = br ? -1 : 1;

    // zero B pad rows (48..63) of both stages/tiles once
    for (int i = t; i < 2048; i += 256) {
        int region = i >> 9;               // 0..3: stage0(hi),(lo),stage1(hi),(lo)
        uint32_t off = (region >> 1) * XP_STG + 2 * XP_A + (region & 1) * XP_B
                     + 6144 + (i & 511) * 4;
        *(uint32_t*)(smem + off) = 0u;
    }

    // convert-thread mapping: 16 d-quads x 16 row-groups of 8
    const int dq = t & 15;
    const int rg = t >> 4;
    const int d  = dq * 4;
    const int r_lo = rg * 8;

    // mma thread constants
    const int wm = (w >> 1) * 32;
    const int wn = (w & 1) * 32;
    const int ar  = lane & 15;
    const int ach = lane >> 4;
    const int bt8 = lane & 7;
    const int bn8 = (lane >> 4) << 3;
    const int bch = (lane >> 3) & 1;

    float acc[2][4][4];
#pragma unroll
    for (int i = 0; i < 2; i++)
#pragma unroll
        for (int j = 0; j < 4; j++)
#pragma unroll
            for (int q = 0; q < 4; q++) acc[i][j][q] = 0.f;

    // prologue: regs(0) -> convert(0); B(0), B(1) in flight; regs(1) prefetched
    XpRegs R;
    xp_loadregs(R, xz, 0, d, s0, r_lo, g0, dir);
    xp_load_B(Wh, Wl, 0, sb);
    asm volatile("cp.async.commit_group;");
    xp_load_B(Wh, Wl, 1, sb + XP_STG);
    asm volatile("cp.async.commit_group;");
    xp_convert(R, smem, 0, d, r_lo, cw, cb);
    xp_loadregs(R, xz, 1, d, s0, r_lo, g0, dir);

    for (int i = 0; i < NKCH; i++) {
        if (i < NKCH - 1) asm volatile("cp.async.wait_group 1;");
        else              asm volatile("cp.async.wait_group 0;");
        __syncthreads();

        const uint32_t stg = sb + (i & 1) * XP_STG;
        const uint32_t sAh = stg, sAl = stg + XP_A;
        const uint32_t sBh = stg + 2 * XP_A, sBl = stg + 2 * XP_A + XP_B;
#pragma unroll
        for (int ks = 0; ks < 4; ks++) {
            uint32_t ah[2][4], al[2][4], bh[2][4], bl[2][4];
#pragma unroll
            for (int mi = 0; mi < 2; mi++) {
                int r = wm + mi * 16 + ar;
                int c = ks * 2 + ach;
                uint32_t off = r * 128 + (((uint32_t)(c ^ (r & 7))) << 4);
                ldsm4(ah[mi], sAh + off);
                ldsm4(al[mi], sAl + off);
            }
#pragma unroll
            for (int ni = 0; ni < 2; ni++) {
                int n = wn + ni * 16 + bn8 + bt8;
                int c = ks * 2 + bch;
                uint32_t off = n * 128 + (((uint32_t)(c ^ (n & 7))) << 4);
                ldsm4(bh[ni], sBh + off);
                ldsm4(bl[ni], sBl + off);
            }
#pragma unroll
            for (int mi = 0; mi < 2; mi++)
#pragma unroll
                for (int nj = 0; nj < 4; nj++) {
                    const uint32_t* bhp = &bh[nj >> 1][(nj & 1) * 2];
                    const uint32_t* blp = &bl[nj >> 1][(nj & 1) * 2];
                    mma16816(acc[mi][nj], ah[mi], bhp);
                    mma16816(acc[mi][nj], ah[mi], blp);
                    mma16816(acc[mi][nj], al[mi], bhp);
                }
        }

        if (i < NKCH - 1) {
            __syncthreads();   // all MMA(i) reads done: stage i&1 B free, stage (i+1)&1 A free
            xp_convert(R, smem, i + 1, d, r_lo, cw, cb);   // A for chunk i+1
            if (i < NKCH - 2) {
                xp_load_B(Wh, Wl, i + 2, stg);              // B into stage i&1
                asm volatile("cp.async.commit_group;");
                xp_loadregs(R, xz, i + 2, d, s0, r_lo, g0, dir);
            }
        }
    }

    // epilogue: C is [NTOK][48]
#pragma unroll
    for (int mi = 0; mi < 2; mi++) {
        int m = m0 + wm + mi * 16 + (lane >> 2);
#pragma unroll
        for (int nj = 0; nj < 4; nj++) {
            int n = wn + nj * 8 + ((lane & 3) << 1);
            if (n < DBCW) {
                *(float2*)(C + (size_t)m * DBCW + n) =
                    make_float2(acc[mi][nj][0], acc[mi][nj][1]);
                *(float2*)(C + (size_t)(m + 8) * DBCW + n) =
                    make_float2(acc[mi][nj][2], acc[mi][nj][3]);
            }
        }
    }
}

// ---------------- fp32 -> bf16 hi/lo weight convert (4 weights, 1 launch) ----
__global__ void k_cvt4(const float* __restrict__ w1, __nv_bfloat16* __restrict__ h1,
                       __nv_bfloat16* __restrict__ l1, int n1,
                       const float* __restrict__ w2, __nv_bfloat16* __restrict__ h2,
                       __nv_bfloat16* __restrict__ l2, int n2,
                       const float* __restrict__ w3, __nv_bfloat16* __restrict__ h3,
                       __nv_bfloat16* __restrict__ l3, int n3,
                       const float* __restrict__ w4, __nv_bfloat16* __restrict__ h4,
                       __nv_bfloat16* __restrict__ l4, int n4)
{
    int i = blockIdx.x * blockDim.x + threadIdx.x;
    const float* w; __nv_bfloat16 *hh, *ll; int j;
    if (i < n1)                     { w = w1; hh = h1; ll = l1; j = i; }
    else if (i < n1+n2)             { w = w2; hh = h2; ll = l2; j = i-n1; }
    else if (i < n1+n2+n3)          { w = w3; hh = h3; ll = l3; j = i-n1-n2; }
    else if (i < n1+n2+n3+n4)       { w = w4; hh = h4; ll = l4; j = i-n1-n2-n3; }
    else return;
    float v = w[j];
    __nv_bfloat16 h = __float2bfloat16(v);
    hh[j] = h;
    ll[j] = __float2bfloat16(v - __bfloat162float(h));
}

// ---------------- LayerNorm -> bf16 hi/lo ----------------
__global__ void k_layernorm(const float* __restrict__ x,
                            const float* __restrict__ w,
                            const float* __restrict__ b,
                            __nv_bfloat16* __restrict__ oh,
                            __nv_bfloat16* __restrict__ ol)
{
    int tok  = blockIdx.x * 8 + (threadIdx.x >> 5);
    int lane = threadIdx.x & 31;
    const float* row = x + (size_t)tok * DM;

    float4 v[4];
    float s = 0.f, s2 = 0.f;
#pragma unroll
    for (int i = 0; i < 4; i++) {
        v[i] = *(const float4*)(row + i * 128 + lane * 4);
        s  += v[i].x + v[i].y + v[i].z + v[i].w;
        s2 += v[i].x*v[i].x + v[i].y*v[i].y + v[i].z*v[i].z + v[i].w*v[i].w;
    }
#pragma unroll
    for (int o = 16; o; o >>= 1) {
        s  += __shfl_xor_sync(0xffffffffu, s,  o);
        s2 += __shfl_xor_sync(0xffffffffu, s2, o);
    }
    float mu   = s * (1.f / DM);
    float var  = s2 * (1.f / DM) - mu * mu;
    float rinv = rsqrtf(var + 1e-5f);

#pragma unroll
    for (int i = 0; i < 4; i++) {
        int d = i * 128 + lane * 4;
        float4 w4 = *(const float4*)(w + d);
        float4 b4 = *(const float4*)(b + d);
        float o4[4];
        o4[0] = (v[i].x - mu) * rinv * w4.x + b4.x;
        o4[1] = (v[i].y - mu) * rinv * w4.y + b4.y;
        o4[2] = (v[i].z - mu) * rinv * w4.z + b4.z;
        o4[3] = (v[i].w - mu) * rinv * w4.w + b4.w;
        __nv_bfloat16 hh[4], ll[4];
#pragma unroll
        for (int q = 0; q < 4; q++) {
            hh[q] = __float2bfloat16(o4[q]);
            ll[q] = __float2bfloat16(o4[q] - __bfloat162float(hh[q]));
        }
        *(uint2*)(oh + (size_t)tok * DM + d) = *(uint2*)hh;
        *(uint2*)(ol + (size_t)tok * DM + d) = *(uint2*)ll;
    }
}

// ---------------- zero lookback flags ----------------
__global__ void k_zero(int* __restrict__ flags) {
    flags[blockIdx.x * 1024 + threadIdx.x] = 0;
}

// ---------------- fused conv + dt_proj + softplus + lookback scan -----------
// Decoupled lookback with inclusive-prefix publication:
//   flag 1 = (P,Q) aggregate available; flag 2 = Hp inclusive prefix available.
#define SCAN_SMEM (TCH*128*4 + TCH*49*4)   // 32768 + 12544 = 45312

__global__ __launch_bounds__(128)
void k_scan(const float* __restrict__ xz,
            const float* __restrict__ dbc0, const float* __restrict__ dbc1,
            const float* __restrict__ cw0,  const float* __restrict__ cb0,
            const float* __restrict__ cw1,  const float* __restrict__ cb1,
            const float* __restrict__ Alog0, const float* __restrict__ Alog1,
            const float* __restrict__ dtw0, const float* __restrict__ dtw1,
            const float* __restrict__ dtb0, const float* __restrict__ dtb1,
            const float* __restrict__ Dp0,  const float* __restrict__ Dp1,
            float* __restrict__ y0g, float* __restrict__ y1g,
            float* __restrict__ P0g, float* __restrict__ Q0g, float* __restrict__ Hp0g,
            float* __restrict__ P1g, float* __restrict__ Q1g, float* __restrict__ Hp1g,
            int* __restrict__ flags)
{
    extern __shared__ float sm[];
    float* delta_s = sm;                 // [TCH][128]
    float* dbc_s   = sm + TCH * 128;     // [TCH][49]

    const int t  = threadIdx.x;
    const int dg = blockIdx.x;
    const int b  = blockIdx.y;
    const int br = blockIdx.z & 1;
    const int chunk = blockIdx.z >> 1;
    const int d  = dg * 128 + t;

    const float* dbc = br ? dbc1 : dbc0;
    const float* Alg = br ? Alog1 : Alog0;
    const float* Wdt = br ? dtw1 : dtw0;
    const float* Bdt = br ? dtb1 : dtb0;
    const float* Dpp = br ? Dp1  : Dp0;
    const float* cwp = br ? cw1 : cw0;
    const float* cbp = br ? cb1 : cb0;
    float* y  = br ? y1g : y0g;
    float* Pg = br ? P1g : P0g;
    float* Qg = br ? Q1g : Q0g;
    float* Hpg = br ? Hp1g : Hp0g;

    for (int i = t; i < 128 * 32; i += 128) {
        int rw_ = i >> 5, k = i & 31;
        sm[rw_ * 33 + k] = Wdt[(size_t)(dg * 128) * 32 + i];
    }
    const int tok0 = b * LSEQ + chunk * TCH;
    for (int i = t; i < TCH * 48; i += 128)
        dbc_s[(i / 48) * 49 + (i % 48)] = dbc[(size_t)tok0 * 48 + i];
    __syncthreads();
    float w[32];
#pragma unroll
    for (int k = 0; k < 32; k++) w[k] = sm[t * 33 + k];
    __syncthreads();

    float Av[DS];
    {
        float4 a0 = *(const float4*)(Alg + d * DS);
        float4 a1 = *(const float4*)(Alg + d * DS + 4);
        Av[0] = -__expf(a0.x); Av[1] = -__expf(a0.y); Av[2] = -__expf(a0.z); Av[3] = -__expf(a0.w);
        Av[4] = -__expf(a1.x); Av[5] = -__expf(a1.y); Av[6] = -__expf(a1.z); Av[7] = -__expf(a1.w);
    }
    const float Av0 = Av[0];
    bool uni = true;
#pragma unroll
    for (int n = 1; n < DS; n++)
        uni = uni && (fabsf(Av[n] - (n + 1) * Av0) <= 2e-5f * (n + 1));

    const float bias = Bdt[d];
    const float Dd   = Dpp[d];
    const float cwd0 = cwp[d * 2], cwd1 = cwp[d * 2 + 1], cbd = cbp[d];

    const int s0  = chunk * TCH;
    const int r0  = br ? (b * LSEQ + LSEQ - 1 - s0) : tok0;
    const int dir = br ? -1 : 1;

    float h[DS], P[DS], S = 0.f;
#pragma unroll
    for (int n = 0; n < DS; n++) { h[n] = 0.f; P[n] = 1.f; }

    float xprev = (s0 > 0) ? xz[(size_t)(r0 - dir) * (2 * DI) + d] : 0.f;
    for (int tt = 0; tt < TCH; tt++) {
        float xcur = xz[(size_t)(r0 + dir * tt) * (2 * DI) + d];
        float u = silu(fmaf(cwd0, xprev, fmaf(cwd1, xcur, cbd)));
        xprev = xcur;

        const float* row = &dbc_s[tt * 49];
        float a0 = bias, a1 = 0.f, a2 = 0.f, a3 = 0.f;
#pragma unroll
        for (int k = 0; k < 32; k += 4) {
            a0 = fmaf(row[k + 0], w[k + 0], a0);
            a1 = fmaf(row[k + 1], w[k + 1], a1);
            a2 = fmaf(row[k + 2], w[k + 2], a2);
            a3 = fmaf(row[k + 3], w[k + 3], a3);
        }
        float v = (a0 + a1) + (a2 + a3);
        float dl = (v > 20.f) ? v : log1pf(__expf(v));
        delta_s[tt * 128 + t] = dl;
        float du = dl * u;
        if (uni) {
            S += dl;
            float e1 = __expf(dl * Av0);
            float an = 1.f;
#pragma unroll
            for (int n = 0; n < DS; n++) {
                an *= e1;
                h[n] = fmaf(an, h[n], du * row[32 + n]);
            }
        } else {
#pragma unroll
            for (int n = 0; n < DS; n++) {
                float a = __expf(dl * Av[n]);
                P[n] *= a;
                h[n] = fmaf(a, h[n], du * row[32 + n]);
            }
        }
    }
    if (uni) {
#pragma unroll
        for (int n = 0; n < DS; n++) P[n] = __expf(S * Av[n]);
    }

    // publish aggregate (P, Q), flag = 1
    const int cidx = chunk * NCHAN + b * DI + d;
    {
        *(float4*)(Pg + (size_t)cidx * 8)     = make_float4(P[0], P[1], P[2], P[3]);
        *(float4*)(Pg + (size_t)cidx * 8 + 4) = make_float4(P[4], P[5], P[6], P[7]);
        *(float4*)(Qg + (size_t)cidx * 8)     = make_float4(h[0], h[1], h[2], h[3]);
        *(float4*)(Qg + (size_t)cidx * 8 + 4) = make_float4(h[4], h[5], h[6], h[7]);
    }
    __threadfence();
    __syncthreads();
    const int fi = blockIdx.z * 16 + b * 4 + dg;
    if (t == 0 && chunk > 0) {
        asm volatile("st.global.release.gpu.b32 [%0], %1;" :: "l"(flags + fi), "r"(1) : "memory");
    }

    // decoupled lookback: stop at first predecessor with inclusive prefix
    float h0[DS], pref[DS];
#pragma unroll
    for (int n = 0; n < DS; n++) { h0[n] = 0.f; pref[n] = 1.f; }
    for (int j = chunk - 1; j >= 0; j--) {
        const int fj = (j * 2 + br) * 16 + b * 4 + dg;
        int f;
        do {
            asm volatile("ld.global.acquire.gpu.b32 %0, [%1];" : "=r"(f) : "l"(flags + fj) : "memory");
            if (!f) __nanosleep(64);
        } while (!f);
        const size_t idxj = (size_t)(j * NCHAN + b * DI + d) * 8;
        if (f == 2) {
            float4 ha = *(const float4*)(Hpg + idxj);
            float4 hb = *(const float4*)(Hpg + idxj + 4);
            float hv[DS] = { ha.x, ha.y, ha.z, ha.w, hb.x, hb.y, hb.z, hb.w };
#pragma unroll
            for (int n = 0; n < DS; n++)
                h0[n] = fmaf(pref[n], hv[n], h0[n]);
            break;
        }
        float4 qa = *(const float4*)(Qg + idxj);
        float4 qb = *(const float4*)(Qg + idxj + 4);
        float4 pa = *(const float4*)(Pg + idxj);
        float4 pb = *(const float4*)(Pg + idxj + 4);
        float qv[DS] = { qa.x, qa.y, qa.z, qa.w, qb.x, qb.y, qb.z, qb.w };
        float pv2[DS] = { pa.x, pa.y, pa.z, pa.w, pb.x, pb.y, pb.z, pb.w };
#pragma unroll
        for (int n = 0; n < DS; n++) {
            h0[n] = fmaf(pref[n], qv[n], h0[n]);
            pref[n] *= pv2[n];
        }
    }

    // publish inclusive prefix Hinc = h0*P + Q, flag = 2 (last chunk skips)
    if (chunk < NCH - 1) {
        float4 hia = make_float4(fmaf(h0[0], P[0], h[0]), fmaf(h0[1], P[1], h[1]),
                                 fmaf(h0[2], P[2], h[2]), fmaf(h0[3], P[3], h[3]));
        float4 hib = make_float4(fmaf(h0[4], P[4], h[4]), fmaf(h0[5], P[5], h[5]),
                                 fmaf(h0[6], P[6], h[6]), fmaf(h0[7], P[7], h[7]));
        *(float4*)(Hpg + (size_t)cidx * 8)     = hia;
        *(float4*)(Hpg + (size_t)cidx * 8 + 4) = hib;
        __threadfence();
        __syncthreads();
        if (t == 0) {
            asm volatile("st.global.release.gpu.b32 [%0], %1;" :: "l"(flags + fi), "r"(2) : "memory");
        }
    }

    // sweep 2: full recurrence from h0, emit y (u recomputed; xz L2-hot)
#pragma unroll
    for (int n = 0; n < DS; n++) h[n] = h0[n];
    xprev = (s0 > 0) ? xz[(size_t)(r0 - dir) * (2 * DI) + d] : 0.f;
    for (int tt = 0; tt < TCH; tt++) {
        float xcur = xz[(size_t)(r0 + dir * tt) * (2 * DI) + d];
        float u = silu(fmaf(cwd0, xprev, fmaf(cwd1, xcur, cbd)));
        xprev = xcur;

        float dl = delta_s[tt * 128 + t];
        float du = dl * u;
        const float* row = &dbc_s[tt * 49];
        float yv = 0.f;
        if (uni) {
            float e1 = __expf(dl * Av0);
            float an = 1.f;
#pragma unroll
            for (int n = 0; n < DS; n++) {
                an *= e1;
                h[n] = fmaf(an, h[n], du * row[32 + n]);
                yv = fmaf(h[n], row[40 + n], yv);
            }
        } else {
#pragma unroll
            for (int n = 0; n < DS; n++) {
                float a = __expf(dl * Av[n]);
                h[n] = fmaf(a, h[n], du * row[32 + n]);
                yv = fmaf(h[n], row[40 + n], yv);
            }
        }
        y[(size_t)(tok0 + tt) * DI + d] = fmaf(u, Dd, yv);
    }
}

// ---------------- combine branches, gate, RMSNorm -> bf16 hi/lo ---------------
__global__ void k_rms(const float* __restrict__ yf, const float* __restrict__ yb,
                      const float* __restrict__ xz, const float* __restrict__ rw,
                      __nv_bfloat16* __restrict__ oh, __nv_bfloat16* __restrict__ ol)
{
    int tok  = blockIdx.x * 8 + (threadIdx.x >> 5);
    int lane = threadIdx.x & 31;
    int s    = tok & (LSEQ - 1);
    int rtok = tok - s + (LSEQ - 1 - s);

    float4 v[4];
    float ss = 0.f;
#pragma unroll
    for (int i = 0; i < 4; i++) {
        int d = i * 128 + lane * 4;
        float4 a = *(const float4*)(yf + (size_t)tok * DI + d);
        float4 c = *(const float4*)(yb + (size_t)rtok * DI + d);
        float4 z = *(const float4*)(xz + (size_t)tok * (2 * DI) + DI + d);
        float4 o;
        o.x = 0.5f * (a.x + c.x) * silu(z.x);
        o.y = 0.5f * (a.y + c.y) * silu(z.y);
        o.z = 0.5f * (a.z + c.z) * silu(z.z);
        o.w = 0.5f * (a.w + c.w) * silu(z.w);
        ss += o.x*o.x + o.y*o.y + o.z*o.z + o.w*o.w;
        v[i] = o;
    }
#pragma unroll
    for (int o = 16; o; o >>= 1) ss += __shfl_xor_sync(0xffffffffu, ss, o);
    float sc = rsqrtf(ss * (1.f / DI) + 1e-5f);

#pragma unroll
    for (int i = 0; i < 4; i++) {
        int d = i * 128 + lane * 4;
        float4 w4 = *(const float4*)(rw + d);
        float o4[4];
        o4[0] = v[i].x * sc * w4.x;
        o4[1] = v[i].y * sc * w4.y;
        o4[2] = v[i].z * sc * w4.z;
        o4[3] = v[i].w * sc * w4.w;
        __nv_bfloat16 hh[4], ll[4];
#pragma unroll
        for (int q = 0; q < 4; q++) {
            hh[q] = __float2bfloat16(o4[q]);
            ll[q] = __float2bfloat16(o4[q] - __bfloat162float(hh[q]));
        }
        *(uint2*)(oh + (size_t)tok * DI + d) = *(uint2*)hh;
        *(uint2*)(ol + (size_t)tok * DI + d) = *(uint2*)ll;
    }
}

// ---------------- host launch ----------------
extern "C" void kernel_launch(void* const* d_in, const int* in_sizes, int n_in,
                              void* d_out, int out_size)
{
    const float* x          = (const float*)d_in[0];
    const float* ln_w       = (const float*)d_in[1];
    const float* ln_b       = (const float*)d_in[2];
    const float* in_proj_w  = (const float*)d_in[3];
    const float* conv_w     = (const float*)d_in[4];
    const float* conv_b     = (const float*)d_in[5];
    const float* x_proj_w   = (const float*)d_in[6];
    const float* dt_proj_w  = (const float*)d_in[7];
    const float* dt_proj_b  = (const float*)d_in[8];
    const float* A_log      = (const float*)d_in[9];
    const float* Dp         = (const float*)d_in[10];
    const float* conv_w_b   = (const float*)d_in[11];
    const float* conv_b_b   = (const float*)d_in[12];
    const float* x_proj_w_b = (const float*)d_in[13];
    const float* dt_proj_w_b= (const float*)d_in[14];
    const float* dt_proj_b_b= (const float*)d_in[15];
    const float* A_log_b    = (const float*)d_in[16];
    const float* D_b        = (const float*)d_in[17];
    const float* rms_w      = (const float*)d_in[18];
    const float* out_proj_w = (const float*)d_in[19];
    float* out = (float*)d_out;

    __nv_bfloat16 *lnh, *lnl, *wih, *wil, *woh, *wol, *ynh, *ynl;
    __nv_bfloat16 *xwh0, *xwl0, *xwh1, *xwl1;
    float *xz, *dbc0, *dbc1, *y0, *y1;
    float *P0, *Q0, *Hp0, *P1, *Q1, *Hp1;
    int* flags;
    cudaGetSymbolAddress((void**)&lnh,  g_lnh);
    cudaGetSymbolAddress((void**)&lnl,  g_lnl);
    cudaGetSymbolAddress((void**)&wih,  g_wih);
    cudaGetSymbolAddress((void**)&wil,  g_wil);
    cudaGetSymbolAddress((void**)&woh,  g_woh);
    cudaGetSymbolAddress((void**)&wol,  g_wol);
    cudaGetSymbolAddress((void**)&xwh0, g_xwh0);
    cudaGetSymbolAddress((void**)&xwl0, g_xwl0);
    cudaGetSymbolAddress((void**)&xwh1, g_xwh1);
    cudaGetSymbolAddress((void**)&xwl1, g_xwl1);
    cudaGetSymbolAddress((void**)&ynh,  g_ynh);
    cudaGetSymbolAddress((void**)&ynl,  g_ynl);
    cudaGetSymbolAddress((void**)&xz,   g_xz);
    cudaGetSymbolAddress((void**)&dbc0, g_dbc0);
    cudaGetSymbolAddress((void**)&dbc1, g_dbc1);
    cudaGetSymbolAddress((void**)&y0,   g_y0);
    cudaGetSymbolAddress((void**)&y1,   g_y1);
    cudaGetSymbolAddress((void**)&P0,   g_P0);
    cudaGetSymbolAddress((void**)&Q0,   g_Q0);
    cudaGetSymbolAddress((void**)&Hp0,  g_Hp0);
    cudaGetSymbolAddress((void**)&P1,   g_P1);
    cudaGetSymbolAddress((void**)&Q1,   g_Q1);
    cudaGetSymbolAddress((void**)&Hp1,  g_Hp1);
    cudaGetSymbolAddress((void**)&flags, g_flags);

    cudaFuncSetAttribute(k_mma<false>, cudaFuncAttributeMaxDynamicSharedMemorySize, MMA_SMEM);
    cudaFuncSetAttribute(k_mma<true>,  cudaFuncAttributeMaxDynamicSharedMemorySize, MMA_SMEM);
    cudaFuncSetAttribute(k_xproj, cudaFuncAttributeMaxDynamicSharedMemorySize, XP_SMEM);
    cudaFuncSetAttribute(k_scan, cudaFuncAttributeMaxDynamicSharedMemorySize, SCAN_SMEM);

    // 0. convert weights to bf16 hi/lo (single launch)
    int ncvt = 2*DI*DM + DM*DI + DBCW*DI + DBCW*DI;
    k_cvt4<<<(ncvt + 255)/256, 256>>>(
        in_proj_w, wih, wil, 2*DI*DM,
        out_proj_w, woh, wol, DM*DI,
        x_proj_w,  xwh0, xwl0, DBCW*DI,
        x_proj_w_b, xwh1, xwl1, DBCW*DI);

    // 1. LayerNorm -> bf16 hi/lo
    k_layernorm<<<NTOK / 8, 256>>>(x, ln_w, ln_b, lnh, lnl);

    // 2. in_proj (mma.sync split-bf16, 256x128 tile): -> xz fp32
    k_mma<false><<<dim3(2*DI/128, NTOK/256), 512, MMA_SMEM>>>(lnh, lnl, wih, wil, xz, 2*DI, nullptr);

    // 3. x_proj: fused conv+silu + tensor-core split-bf16, reg-pipelined A
    k_xproj<<<dim3(NTOK/128, 2), 256, XP_SMEM>>>(
        xz, conv_w, conv_b, conv_w_b, conv_b_b,
        xwh0, xwl0, xwh1, xwl1, dbc0, dbc1);

    // 4. fused conv + dt_proj + selective scan (decoupled lookback w/ prefix)
    k_zero<<<2, 1024>>>(flags);
    k_scan<<<dim3(DI/128, BATCH, NCH*2), 128, SCAN_SMEM>>>(
        xz, dbc0, dbc1, conv_w, conv_b, conv_w_b, conv_b_b,
        A_log, A_log_b, dt_proj_w, dt_proj_w_b, dt_proj_b, dt_proj_b_b,
        Dp, D_b, y0, y1, P0, Q0, Hp0, P1, Q1, Hp1, flags);

    // 5. combine + silu(z) gate + RMSNorm -> bf16 hi/lo
    k_rms<<<NTOK / 8, 256>>>(y0, y1, xz, rms_w, ynh, ynl);

    // 6. out_proj (mma.sync split-bf16) + residual -> d_out
    k_mma<true><<<dim3(DM/128, NTOK/256), 512, MMA_SMEM>>>(ynh, ynl, woh, wol, out, DM, x);
}

// round 14
// speedup vs baseline: 1.1889x; 1.0492x over previous
#include <cuda_runtime.h>
#include <cuda_bf16.h>
#include <cstdint>

// ---------------- problem constants ----------------
#define BATCH   4
#define LSEQ    4096
#define NTOK    (BATCH*LSEQ)       // 16384
#define DM      512
#define DI      512
#define DS      8
#define DTRANK  32
#define DBCW    48                 // DT_RANK + 2*D_STATE

// chunked scan config
#define NCH     64
#define TCH     (LSEQ/NCH)         // 64
#define NCHAN   (BATCH*DI)         // 2048
#define CHTOT   (NCHAN*NCH)        // 131072

// ---------------- scratch (device globals; no runtime alloc) ----------------
__device__ __nv_bfloat16 g_lnh[NTOK*DM];
__device__ __nv_bfloat16 g_lnl[NTOK*DM];
__device__ __nv_bfloat16 g_wih[2*DI*DM];
__device__ __nv_bfloat16 g_wil[2*DI*DM];
__device__ __nv_bfloat16 g_woh[DM*DI];
__device__ __nv_bfloat16 g_wol[DM*DI];
__device__ __nv_bfloat16 g_xwh0[DBCW*DI];
__device__ __nv_bfloat16 g_xwl0[DBCW*DI];
__device__ __nv_bfloat16 g_xwh1[DBCW*DI];
__device__ __nv_bfloat16 g_xwl1[DBCW*DI];
__device__ __nv_bfloat16 g_ynh[NTOK*DI];
__device__ __nv_bfloat16 g_ynl[NTOK*DI];
__device__ float g_xz  [NTOK*2*DI];
__device__ float g_dbc0[NTOK*DBCW];
__device__ float g_dbc1[NTOK*DBCW];
__device__ float g_y0  [NTOK*DI];
__device__ float g_y1  [NTOK*DI];
__device__ float g_P0  [DS*CHTOT];
__device__ float g_Q0  [DS*CHTOT];
__device__ float g_Hp0 [DS*CHTOT];
__device__ float g_P1  [DS*CHTOT];
__device__ float g_Q1  [DS*CHTOT];
__device__ float g_Hp1 [DS*CHTOT];
__device__ int   g_flags[2048];

// ---------------- helpers ----------------
__device__ __forceinline__ uint32_t smem_u32(const void* p) {
    uint32_t a;
    asm("{ .reg .u64 t; cvta.to.shared.u64 t, %1; cvt.u32.u64 %0, t; }" : "=r"(a) : "l"(p));
    return a;
}
__device__ __forceinline__ void ldsm4(uint32_t* r, uint32_t addr) {
    asm volatile("ldmatrix.sync.aligned.m8n8.x4.shared.b16 {%0,%1,%2,%3}, [%4];"
        : "=r"(r[0]), "=r"(r[1]), "=r"(r[2]), "=r"(r[3]) : "r"(addr));
}
__device__ __forceinline__ void mma16816(float* c, const uint32_t* a, const uint32_t* b) {
    asm volatile("mma.sync.aligned.m16n8k16.row.col.f32.bf16.bf16.f32 "
        "{%0,%1,%2,%3},{%4,%5,%6,%7},{%8,%9},{%0,%1,%2,%3};"
        : "+f"(c[0]), "+f"(c[1]), "+f"(c[2]), "+f"(c[3])
        : "r"(a[0]), "r"(a[1]), "r"(a[2]), "r"(a[3]), "r"(b[0]), "r"(b[1]));
}
__device__ __forceinline__ float silu(float v) { return v / (1.f + __expf(-v)); }

// ---------------- mma.sync split-bf16 GEMM, 128x64 tile, 2 CTAs/SM ----------
#define KCH     64
#define NKCH    (512/KCH)          // 8
#define M2_A    16384              // 128x64 bf16
#define M2_B    8192               // 64x64 bf16
#define M2_STG  (2*M2_A + 2*M2_B)  // 49152
#define M2_SMEM (2*M2_STG)         // 98304

__device__ __forceinline__ void m2_load(
    const __nv_bfloat16* __restrict__ Ah, const __nv_bfloat16* __restrict__ Al,
    const __nv_bfloat16* __restrict__ Bh, const __nv_bfloat16* __restrict__ Bl,
    int m0, int n0, int kc, uint32_t stage)
{
    const int t = threadIdx.x;
#pragma unroll
    for (int it = 0; it < 12; it++) {
        int idx = it * 256 + t;            // 0..3071 16B-chunks
        const __nv_bfloat16* gb;
        uint32_t toff;
        int local, base;
        if (idx < 2048) {                  // A hi/lo: 128 rows x 8 c16 each
            int which = idx >> 10;
            local = idx & 1023;
            gb = which ? Al : Ah;
            toff = which ? M2_A : 0u;
            base = m0;
        } else {                           // B hi/lo: 64 rows x 8 c16 each
            int idx2 = idx - 2048;
            int which = idx2 >> 9;
            local = idx2 & 511;
            gb = which ? Bl : Bh;
            toff = 2 * M2_A + (which ? M2_B : 0);
            base = n0;
        }
        int row = local >> 3;
        int c   = local & 7;
        const void* ga = gb + (size_t)(base + row) * 512 + kc * KCH + c * 8;
        uint32_t sa = stage + toff + row * 128 + ((c ^ (row & 7)) << 4);
        asm volatile("cp.async.cg.shared.global [%0], [%1], 16;" :: "r"(sa), "l"(ga));
    }
}

template<bool RESID>
__global__ __launch_bounds__(256, 2)
void k_mma(const __nv_bfloat16* __restrict__ Ah, const __nv_bfloat16* __restrict__ Al,
           const __nv_bfloat16* __restrict__ Bh, const __nv_bfloat16* __restrict__ Bl,
           float* __restrict__ C, int N, const float* __restrict__ resid)
{
    extern __shared__ __align__(128) char smem[];
    const uint32_t sb = smem_u32(smem);
    const int m0 = blockIdx.y * 128;
    const int n0 = blockIdx.x * 64;
    const int w  = threadIdx.x >> 5;
    const int lane = threadIdx.x & 31;
    const int wm = (w >> 1) * 32;      // 4x2 warp grid, warp tile 32x32
    const int wn = (w & 1) * 32;

    float acc[2][4][4];
#pragma unroll
    for (int i = 0; i < 2; i++)
#pragma unroll
        for (int j = 0; j < 4; j++)
#pragma unroll
            for (int q = 0; q < 4; q++) acc[i][j][q] = 0.f;

    const int ar  = lane & 15;
    const int ach = lane >> 4;
    const int bt8 = lane & 7;
    const int bn8 = (lane >> 4) << 3;
    const int bch = (lane >> 3) & 1;

    m2_load(Ah, Al, Bh, Bl, m0, n0, 0, sb);
    asm volatile("cp.async.commit_group;");
    m2_load(Ah, Al, Bh, Bl, m0, n0, 1, sb + M2_STG);
    asm volatile("cp.async.commit_group;");

    for (int i = 0; i < NKCH; i++) {
        if (i < NKCH - 1) asm volatile("cp.async.wait_group 1;");
        else              asm volatile("cp.async.wait_group 0;");
        __syncthreads();

        const uint32_t stg = sb + (i & 1) * M2_STG;
        const uint32_t sAh = stg, sAl = stg + M2_A;
        const uint32_t sBh = stg + 2 * M2_A, sBl = stg + 2 * M2_A + M2_B;

#pragma unroll
        for (int ks = 0; ks < 4; ks++) {
            uint32_t ah[2][4], al[2][4], bh[2][4], bl[2][4];
#pragma unroll
            for (int mi = 0; mi < 2; mi++) {
                int r = wm + mi * 16 + ar;
                int c = ks * 2 + ach;
                uint32_t off = r * 128 + (((uint32_t)(c ^ (r & 7))) << 4);
                ldsm4(ah[mi], sAh + off);
                ldsm4(al[mi], sAl + off);
            }
#pragma unroll
            for (int ni = 0; ni < 2; ni++) {
                int n = wn + ni * 16 + bn8 + bt8;
                int c = ks * 2 + bch;
                uint32_t off = n * 128 + (((uint32_t)(c ^ (n & 7))) << 4);
                ldsm4(bh[ni], sBh + off);
                ldsm4(bl[ni], sBl + off);
            }
#pragma unroll
            for (int mi = 0; mi < 2; mi++)
#pragma unroll
                for (int nj = 0; nj < 4; nj++) {
                    const uint32_t* bhp = &bh[nj >> 1][(nj & 1) * 2];
                    const uint32_t* blp = &bl[nj >> 1][(nj & 1) * 2];
                    mma16816(acc[mi][nj], ah[mi], bhp);
                    mma16816(acc[mi][nj], ah[mi], blp);
                    mma16816(acc[mi][nj], al[mi], bhp);
                }
        }

        if (i < NKCH - 2) {
            __syncthreads();
            m2_load(Ah, Al, Bh, Bl, m0, n0, i + 2, stg);
            asm volatile("cp.async.commit_group;");
        }
    }

#pragma unroll
    for (int mi = 0; mi < 2; mi++) {
        int m = m0 + wm + mi * 16 + (lane >> 2);
#pragma unroll
        for (int nj = 0; nj < 4; nj++) {
            int n = n0 + wn + nj * 8 + ((lane & 3) << 1);
            float2 v0 = make_float2(acc[mi][nj][0], acc[mi][nj][1]);
            float2 v1 = make_float2(acc[mi][nj][2], acc[mi][nj][3]);
            if (RESID) {
                float2 r0 = *(const float2*)(resid + (size_t)m * N + n);
                float2 r1 = *(const float2*)(resid + (size_t)(m + 8) * N + n);
                v0.x += r0.x; v0.y += r0.y; v1.x += r1.x; v1.y += r1.y;
            }
            *(float2*)(C + (size_t)m * N + n)       = v0;
            *(float2*)(C + (size_t)(m + 8) * N + n) = v1;
        }
    }
}

// ---------------- x_proj: fused conv+silu A-build + split-bf16 mma ----------
#define XP_A    16384              // 128x64 bf16
#define XP_B    8192               // 64x64 bf16
#define XP_STG  (2*XP_A + 2*XP_B)  // 49152
#define XP_SMEM (2*XP_STG)         // 98304

struct XpRegs { float4 v[9]; };    // xprev + 8 rows

__device__ __forceinline__ void xp_load_B(
    const __nv_bfloat16* __restrict__ Wh, const __nv_bfloat16* __restrict__ Wl,
    int kc, uint32_t stage)
{
    const int t = threadIdx.x;
#pragma unroll
    for (int it = 0; it < 3; it++) {
        int idx = it * 256 + t;            // 0..767
        int which = idx >= 384;
        int local = idx - which * 384;
        int row = local >> 3;              // 0..47
        int c   = local & 7;
        const void* ga = (which ? Wl : Wh) + (size_t)row * 512 + kc * KCH + c * 8;
        uint32_t sa = stage + 2 * XP_A + which * XP_B + row * 128 + ((c ^ (row & 7)) << 4);
        asm volatile("cp.async.cg.shared.global [%0], [%1], 16;" :: "r"(sa), "l"(ga));
    }
}

__device__ __forceinline__ void xp_loadregs(
    XpRegs& R, const float* __restrict__ xz, int i,
    int d, int s0, int r_lo, int g0, int dir)
{
    const float* basep = xz + i * KCH + d;
    R.v[0] = (s0 + r_lo) > 0
        ? *(const float4*)(basep + (size_t)(g0 + dir * (r_lo - 1)) * (2 * DI))
        : make_float4(0.f, 0.f, 0.f, 0.f);
#pragma unroll
    for (int j = 0; j < 8; j++)
        R.v[1 + j] = *(const float4*)(basep + (size_t)(g0 + dir * (r_lo + j)) * (2 * DI));
}

__device__ __forceinline__ void xp_convert(
    const XpRegs& R, char* smem, int i,
    int d, int r_lo, const float* __restrict__ cw, const float* __restrict__ cb)
{
    const int ch = i * KCH + d;
    float4 cwa  = *(const float4*)(cw + ch * 2);       // w0,w1 [ch], [ch+1]
    float4 cwb2 = *(const float4*)(cw + ch * 2 + 4);   // w0,w1 [ch+2], [ch+3]
    float4 cbv  = *(const float4*)(cb + ch);
    float4 xprev = R.v[0];
    const uint32_t sbase = (i & 1) * XP_STG;
#pragma unroll
    for (int j = 0; j < 8; j++) {
        const int r = r_lo + j;
        float4 xc = R.v[1 + j];
        float u0 = silu(fmaf(cwa.x,  xprev.x, fmaf(cwa.y,  xc.x, cbv.x)));
        float u1 = silu(fmaf(cwa.z,  xprev.y, fmaf(cwa.w,  xc.y, cbv.y)));
        float u2 = silu(fmaf(cwb2.x, xprev.z, fmaf(cwb2.y, xc.z, cbv.z)));
        float u3 = silu(fmaf(cwb2.z, xprev.w, fmaf(cwb2.w, xc.w, cbv.w)));
        xprev = xc;
        __nv_bfloat16 h0 = __float2bfloat16(u0), h1 = __float2bfloat16(u1);
        __nv_bfloat16 h2 = __float2bfloat16(u2), h3 = __float2bfloat16(u3);
        __nv_bfloat16 l0 = __float2bfloat16(u0 - __bfloat162float(h0));
        __nv_bfloat16 l1 = __float2bfloat16(u1 - __bfloat162float(h1));
        __nv_bfloat16 l2 = __float2bfloat16(u2 - __bfloat162float(h2));
        __nv_bfloat16 l3 = __float2bfloat16(u3 - __bfloat162float(h3));
        const int c16 = d >> 3;
        uint32_t off = sbase + r * 128
                     + ((uint32_t)(c16 ^ (r & 7)) << 4) + (d & 7) * 2;
        uint2 hv, lv;
        __nv_bfloat162 p;
        p = __nv_bfloat162(h0, h1); hv.x = *(uint32_t*)&p;
        p = __nv_bfloat162(h2, h3); hv.y = *(uint32_t*)&p;
        p = __nv_bfloat162(l0, l1); lv.x = *(uint32_t*)&p;
        p = __nv_bfloat162(l2, l3); lv.y = *(uint32_t*)&p;
        *(uint2*)(smem + off)        = hv;
        *(uint2*)(smem + off + XP_A) = lv;
    }
}

__global__ __launch_bounds__(256, 2)
void k_xproj(const float* __restrict__ xz,
             const float* __restrict__ cw0, const float* __restrict__ cb0,
             const float* __restrict__ cw1, const float* __restrict__ cb1,
             const __nv_bfloat16* __restrict__ xwh0, const __nv_bfloat16* __restrict__ xwl0,
             const __nv_bfloat16* __restrict__ xwh1, const __nv_bfloat16* __restrict__ xwl1,
             float* __restrict__ C0, float* __restrict__ C1)
{
    extern __shared__ __align__(128) char smem[];
    const uint32_t sb = smem_u32(smem);
    const int br = blockIdx.y;
    const int m0 = blockIdx.x * 128;
    const int t  = threadIdx.x;
    const int w  = t >> 5;
    const int lane = t & 31;

    const float* cw = br ? cw1 : cw0;
    const float* cb = br ? cb1 : cb0;
    const __nv_bfloat16* Wh = br ? xwh1 : xwh0;
    const __nv_bfloat16* Wl = br ? xwl1 : xwl0;
    float* C = br ? C1 : C0;

    const int s0  = m0 & (LSEQ - 1);
    const int bb  = m0 >> 12;
    const int g0  = br ? (bb * LSEQ + LSEQ - 1 - s0) : m0;  // gmem row of scan row 0
    const int dir = br ? -1 : 1;

    // zero B pad rows (48..63) of both stages/tiles once
    for (int i = t; i < 2048; i += 256) {
        int region = i >> 9;               // 0..3: stage0(hi),(lo),stage1(hi),(lo)
        uint32_t off = (region >> 1) * XP_STG + 2 * XP_A + (region & 1) * XP_B
                     + 6144 + (i & 511) * 4;
        *(uint32_t*)(smem + off) = 0u;
    }

    // convert-thread mapping: 16 d-quads x 16 row-groups of 8
    const int dq = t & 15;
    const int rg = t >> 4;
    const int d  = dq * 4;
    const int r_lo = rg * 8;

    // mma thread constants
    const int wm = (w >> 1) * 32;
    const int wn = (w & 1) * 32;
    const int ar  = lane & 15;
    const int ach = lane >> 4;
    const int bt8 = lane & 7;
    const int bn8 = (lane >> 4) << 3;
    const int bch = (lane >> 3) & 1;

    float acc[2][4][4];
#pragma unroll
    for (int i = 0; i < 2; i++)
#pragma unroll
        for (int j = 0; j < 4; j++)
#pragma unroll
            for (int q = 0; q < 4; q++) acc[i][j][q] = 0.f;

    // prologue: regs(0) -> convert(0); B(0), B(1) in flight; regs(1) prefetched
    XpRegs R;
    xp_loadregs(R, xz, 0, d, s0, r_lo, g0, dir);
    xp_load_B(Wh, Wl, 0, sb);
    asm volatile("cp.async.commit_group;");
    xp_load_B(Wh, Wl, 1, sb + XP_STG);
    asm volatile("cp.async.commit_group;");
    xp_convert(R, smem, 0, d, r_lo, cw, cb);
    xp_loadregs(R, xz, 1, d, s0, r_lo, g0, dir);

    for (int i = 0; i < NKCH; i++) {
        if (i < NKCH - 1) asm volatile("cp.async.wait_group 1;");
        else              asm volatile("cp.async.wait_group 0;");
        __syncthreads();

        const uint32_t stg = sb + (i & 1) * XP_STG;
        const uint32_t sAh = stg, sAl = stg + XP_A;
        const uint32_t sBh = stg + 2 * XP_A, sBl = stg + 2 * XP_A + XP_B;
#pragma unroll
        for (int ks = 0; ks < 4; ks++) {
            uint32_t ah[2][4], al[2][4], bh[2][4], bl[2][4];
#pragma unroll
            for (int mi = 0; mi < 2; mi++) {
                int r = wm + mi * 16 + ar;
                int c = ks * 2 + ach;
                uint32_t off = r * 128 + (((uint32_t)(c ^ (r & 7))) << 4);
                ldsm4(ah[mi], sAh + off);
                ldsm4(al[mi], sAl + off);
            }
#pragma unroll
            for (int ni = 0; ni < 2; ni++) {
                int n = wn + ni * 16 + bn8 + bt8;
                int c = ks * 2 + bch;
                uint32_t off = n * 128 + (((uint32_t)(c ^ (n & 7))) << 4);
                ldsm4(bh[ni], sBh + off);
                ldsm4(bl[ni], sBl + off);
            }
#pragma unroll
            for (int mi = 0; mi < 2; mi++)
#pragma unroll
                for (int nj = 0; nj < 4; nj++) {
                    const uint32_t* bhp = &bh[nj >> 1][(nj & 1) * 2];
                    const uint32_t* blp = &bl[nj >> 1][(nj & 1) * 2];
                    mma16816(acc[mi][nj], ah[mi], bhp);
                    mma16816(acc[mi][nj], ah[mi], blp);
                    mma16816(acc[mi][nj], al[mi], bhp);
                }
        }

        if (i < NKCH - 1) {
            __syncthreads();   // all MMA(i) reads done: stage i&1 B free, stage (i+1)&1 A free
            xp_convert(R, smem, i + 1, d, r_lo, cw, cb);   // A for chunk i+1
            if (i < NKCH - 2) {
                xp_load_B(Wh, Wl, i + 2, stg);              // B into stage i&1
                asm volatile("cp.async.commit_group;");
                xp_loadregs(R, xz, i + 2, d, s0, r_lo, g0, dir);
            }
        }
    }

    // epilogue: C is [NTOK][48]
#pragma unroll
    for (int mi = 0; mi < 2; mi++) {
        int m = m0 + wm + mi * 16 + (lane >> 2);
#pragma unroll
        for (int nj = 0; nj < 4; nj++) {
            int n = wn + nj * 8 + ((lane & 3) << 1);
            if (n < DBCW) {
                *(float2*)(C + (size_t)m * DBCW + n) =
                    make_float2(acc[mi][nj][0], acc[mi][nj][1]);
                *(float2*)(C + (size_t)(m + 8) * DBCW + n) =
                    make_float2(acc[mi][nj][2], acc[mi][nj][3]);
            }
        }
    }
}

// ---------------- fp32 -> bf16 hi/lo weight convert (4 weights, 1 launch) ----
__global__ void k_cvt4(const float* __restrict__ w1, __nv_bfloat16* __restrict__ h1,
                       __nv_bfloat16* __restrict__ l1, int n1,
                       const float* __restrict__ w2, __nv_bfloat16* __restrict__ h2,
                       __nv_bfloat16* __restrict__ l2, int n2,
                       const float* __restrict__ w3, __nv_bfloat16* __restrict__ h3,
                       __nv_bfloat16* __restrict__ l3, int n3,
                       const float* __restrict__ w4, __nv_bfloat16* __restrict__ h4,
                       __nv_bfloat16* __restrict__ l4, int n4)
{
    int i = blockIdx.x * blockDim.x + threadIdx.x;
    const float* w; __nv_bfloat16 *hh, *ll; int j;
    if (i < n1)                     { w = w1; hh = h1; ll = l1; j = i; }
    else if (i < n1+n2)             { w = w2; hh = h2; ll = l2; j = i-n1; }
    else if (i < n1+n2+n3)          { w = w3; hh = h3; ll = l3; j = i-n1-n2; }
    else if (i < n1+n2+n3+n4)       { w = w4; hh = h4; ll = l4; j = i-n1-n2-n3; }
    else return;
    float v = w[j];
    __nv_bfloat16 h = __float2bfloat16(v);
    hh[j] = h;
    ll[j] = __float2bfloat16(v - __bfloat162float(h));
}

// ---------------- LayerNorm -> bf16 hi/lo ----------------
__global__ void k_layernorm(const float* __restrict__ x,
                            const float* __restrict__ w,
                            const float* __restrict__ b,
                            __nv_bfloat16* __restrict__ oh,
                            __nv_bfloat16* __restrict__ ol)
{
    int tok  = blockIdx.x * 8 + (threadIdx.x >> 5);
    int lane = threadIdx.x & 31;
    const float* row = x + (size_t)tok * DM;

    float4 v[4];
    float s = 0.f, s2 = 0.f;
#pragma unroll
    for (int i = 0; i < 4; i++) {
        v[i] = *(const float4*)(row + i * 128 + lane * 4);
        s  += v[i].x + v[i].y + v[i].z + v[i].w;
        s2 += v[i].x*v[i].x + v[i].y*v[i].y + v[i].z*v[i].z + v[i].w*v[i].w;
    }
#pragma unroll
    for (int o = 16; o; o >>= 1) {
        s  += __shfl_xor_sync(0xffffffffu, s,  o);
        s2 += __shfl_xor_sync(0xffffffffu, s2, o);
    }
    float mu   = s * (1.f / DM);
    float var  = s2 * (1.f / DM) - mu * mu;
    float rinv = rsqrtf(var + 1e-5f);

#pragma unroll
    for (int i = 0; i < 4; i++) {
        int d = i * 128 + lane * 4;
        float4 w4 = *(const float4*)(w + d);
        float4 b4 = *(const float4*)(b + d);
        float o4[4];
        o4[0] = (v[i].x - mu) * rinv * w4.x + b4.x;
        o4[1] = (v[i].y - mu) * rinv * w4.y + b4.y;
        o4[2] = (v[i].z - mu) * rinv * w4.z + b4.z;
        o4[3] = (v[i].w - mu) * rinv * w4.w + b4.w;
        __nv_bfloat16 hh[4], ll[4];
#pragma unroll
        for (int q = 0; q < 4; q++) {
            hh[q] = __float2bfloat16(o4[q]);
            ll[q] = __float2bfloat16(o4[q] - __bfloat162float(hh[q]));
        }
        *(uint2*)(oh + (size_t)tok * DM + d) = *(uint2*)hh;
        *(uint2*)(ol + (size_t)tok * DM + d) = *(uint2*)ll;
    }
}

// ---------------- zero lookback flags ----------------
__global__ void k_zero(int* __restrict__ flags) {
    flags[blockIdx.x * 1024 + threadIdx.x] = 0;
}

// ---------------- fused conv + dt_proj + softplus + lookback scan -----------
// Decoupled lookback with inclusive-prefix publication:
//   flag 1 = (P,Q) aggregate available; flag 2 = Hp inclusive prefix available.
#define SCAN_SMEM (TCH*128*4 + TCH*49*4)   // 32768 + 12544 = 45312

__global__ __launch_bounds__(128)
void k_scan(const float* __restrict__ xz,
            const float* __restrict__ dbc0, const float* __restrict__ dbc1,
            const float* __restrict__ cw0,  const float* __restrict__ cb0,
            const float* __restrict__ cw1,  const float* __restrict__ cb1,
            const float* __restrict__ Alog0, const float* __restrict__ Alog1,
            const float* __restrict__ dtw0, const float* __restrict__ dtw1,
            const float* __restrict__ dtb0, const float* __restrict__ dtb1,
            const float* __restrict__ Dp0,  const float* __restrict__ Dp1,
            float* __restrict__ y0g, float* __restrict__ y1g,
            float* __restrict__ P0g, float* __restrict__ Q0g, float* __restrict__ Hp0g,
            float* __restrict__ P1g, float* __restrict__ Q1g, float* __restrict__ Hp1g,
            int* __restrict__ flags)
{
    extern __shared__ float sm[];
    float* delta_s = sm;                 // [TCH][128]
    float* dbc_s   = sm + TCH * 128;     // [TCH][49]

    const int t  = threadIdx.x;
    const int dg = blockIdx.x;
    const int b  = blockIdx.y;
    const int br = blockIdx.z & 1;
    const int chunk = blockIdx.z >> 1;
    const int d  = dg * 128 + t;

    const float* dbc = br ? dbc1 : dbc0;
    const float* Alg = br ? Alog1 : Alog0;
    const float* Wdt = br ? dtw1 : dtw0;
    const float* Bdt = br ? dtb1 : dtb0;
    const float* Dpp = br ? Dp1  : Dp0;
    const float* cwp = br ? cw1 : cw0;
    const float* cbp = br ? cb1 : cb0;
    float* y  = br ? y1g : y0g;
    float* Pg = br ? P1g : P0g;
    float* Qg = br ? Q1g : Q0g;
    float* Hpg = br ? Hp1g : Hp0g;

    for (int i = t; i < 128 * 32; i += 128) {
        int rw_ = i >> 5, k = i & 31;
        sm[rw_ * 33 + k] = Wdt[(size_t)(dg * 128) * 32 + i];
    }
    const int tok0 = b * LSEQ + chunk * TCH;
    for (int i = t; i < TCH * 48; i += 128)
        dbc_s[(i / 48) * 49 + (i % 48)] = dbc[(size_t)tok0 * 48 + i];
    __syncthreads();
    float w[32];
#pragma unroll
    for (int k = 0; k < 32; k++) w[k] = sm[t * 33 + k];
    __syncthreads();

    float Av[DS];
    {
        float4 a0 = *(const float4*)(Alg + d * DS);
        float4 a1 = *(const float4*)(Alg + d * DS + 4);
        Av[0] = -__expf(a0.x); Av[1] = -__expf(a0.y); Av[2] = -__expf(a0.z); Av[3] = -__expf(a0.w);
        Av[4] = -__expf(a1.x); Av[5] = -__expf(a1.y); Av[6] = -__expf(a1.z); Av[7] = -__expf(a1.w);
    }
    const float Av0 = Av[0];
    bool uni = true;
#pragma unroll
    for (int n = 1; n < DS; n++)
        uni = uni && (fabsf(Av[n] - (n + 1) * Av0) <= 2e-5f * (n + 1));

    const float bias = Bdt[d];
    const float Dd   = Dpp[d];
    const float cwd0 = cwp[d * 2], cwd1 = cwp[d * 2 + 1], cbd = cbp[d];

    const int s0  = chunk * TCH;
    const int r0  = br ? (b * LSEQ + LSEQ - 1 - s0) : tok0;
    const int dir = br ? -1 : 1;

    float h[DS], P[DS], S = 0.f;
#pragma unroll
    for (int n = 0; n < DS; n++) { h[n] = 0.f; P[n] = 1.f; }

    float xprev = (s0 > 0) ? xz[(size_t)(r0 - dir) * (2 * DI) + d] : 0.f;
    for (int tt = 0; tt < TCH; tt++) {
        float xcur = xz[(size_t)(r0 + dir * tt) * (2 * DI) + d];
        float u = silu(fmaf(cwd0, xprev, fmaf(cwd1, xcur, cbd)));
        xprev = xcur;

        const float* row = &dbc_s[tt * 49];
        float a0 = bias, a1 = 0.f, a2 = 0.f, a3 = 0.f;
#pragma unroll
        for (int k = 0; k < 32; k += 4) {
            a0 = fmaf(row[k + 0], w[k + 0], a0);
            a1 = fmaf(row[k + 1], w[k + 1], a1);
            a2 = fmaf(row[k + 2], w[k + 2], a2);
            a3 = fmaf(row[k + 3], w[k + 3], a3);
        }
        float v = (a0 + a1) + (a2 + a3);
        float dl = (v > 20.f) ? v : log1pf(__expf(v));
        delta_s[tt * 128 + t] = dl;
        float du = dl * u;
        if (uni) {
            S += dl;
            float e1 = __expf(dl * Av0);
            float an = 1.f;
#pragma unroll
            for (int n = 0; n < DS; n++) {
                an *= e1;
                h[n] = fmaf(an, h[n], du * row[32 + n]);
            }
        } else {
#pragma unroll
            for (int n = 0; n < DS; n++) {
                float a = __expf(dl * Av[n]);
                P[n] *= a;
                h[n] = fmaf(a, h[n], du * row[32 + n]);
            }
        }
    }
    if (uni) {
#pragma unroll
        for (int n = 0; n < DS; n++) P[n] = __expf(S * Av[n]);
    }

    // publish aggregate (P, Q), flag = 1
    const int cidx = chunk * NCHAN + b * DI + d;
    {
        *(float4*)(Pg + (size_t)cidx * 8)     = make_float4(P[0], P[1], P[2], P[3]);
        *(float4*)(Pg + (size_t)cidx * 8 + 4) = make_float4(P[4], P[5], P[6], P[7]);
        *(float4*)(Qg + (size_t)cidx * 8)     = make_float4(h[0], h[1], h[2], h[3]);
        *(float4*)(Qg + (size_t)cidx * 8 + 4) = make_float4(h[4], h[5], h[6], h[7]);
    }
    __threadfence();
    __syncthreads();
    const int fi = blockIdx.z * 16 + b * 4 + dg;
    if (t == 0 && chunk > 0) {
        asm volatile("st.global.release.gpu.b32 [%0], %1;" :: "l"(flags + fi), "r"(1) : "memory");
    }

    // decoupled lookback: stop at first predecessor with inclusive prefix
    float h0[DS], pref[DS];
#pragma unroll
    for (int n = 0; n < DS; n++) { h0[n] = 0.f; pref[n] = 1.f; }
    for (int j = chunk - 1; j >= 0; j--) {
        const int fj = (j * 2 + br) * 16 + b * 4 + dg;
        int f;
        do {
            asm volatile("ld.global.acquire.gpu.b32 %0, [%1];" : "=r"(f) : "l"(flags + fj) : "memory");
            if (!f) __nanosleep(64);
        } while (!f);
        const size_t idxj = (size_t)(j * NCHAN + b * DI + d) * 8;
        if (f == 2) {
            float4 ha = *(const float4*)(Hpg + idxj);
            float4 hb = *(const float4*)(Hpg + idxj + 4);
            float hv[DS] = { ha.x, ha.y, ha.z, ha.w, hb.x, hb.y, hb.z, hb.w };
#pragma unroll
            for (int n = 0; n < DS; n++)
                h0[n] = fmaf(pref[n], hv[n], h0[n]);
            break;
        }
        float4 qa = *(const float4*)(Qg + idxj);
        float4 qb = *(const float4*)(Qg + idxj + 4);
        float4 pa = *(const float4*)(Pg + idxj);
        float4 pb = *(const float4*)(Pg + idxj + 4);
        float qv[DS] = { qa.x, qa.y, qa.z, qa.w, qb.x, qb.y, qb.z, qb.w };
        float pv2[DS] = { pa.x, pa.y, pa.z, pa.w, pb.x, pb.y, pb.z, pb.w };
#pragma unroll
        for (int n = 0; n < DS; n++) {
            h0[n] = fmaf(pref[n], qv[n], h0[n]);
            pref[n] *= pv2[n];
        }
    }

    // publish inclusive prefix Hinc = h0*P + Q, flag = 2 (last chunk skips)
    if (chunk < NCH - 1) {
        float4 hia = make_float4(fmaf(h0[0], P[0], h[0]), fmaf(h0[1], P[1], h[1]),
                                 fmaf(h0[2], P[2], h[2]), fmaf(h0[3], P[3], h[3]));
        float4 hib = make_float4(fmaf(h0[4], P[4], h[4]), fmaf(h0[5], P[5], h[5]),
                                 fmaf(h0[6], P[6], h[6]), fmaf(h0[7], P[7], h[7]));
        *(float4*)(Hpg + (size_t)cidx * 8)     = hia;
        *(float4*)(Hpg + (size_t)cidx * 8 + 4) = hib;
        __threadfence();
        __syncthreads();
        if (t == 0) {
            asm volatile("st.global.release.gpu.b32 [%0], %1;" :: "l"(flags + fi), "r"(2) : "memory");
        }
    }

    // sweep 2: full recurrence from h0, emit y (u recomputed; xz L2-hot)
#pragma unroll
    for (int n = 0; n < DS; n++) h[n] = h0[n];
    xprev = (s0 > 0) ? xz[(size_t)(r0 - dir) * (2 * DI) + d] : 0.f;
    for (int tt = 0; tt < TCH; tt++) {
        float xcur = xz[(size_t)(r0 + dir * tt) * (2 * DI) + d];
        float u = silu(fmaf(cwd0, xprev, fmaf(cwd1, xcur, cbd)));
        xprev = xcur;

        float dl = delta_s[tt * 128 + t];
        float du = dl * u;
        const float* row = &dbc_s[tt * 49];
        float yv = 0.f;
        if (uni) {
            float e1 = __expf(dl * Av0);
            float an = 1.f;
#pragma unroll
            for (int n = 0; n < DS; n++) {
                an *= e1;
                h[n] = fmaf(an, h[n], du * row[32 + n]);
                yv = fmaf(h[n], row[40 + n], yv);
            }
        } else {
#pragma unroll
            for (int n = 0; n < DS; n++) {
                float a = __expf(dl * Av[n]);
                h[n] = fmaf(a, h[n], du * row[32 + n]);
                yv = fmaf(h[n], row[40 + n], yv);
            }
        }
        y[(size_t)(tok0 + tt) * DI + d] = fmaf(u, Dd, yv);
    }
}

// ---------------- combine branches, gate, RMSNorm -> bf16 hi/lo ---------------
__global__ void k_rms(const float* __restrict__ yf, const float* __restrict__ yb,
                      const float* __restrict__ xz, const float* __restrict__ rw,
                      __nv_bfloat16* __restrict__ oh, __nv_bfloat16* __restrict__ ol)
{
    int tok  = blockIdx.x * 8 + (threadIdx.x >> 5);
    int lane = threadIdx.x & 31;
    int s    = tok & (LSEQ - 1);
    int rtok = tok - s + (LSEQ - 1 - s);

    float4 v[4];
    float ss = 0.f;
#pragma unroll
    for (int i = 0; i < 4; i++) {
        int d = i * 128 + lane * 4;
        float4 a = *(const float4*)(yf + (size_t)tok * DI + d);
        float4 c = *(const float4*)(yb + (size_t)rtok * DI + d);
        float4 z = *(const float4*)(xz + (size_t)tok * (2 * DI) + DI + d);
        float4 o;
        o.x = 0.5f * (a.x + c.x) * silu(z.x);
        o.y = 0.5f * (a.y + c.y) * silu(z.y);
        o.z = 0.5f * (a.z + c.z) * silu(z.z);
        o.w = 0.5f * (a.w + c.w) * silu(z.w);
        ss += o.x*o.x + o.y*o.y + o.z*o.z + o.w*o.w;
        v[i] = o;
    }
#pragma unroll
    for (int o = 16; o; o >>= 1) ss += __shfl_xor_sync(0xffffffffu, ss, o);
    float sc = rsqrtf(ss * (1.f / DI) + 1e-5f);

#pragma unroll
    for (int i = 0; i < 4; i++) {
        int d = i * 128 + lane * 4;
        float4 w4 = *(const float4*)(rw + d);
        float o4[4];
        o4[0] = v[i].x * sc * w4.x;
        o4[1] = v[i].y * sc * w4.y;
        o4[2] = v[i].z * sc * w4.z;
        o4[3] = v[i].w * sc * w4.w;
        __nv_bfloat16 hh[4], ll[4];
#pragma unroll
        for (int q = 0; q < 4; q++) {
            hh[q] = __float2bfloat16(o4[q]);
            ll[q] = __float2bfloat16(o4[q] - __bfloat162float(hh[q]));
        }
        *(uint2*)(oh + (size_t)tok * DI + d) = *(uint2*)hh;
        *(uint2*)(ol + (size_t)tok * DI + d) = *(uint2*)ll;
    }
}

// ---------------- host launch ----------------
extern "C" void kernel_launch(void* const* d_in, const int* in_sizes, int n_in,
                              void* d_out, int out_size)
{
    const float* x          = (const float*)d_in[0];
    const float* ln_w       = (const float*)d_in[1];
    const float* ln_b       = (const float*)d_in[2];
    const float* in_proj_w  = (const float*)d_in[3];
    const float* conv_w     = (const float*)d_in[4];
    const float* conv_b     = (const float*)d_in[5];
    const float* x_proj_w   = (const float*)d_in[6];
    const float* dt_proj_w  = (const float*)d_in[7];
    const float* dt_proj_b  = (const float*)d_in[8];
    const float* A_log      = (const float*)d_in[9];
    const float* Dp         = (const float*)d_in[10];
    const float* conv_w_b   = (const float*)d_in[11];
    const float* conv_b_b   = (const float*)d_in[12];
    const float* x_proj_w_b = (const float*)d_in[13];
    const float* dt_proj_w_b= (const float*)d_in[14];
    const float* dt_proj_b_b= (const float*)d_in[15];
    const float* A_log_b    = (const float*)d_in[16];
    const float* D_b        = (const float*)d_in[17];
    const float* rms_w      = (const float*)d_in[18];
    const float* out_proj_w = (const float*)d_in[19];
    float* out = (float*)d_out;

    __nv_bfloat16 *lnh, *lnl, *wih, *wil, *woh, *wol, *ynh, *ynl;
    __nv_bfloat16 *xwh0, *xwl0, *xwh1, *xwl1;
    float *xz, *dbc0, *dbc1, *y0, *y1;
    float *P0, *Q0, *Hp0, *P1, *Q1, *Hp1;
    int* flags;
    cudaGetSymbolAddress((void**)&lnh,  g_lnh);
    cudaGetSymbolAddress((void**)&lnl,  g_lnl);
    cudaGetSymbolAddress((void**)&wih,  g_wih);
    cudaGetSymbolAddress((void**)&wil,  g_wil);
    cudaGetSymbolAddress((void**)&woh,  g_woh);
    cudaGetSymbolAddress((void**)&wol,  g_wol);
    cudaGetSymbolAddress((void**)&xwh0, g_xwh0);
    cudaGetSymbolAddress((void**)&xwl0, g_xwl0);
    cudaGetSymbolAddress((void**)&xwh1, g_xwh1);
    cudaGetSymbolAddress((void**)&xwl1, g_xwl1);
    cudaGetSymbolAddress((void**)&ynh,  g_ynh);
    cudaGetSymbolAddress((void**)&ynl,  g_ynl);
    cudaGetSymbolAddress((void**)&xz,   g_xz);
    cudaGetSymbolAddress((void**)&dbc0, g_dbc0);
    cudaGetSymbolAddress((void**)&dbc1, g_dbc1);
    cudaGetSymbolAddress((void**)&y0,   g_y0);
    cudaGetSymbolAddress((void**)&y1,   g_y1);
    cudaGetSymbolAddress((void**)&P0,   g_P0);
    cudaGetSymbolAddress((void**)&Q0,   g_Q0);
    cudaGetSymbolAddress((void**)&Hp0,  g_Hp0);
    cudaGetSymbolAddress((void**)&P1,   g_P1);
    cudaGetSymbolAddress((void**)&Q1,   g_Q1);
    cudaGetSymbolAddress((void**)&Hp1,  g_Hp1);
    cudaGetSymbolAddress((void**)&flags, g_flags);

    cudaFuncSetAttribute(k_mma<false>, cudaFuncAttributeMaxDynamicSharedMemorySize, M2_SMEM);
    cudaFuncSetAttribute(k_mma<true>,  cudaFuncAttributeMaxDynamicSharedMemorySize, M2_SMEM);
    cudaFuncSetAttribute(k_xproj, cudaFuncAttributeMaxDynamicSharedMemorySize, XP_SMEM);
    cudaFuncSetAttribute(k_scan, cudaFuncAttributeMaxDynamicSharedMemorySize, SCAN_SMEM);

    // 0. convert weights to bf16 hi/lo (single launch)
    int ncvt = 2*DI*DM + DM*DI + DBCW*DI + DBCW*DI;
    k_cvt4<<<(ncvt + 255)/256, 256>>>(
        in_proj_w, wih, wil, 2*DI*DM,
        out_proj_w, woh, wol, DM*DI,
        x_proj_w,  xwh0, xwl0, DBCW*DI,
        x_proj_w_b, xwh1, xwl1, DBCW*DI);

    // 1. LayerNorm -> bf16 hi/lo
    k_layernorm<<<NTOK / 8, 256>>>(x, ln_w, ln_b, lnh, lnl);

    // 2. in_proj (mma.sync split-bf16, 128x64 tile, 2 CTAs/SM): -> xz fp32
    k_mma<false><<<dim3(2*DI/64, NTOK/128), 256, M2_SMEM>>>(lnh, lnl, wih, wil, xz, 2*DI, nullptr);

    // 3. x_proj: fused conv+silu + tensor-core split-bf16, reg-pipelined A
    k_xproj<<<dim3(NTOK/128, 2), 256, XP_SMEM>>>(
        xz, conv_w, conv_b, conv_w_b, conv_b_b,
        xwh0, xwl0, xwh1, xwl1, dbc0, dbc1);

    // 4. fused conv + dt_proj + selective scan (decoupled lookback w/ prefix)
    k_zero<<<2, 1024>>>(flags);
    k_scan<<<dim3(DI/128, BATCH, NCH*2), 128, SCAN_SMEM>>>(
        xz, dbc0, dbc1, conv_w, conv_b, conv_w_b, conv_b_b,
        A_log, A_log_b, dt_proj_w, dt_proj_w_b, dt_proj_b, dt_proj_b_b,
        Dp, D_b, y0, y1, P0, Q0, Hp0, P1, Q1, Hp1, flags);

    // 5. combine + silu(z) gate + RMSNorm -> bf16 hi/lo
    k_rms<<<NTOK / 8, 256>>>(y0, y1, xz, rms_w, ynh, ynl);

    // 6. out_proj (mma.sync split-bf16, 128x64 tile) + residual -> d_out
    k_mma<true><<<dim3(DM/64, NTOK/128), 256, M2_SMEM>>>(ynh, ynl, woh, wol, out, DM, x);
}

// round 15
// speedup vs baseline: 1.2373x; 1.0408x over previous
#include <cuda_runtime.h>
#include <cuda_bf16.h>
#include <cstdint>

// ---------------- problem constants ----------------
#define BATCH   4
#define LSEQ    4096
#define NTOK    (BATCH*LSEQ)       // 16384
#define DM      512
#define DI      512
#define DS      8
#define DTRANK  32
#define DBCW    48                 // DT_RANK + 2*D_STATE

// chunked scan config
#define NCH     64
#define TCH     (LSEQ/NCH)         // 64
#define NCHAN   (BATCH*DI)         // 2048
#define CHTOT   (NCHAN*NCH)        // 131072

// ---------------- scratch (device globals; no runtime alloc) ----------------
__device__ __nv_bfloat16 g_lnh[NTOK*DM];
__device__ __nv_bfloat16 g_lnl[NTOK*DM];
__device__ __nv_bfloat16 g_wih[2*DI*DM];
__device__ __nv_bfloat16 g_wil[2*DI*DM];
__device__ __nv_bfloat16 g_woh[DM*DI];
__device__ __nv_bfloat16 g_wol[DM*DI];
__device__ __nv_bfloat16 g_xwh0[DBCW*DI];
__device__ __nv_bfloat16 g_xwl0[DBCW*DI];
__device__ __nv_bfloat16 g_xwh1[DBCW*DI];
__device__ __nv_bfloat16 g_xwl1[DBCW*DI];
__device__ __nv_bfloat16 g_uh0[NTOK*DI];
__device__ __nv_bfloat16 g_ul0[NTOK*DI];
__device__ __nv_bfloat16 g_uh1[NTOK*DI];
__device__ __nv_bfloat16 g_ul1[NTOK*DI];
__device__ __nv_bfloat16 g_ynh[NTOK*DI];
__device__ __nv_bfloat16 g_ynl[NTOK*DI];
__device__ float g_xz  [NTOK*2*DI];
__device__ float g_dbc0[NTOK*DBCW];
__device__ float g_dbc1[NTOK*DBCW];
__device__ float g_y0  [NTOK*DI];
__device__ float g_y1  [NTOK*DI];
__device__ float g_P0  [DS*CHTOT];
__device__ float g_Q0  [DS*CHTOT];
__device__ float g_Hp0 [DS*CHTOT];
__device__ float g_P1  [DS*CHTOT];
__device__ float g_Q1  [DS*CHTOT];
__device__ float g_Hp1 [DS*CHTOT];
__device__ int   g_flags[2048];

// ---------------- helpers ----------------
__device__ __forceinline__ uint32_t smem_u32(const void* p) {
    uint32_t a;
    asm("{ .reg .u64 t; cvta.to.shared.u64 t, %1; cvt.u32.u64 %0, t; }" : "=r"(a) : "l"(p));
    return a;
}
__device__ __forceinline__ void ldsm4(uint32_t* r, uint32_t addr) {
    asm volatile("ldmatrix.sync.aligned.m8n8.x4.shared.b16 {%0,%1,%2,%3}, [%4];"
        : "=r"(r[0]), "=r"(r[1]), "=r"(r[2]), "=r"(r[3]) : "r"(addr));
}
__device__ __forceinline__ void mma16816(float* c, const uint32_t* a, const uint32_t* b) {
    asm volatile("mma.sync.aligned.m16n8k16.row.col.f32.bf16.bf16.f32 "
        "{%0,%1,%2,%3},{%4,%5,%6,%7},{%8,%9},{%0,%1,%2,%3};"
        : "+f"(c[0]), "+f"(c[1]), "+f"(c[2]), "+f"(c[3])
        : "r"(a[0]), "r"(a[1]), "r"(a[2]), "r"(a[3]), "r"(b[0]), "r"(b[1]));
}
__device__ __forceinline__ float silu(float v) { return v / (1.f + __expf(-v)); }

// ---------------- mma.sync split-bf16 GEMM, 128x64 tile, 2 CTAs/SM ----------
#define KCH     64
#define NKCH    (512/KCH)          // 8
#define M2_A    16384              // 128x64 bf16
#define M2_B    8192               // 64x64 bf16
#define M2_STG  (2*M2_A + 2*M2_B)  // 49152
#define M2_SMEM (2*M2_STG)         // 98304

__device__ __forceinline__ void m2_load(
    const __nv_bfloat16* __restrict__ Ah, const __nv_bfloat16* __restrict__ Al,
    const __nv_bfloat16* __restrict__ Bh, const __nv_bfloat16* __restrict__ Bl,
    int m0, int n0, int kc, uint32_t stage)
{
    const int t = threadIdx.x;
#pragma unroll
    for (int it = 0; it < 12; it++) {
        int idx = it * 256 + t;            // 0..3071 16B-chunks
        const __nv_bfloat16* gb;
        uint32_t toff;
        int local, base;
        if (idx < 2048) {                  // A hi/lo: 128 rows x 8 c16 each
            int which = idx >> 10;
            local = idx & 1023;
            gb = which ? Al : Ah;
            toff = which ? M2_A : 0u;
            base = m0;
        } else {                           // B hi/lo: 64 rows x 8 c16 each
            int idx2 = idx - 2048;
            int which = idx2 >> 9;
            local = idx2 & 511;
            gb = which ? Bl : Bh;
            toff = 2 * M2_A + (which ? M2_B : 0);
            base = n0;
        }
        int row = local >> 3;
        int c   = local & 7;
        const void* ga = gb + (size_t)(base + row) * 512 + kc * KCH + c * 8;
        uint32_t sa = stage + toff + row * 128 + ((c ^ (row & 7)) << 4);
        asm volatile("cp.async.cg.shared.global [%0], [%1], 16;" :: "r"(sa), "l"(ga));
    }
}

template<bool RESID>
__global__ __launch_bounds__(256, 2)
void k_mma(const __nv_bfloat16* __restrict__ Ah, const __nv_bfloat16* __restrict__ Al,
           const __nv_bfloat16* __restrict__ Bh, const __nv_bfloat16* __restrict__ Bl,
           float* __restrict__ C, int N, const float* __restrict__ resid)
{
    extern __shared__ __align__(128) char smem[];
    const uint32_t sb = smem_u32(smem);
    const int m0 = blockIdx.y * 128;
    const int n0 = blockIdx.x * 64;
    const int w  = threadIdx.x >> 5;
    const int lane = threadIdx.x & 31;
    const int wm = (w >> 1) * 32;      // 4x2 warp grid, warp tile 32x32
    const int wn = (w & 1) * 32;

    float acc[2][4][4];
#pragma unroll
    for (int i = 0; i < 2; i++)
#pragma unroll
        for (int j = 0; j < 4; j++)
#pragma unroll
            for (int q = 0; q < 4; q++) acc[i][j][q] = 0.f;

    const int ar  = lane & 15;
    const int ach = lane >> 4;
    const int bt8 = lane & 7;
    const int bn8 = (lane >> 4) << 3;
    const int bch = (lane >> 3) & 1;

    m2_load(Ah, Al, Bh, Bl, m0, n0, 0, sb);
    asm volatile("cp.async.commit_group;");
    m2_load(Ah, Al, Bh, Bl, m0, n0, 1, sb + M2_STG);
    asm volatile("cp.async.commit_group;");

    for (int i = 0; i < NKCH; i++) {
        if (i < NKCH - 1) asm volatile("cp.async.wait_group 1;");
        else              asm volatile("cp.async.wait_group 0;");
        __syncthreads();

        const uint32_t stg = sb + (i & 1) * M2_STG;
        const uint32_t sAh = stg, sAl = stg + M2_A;
        const uint32_t sBh = stg + 2 * M2_A, sBl = stg + 2 * M2_A + M2_B;

#pragma unroll
        for (int ks = 0; ks < 4; ks++) {
            uint32_t ah[2][4], al[2][4], bh[2][4], bl[2][4];
#pragma unroll
            for (int mi = 0; mi < 2; mi++) {
                int r = wm + mi * 16 + ar;
                int c = ks * 2 + ach;
                uint32_t off = r * 128 + (((uint32_t)(c ^ (r & 7))) << 4);
                ldsm4(ah[mi], sAh + off);
                ldsm4(al[mi], sAl + off);
            }
#pragma unroll
            for (int ni = 0; ni < 2; ni++) {
                int n = wn + ni * 16 + bn8 + bt8;
                int c = ks * 2 + bch;
                uint32_t off = n * 128 + (((uint32_t)(c ^ (n & 7))) << 4);
                ldsm4(bh[ni], sBh + off);
                ldsm4(bl[ni], sBl + off);
            }
#pragma unroll
            for (int mi = 0; mi < 2; mi++)
#pragma unroll
                for (int nj = 0; nj < 4; nj++) {
                    const uint32_t* bhp = &bh[nj >> 1][(nj & 1) * 2];
                    const uint32_t* blp = &bl[nj >> 1][(nj & 1) * 2];
                    mma16816(acc[mi][nj], ah[mi], bhp);
                    mma16816(acc[mi][nj], ah[mi], blp);
                    mma16816(acc[mi][nj], al[mi], bhp);
                }
        }

        if (i < NKCH - 2) {
            __syncthreads();
            m2_load(Ah, Al, Bh, Bl, m0, n0, i + 2, stg);
            asm volatile("cp.async.commit_group;");
        }
    }

#pragma unroll
    for (int mi = 0; mi < 2; mi++) {
        int m = m0 + wm + mi * 16 + (lane >> 2);
#pragma unroll
        for (int nj = 0; nj < 4; nj++) {
            int n = n0 + wn + nj * 8 + ((lane & 3) << 1);
            float2 v0 = make_float2(acc[mi][nj][0], acc[mi][nj][1]);
            float2 v1 = make_float2(acc[mi][nj][2], acc[mi][nj][3]);
            if (RESID) {
                float2 r0 = *(const float2*)(resid + (size_t)m * N + n);
                float2 r1 = *(const float2*)(resid + (size_t)(m + 8) * N + n);
                v0.x += r0.x; v0.y += r0.y; v1.x += r1.x; v1.y += r1.y;
            }
            *(float2*)(C + (size_t)m * N + n)       = v0;
            *(float2*)(C + (size_t)(m + 8) * N + n) = v1;
        }
    }
}

// ---------------- conv + silu -> u (bf16 hi/lo, scan-token order) -----------
__global__ void k_conv(const float* __restrict__ xz,
                       const float* __restrict__ cw0, const float* __restrict__ cb0,
                       const float* __restrict__ cw1, const float* __restrict__ cb1,
                       __nv_bfloat16* __restrict__ uh0, __nv_bfloat16* __restrict__ ul0,
                       __nv_bfloat16* __restrict__ uh1, __nv_bfloat16* __restrict__ ul1)
{
    int flat = blockIdx.x * 256 + threadIdx.x;   // NTOK*128 threads
    int dq = flat & 127;
    int tok = flat >> 7;
    int d = dq * 4;
    int s = tok & (LSEQ - 1);
    int b = tok >> 12;
    bool pv = s > 0;

    // forward branch: gmem row = tok
    {
        float4 cwa  = *(const float4*)(cw0 + d * 2);
        float4 cwb2 = *(const float4*)(cw0 + d * 2 + 4);
        float4 cbv  = *(const float4*)(cb0 + d);
        float4 xc = *(const float4*)(xz + (size_t)tok * (2 * DI) + d);
        float4 xp = pv ? *(const float4*)(xz + (size_t)(tok - 1) * (2 * DI) + d)
                       : make_float4(0.f, 0.f, 0.f, 0.f);
        float u0 = silu(fmaf(cwa.x,  xp.x, fmaf(cwa.y,  xc.x, cbv.x)));
        float u1 = silu(fmaf(cwa.z,  xp.y, fmaf(cwa.w,  xc.y, cbv.y)));
        float u2 = silu(fmaf(cwb2.x, xp.z, fmaf(cwb2.y, xc.z, cbv.z)));
        float u3 = silu(fmaf(cwb2.z, xp.w, fmaf(cwb2.w, xc.w, cbv.w)));
        __nv_bfloat16 h0 = __float2bfloat16(u0), h1 = __float2bfloat16(u1);
        __nv_bfloat16 h2 = __float2bfloat16(u2), h3 = __float2bfloat16(u3);
        __nv_bfloat16 l0 = __float2bfloat16(u0 - __bfloat162float(h0));
        __nv_bfloat16 l1 = __float2bfloat16(u1 - __bfloat162float(h1));
        __nv_bfloat16 l2 = __float2bfloat16(u2 - __bfloat162float(h2));
        __nv_bfloat16 l3 = __float2bfloat16(u3 - __bfloat162float(h3));
        uint2 hv, lv;
        __nv_bfloat162 p;
        p = __nv_bfloat162(h0, h1); hv.x = *(uint32_t*)&p;
        p = __nv_bfloat162(h2, h3); hv.y = *(uint32_t*)&p;
        p = __nv_bfloat162(l0, l1); lv.x = *(uint32_t*)&p;
        p = __nv_bfloat162(l2, l3); lv.y = *(uint32_t*)&p;
        *(uint2*)(uh0 + (size_t)tok * DI + d) = hv;
        *(uint2*)(ul0 + (size_t)tok * DI + d) = lv;
    }
    // backward branch: scan token tok <-> gmem row b*L + (L-1-s), prev = row+1
    {
        int g = b * LSEQ + (LSEQ - 1 - s);
        float4 cwa  = *(const float4*)(cw1 + d * 2);
        float4 cwb2 = *(const float4*)(cw1 + d * 2 + 4);
        float4 cbv  = *(const float4*)(cb1 + d);
        float4 xc = *(const float4*)(xz + (size_t)g * (2 * DI) + d);
        float4 xp = pv ? *(const float4*)(xz + (size_t)(g + 1) * (2 * DI) + d)
                       : make_float4(0.f, 0.f, 0.f, 0.f);
        float u0 = silu(fmaf(cwa.x,  xp.x, fmaf(cwa.y,  xc.x, cbv.x)));
        float u1 = silu(fmaf(cwa.z,  xp.y, fmaf(cwa.w,  xc.y, cbv.y)));
        float u2 = silu(fmaf(cwb2.x, xp.z, fmaf(cwb2.y, xc.z, cbv.z)));
        float u3 = silu(fmaf(cwb2.z, xp.w, fmaf(cwb2.w, xc.w, cbv.w)));
        __nv_bfloat16 h0 = __float2bfloat16(u0), h1 = __float2bfloat16(u1);
        __nv_bfloat16 h2 = __float2bfloat16(u2), h3 = __float2bfloat16(u3);
        __nv_bfloat16 l0 = __float2bfloat16(u0 - __bfloat162float(h0));
        __nv_bfloat16 l1 = __float2bfloat16(u1 - __bfloat162float(h1));
        __nv_bfloat16 l2 = __float2bfloat16(u2 - __bfloat162float(h2));
        __nv_bfloat16 l3 = __float2bfloat16(u3 - __bfloat162float(h3));
        uint2 hv, lv;
        __nv_bfloat162 p;
        p = __nv_bfloat162(h0, h1); hv.x = *(uint32_t*)&p;
        p = __nv_bfloat162(h2, h3); hv.y = *(uint32_t*)&p;
        p = __nv_bfloat162(l0, l1); lv.x = *(uint32_t*)&p;
        p = __nv_bfloat162(l2, l3); lv.y = *(uint32_t*)&p;
        *(uint2*)(uh1 + (size_t)tok * DI + d) = hv;
        *(uint2*)(ul1 + (size_t)tok * DI + d) = lv;
    }
}

// ---------------- x_proj: u (precomputed) x W, split-bf16 mma ---------------
#define XP_A    16384              // 128x64 bf16
#define XP_B    8192               // 64x64 bf16
#define XP_STG  (2*XP_A + 2*XP_B)  // 49152
#define XP_SMEM (2*XP_STG)         // 98304

__device__ __forceinline__ void xp_load(
    const __nv_bfloat16* __restrict__ Uh, const __nv_bfloat16* __restrict__ Ul,
    const __nv_bfloat16* __restrict__ Wh, const __nv_bfloat16* __restrict__ Wl,
    int m0, int kc, uint32_t stage)
{
    const int t = threadIdx.x;
#pragma unroll
    for (int it = 0; it < 11; it++) {      // 11*256 = 2816 chunks exactly
        int idx = it * 256 + t;
        const __nv_bfloat16* gb;
        uint32_t toff;
        int row, c;
        if (idx < 2048) {                  // A hi/lo from u arrays
            int which = idx >> 10;
            int local = idx & 1023;
            gb = which ? Ul : Uh;
            toff = which ? XP_A : 0u;
            row = local >> 3;
            c   = local & 7;
            gb += (size_t)(m0 + row) * 512 + kc * KCH + c * 8;
        } else {                           // B hi/lo (48 rows each)
            int idx2 = idx - 2048;
            int which = idx2 >= 384;
            int local = idx2 - which * 384;
            row = local >> 3;
            c   = local & 7;
            gb = (which ? Wl : Wh) + (size_t)row * 512 + kc * KCH + c * 8;
            toff = 2 * XP_A + (which ? XP_B : 0);
        }
        uint32_t sa = stage + toff + row * 128 + ((c ^ (row & 7)) << 4);
        asm volatile("cp.async.cg.shared.global [%0], [%1], 16;" :: "r"(sa), "l"(gb));
    }
}

__global__ __launch_bounds__(256, 2)
void k_xproj(const __nv_bfloat16* __restrict__ uh0, const __nv_bfloat16* __restrict__ ul0,
             const __nv_bfloat16* __restrict__ uh1, const __nv_bfloat16* __restrict__ ul1,
             const __nv_bfloat16* __restrict__ xwh0, const __nv_bfloat16* __restrict__ xwl0,
             const __nv_bfloat16* __restrict__ xwh1, const __nv_bfloat16* __restrict__ xwl1,
             float* __restrict__ C0, float* __restrict__ C1)
{
    extern __shared__ __align__(128) char smem[];
    const uint32_t sb = smem_u32(smem);
    const int br = blockIdx.y;
    const int m0 = blockIdx.x * 128;
    const int t  = threadIdx.x;
    const int w  = t >> 5;
    const int lane = t & 31;

    const __nv_bfloat16* Uh = br ? uh1 : uh0;
    const __nv_bfloat16* Ul = br ? ul1 : ul0;
    const __nv_bfloat16* Wh = br ? xwh1 : xwh0;
    const __nv_bfloat16* Wl = br ? xwl1 : xwl0;
    float* C = br ? C1 : C0;

    // zero B pad rows (48..63) of both stages/tiles once
    for (int i = t; i < 2048; i += 256) {
        int region = i >> 9;               // 0..3: stage0(hi),(lo),stage1(hi),(lo)
        uint32_t off = (region >> 1) * XP_STG + 2 * XP_A + (region & 1) * XP_B
                     + 6144 + (i & 511) * 4;
        *(uint32_t*)(smem + off) = 0u;
    }
    __syncthreads();

    const int wm = (w >> 1) * 32;
    const int wn = (w & 1) * 32;
    const int ar  = lane & 15;
    const int ach = lane >> 4;
    const int bt8 = lane & 7;
    const int bn8 = (lane >> 4) << 3;
    const int bch = (lane >> 3) & 1;

    float acc[2][4][4];
#pragma unroll
    for (int i = 0; i < 2; i++)
#pragma unroll
        for (int j = 0; j < 4; j++)
#pragma unroll
            for (int q = 0; q < 4; q++) acc[i][j][q] = 0.f;

    xp_load(Uh, Ul, Wh, Wl, m0, 0, sb);
    asm volatile("cp.async.commit_group;");
    xp_load(Uh, Ul, Wh, Wl, m0, 1, sb + XP_STG);
    asm volatile("cp.async.commit_group;");

    for (int i = 0; i < NKCH; i++) {
        if (i < NKCH - 1) asm volatile("cp.async.wait_group 1;");
        else              asm volatile("cp.async.wait_group 0;");
        __syncthreads();

        const uint32_t stg = sb + (i & 1) * XP_STG;
        const uint32_t sAh = stg, sAl = stg + XP_A;
        const uint32_t sBh = stg + 2 * XP_A, sBl = stg + 2 * XP_A + XP_B;
#pragma unroll
        for (int ks = 0; ks < 4; ks++) {
            uint32_t ah[2][4], al[2][4], bh[2][4], bl[2][4];
#pragma unroll
            for (int mi = 0; mi < 2; mi++) {
                int r = wm + mi * 16 + ar;
                int c = ks * 2 + ach;
                uint32_t off = r * 128 + (((uint32_t)(c ^ (r & 7))) << 4);
                ldsm4(ah[mi], sAh + off);
                ldsm4(al[mi], sAl + off);
            }
#pragma unroll
            for (int ni = 0; ni < 2; ni++) {
                int n = wn + ni * 16 + bn8 + bt8;
                int c = ks * 2 + bch;
                uint32_t off = n * 128 + (((uint32_t)(c ^ (n & 7))) << 4);
                ldsm4(bh[ni], sBh + off);
                ldsm4(bl[ni], sBl + off);
            }
#pragma unroll
            for (int mi = 0; mi < 2; mi++)
#pragma unroll
                for (int nj = 0; nj < 4; nj++) {
                    const uint32_t* bhp = &bh[nj >> 1][(nj & 1) * 2];
                    const uint32_t* blp = &bl[nj >> 1][(nj & 1) * 2];
                    mma16816(acc[mi][nj], ah[mi], bhp);
                    mma16816(acc[mi][nj], ah[mi], blp);
                    mma16816(acc[mi][nj], al[mi], bhp);
                }
        }

        if (i < NKCH - 2) {
            __syncthreads();
            xp_load(Uh, Ul, Wh, Wl, m0, i + 2, stg);
            asm volatile("cp.async.commit_group;");
        }
    }

    // epilogue: C is [NTOK][48]
#pragma unroll
    for (int mi = 0; mi < 2; mi++) {
        int m = m0 + wm + mi * 16 + (lane >> 2);
#pragma unroll
        for (int nj = 0; nj < 4; nj++) {
            int n = wn + nj * 8 + ((lane & 3) << 1);
            if (n < DBCW) {
                *(float2*)(C + (size_t)m * DBCW + n) =
                    make_float2(acc[mi][nj][0], acc[mi][nj][1]);
                *(float2*)(C + (size_t)(m + 8) * DBCW + n) =
                    make_float2(acc[mi][nj][2], acc[mi][nj][3]);
            }
        }
    }
}

// ---------------- fp32 -> bf16 hi/lo weight convert (4 weights, 1 launch) ----
__global__ void k_cvt4(const float* __restrict__ w1, __nv_bfloat16* __restrict__ h1,
                       __nv_bfloat16* __restrict__ l1, int n1,
                       const float* __restrict__ w2, __nv_bfloat16* __restrict__ h2,
                       __nv_bfloat16* __restrict__ l2, int n2,
                       const float* __restrict__ w3, __nv_bfloat16* __restrict__ h3,
                       __nv_bfloat16* __restrict__ l3, int n3,
                       const float* __restrict__ w4, __nv_bfloat16* __restrict__ h4,
                       __nv_bfloat16* __restrict__ l4, int n4)
{
    int i = blockIdx.x * blockDim.x + threadIdx.x;
    const float* w; __nv_bfloat16 *hh, *ll; int j;
    if (i < n1)                     { w = w1; hh = h1; ll = l1; j = i; }
    else if (i < n1+n2)             { w = w2; hh = h2; ll = l2; j = i-n1; }
    else if (i < n1+n2+n3)          { w = w3; hh = h3; ll = l3; j = i-n1-n2; }
    else if (i < n1+n2+n3+n4)       { w = w4; hh = h4; ll = l4; j = i-n1-n2-n3; }
    else return;
    float v = w[j];
    __nv_bfloat16 h = __float2bfloat16(v);
    hh[j] = h;
    ll[j] = __float2bfloat16(v - __bfloat162float(h));
}

// ---------------- LayerNorm -> bf16 hi/lo ----------------
__global__ void k_layernorm(const float* __restrict__ x,
                            const float* __restrict__ w,
                            const float* __restrict__ b,
                            __nv_bfloat16* __restrict__ oh,
                            __nv_bfloat16* __restrict__ ol)
{
    int tok  = blockIdx.x * 8 + (threadIdx.x >> 5);
    int lane = threadIdx.x & 31;
    const float* row = x + (size_t)tok * DM;

    float4 v[4];
    float s = 0.f, s2 = 0.f;
#pragma unroll
    for (int i = 0; i < 4; i++) {
        v[i] = *(const float4*)(row + i * 128 + lane * 4);
        s  += v[i].x + v[i].y + v[i].z + v[i].w;
        s2 += v[i].x*v[i].x + v[i].y*v[i].y + v[i].z*v[i].z + v[i].w*v[i].w;
    }
#pragma unroll
    for (int o = 16; o; o >>= 1) {
        s  += __shfl_xor_sync(0xffffffffu, s,  o);
        s2 += __shfl_xor_sync(0xffffffffu, s2, o);
    }
    float mu   = s * (1.f / DM);
    float var  = s2 * (1.f / DM) - mu * mu;
    float rinv = rsqrtf(var + 1e-5f);

#pragma unroll
    for (int i = 0; i < 4; i++) {
        int d = i * 128 + lane * 4;
        float4 w4 = *(const float4*)(w + d);
        float4 b4 = *(const float4*)(b + d);
        float o4[4];
        o4[0] = (v[i].x - mu) * rinv * w4.x + b4.x;
        o4[1] = (v[i].y - mu) * rinv * w4.y + b4.y;
        o4[2] = (v[i].z - mu) * rinv * w4.z + b4.z;
        o4[3] = (v[i].w - mu) * rinv * w4.w + b4.w;
        __nv_bfloat16 hh[4], ll[4];
#pragma unroll
        for (int q = 0; q < 4; q++) {
            hh[q] = __float2bfloat16(o4[q]);
            ll[q] = __float2bfloat16(o4[q] - __bfloat162float(hh[q]));
        }
        *(uint2*)(oh + (size_t)tok * DM + d) = *(uint2*)hh;
        *(uint2*)(ol + (size_t)tok * DM + d) = *(uint2*)ll;
    }
}

// ---------------- zero lookback flags ----------------
__global__ void k_zero(int* __restrict__ flags) {
    flags[blockIdx.x * 1024 + threadIdx.x] = 0;
}

// ---------------- fused dt_proj + softplus + lookback scan -------------------
// u precomputed (bf16 hi/lo); decoupled lookback with inclusive prefix.
#define SCAN_SMEM (TCH*128*4 + TCH*49*4)   // 32768 + 12544 = 45312

__global__ __launch_bounds__(128)
void k_scan(const __nv_bfloat16* __restrict__ uh0, const __nv_bfloat16* __restrict__ ul0,
            const __nv_bfloat16* __restrict__ uh1, const __nv_bfloat16* __restrict__ ul1,
            const float* __restrict__ dbc0, const float* __restrict__ dbc1,
            const float* __restrict__ Alog0, const float* __restrict__ Alog1,
            const float* __restrict__ dtw0, const float* __restrict__ dtw1,
            const float* __restrict__ dtb0, const float* __restrict__ dtb1,
            const float* __restrict__ Dp0,  const float* __restrict__ Dp1,
            float* __restrict__ y0g, float* __restrict__ y1g,
            float* __restrict__ P0g, float* __restrict__ Q0g, float* __restrict__ Hp0g,
            float* __restrict__ P1g, float* __restrict__ Q1g, float* __restrict__ Hp1g,
            int* __restrict__ flags)
{
    extern __shared__ float sm[];
    float* delta_s = sm;                 // [TCH][128]
    float* dbc_s   = sm + TCH * 128;     // [TCH][49]

    const int t  = threadIdx.x;
    const int dg = blockIdx.x;
    const int b  = blockIdx.y;
    const int br = blockIdx.z & 1;
    const int chunk = blockIdx.z >> 1;
    const int d  = dg * 128 + t;

    const __nv_bfloat16* uhp = br ? uh1 : uh0;
    const __nv_bfloat16* ulp = br ? ul1 : ul0;
    const float* dbc = br ? dbc1 : dbc0;
    const float* Alg = br ? Alog1 : Alog0;
    const float* Wdt = br ? dtw1 : dtw0;
    const float* Bdt = br ? dtb1 : dtb0;
    const float* Dpp = br ? Dp1  : Dp0;
    float* y  = br ? y1g : y0g;
    float* Pg = br ? P1g : P0g;
    float* Qg = br ? Q1g : Q0g;
    float* Hpg = br ? Hp1g : Hp0g;

    for (int i = t; i < 128 * 32; i += 128) {
        int rw_ = i >> 5, k = i & 31;
        sm[rw_ * 33 + k] = Wdt[(size_t)(dg * 128) * 32 + i];
    }
    const int tok0 = b * LSEQ + chunk * TCH;
    for (int i = t; i < TCH * 48; i += 128)
        dbc_s[(i / 48) * 49 + (i % 48)] = dbc[(size_t)tok0 * 48 + i];
    __syncthreads();
    float w[32];
#pragma unroll
    for (int k = 0; k < 32; k++) w[k] = sm[t * 33 + k];
    __syncthreads();

    float Av[DS];
    {
        float4 a0 = *(const float4*)(Alg + d * DS);
        float4 a1 = *(const float4*)(Alg + d * DS + 4);
        Av[0] = -__expf(a0.x); Av[1] = -__expf(a0.y); Av[2] = -__expf(a0.z); Av[3] = -__expf(a0.w);
        Av[4] = -__expf(a1.x); Av[5] = -__expf(a1.y); Av[6] = -__expf(a1.z); Av[7] = -__expf(a1.w);
    }
    const float Av0 = Av[0];
    bool uni = true;
#pragma unroll
    for (int n = 1; n < DS; n++)
        uni = uni && (fabsf(Av[n] - (n + 1) * Av0) <= 2e-5f * (n + 1));

    const float bias = Bdt[d];
    const float Dd   = Dpp[d];

    float h[DS], P[DS], S = 0.f;
#pragma unroll
    for (int n = 0; n < DS; n++) { h[n] = 0.f; P[n] = 1.f; }

    for (int tt = 0; tt < TCH; tt++) {
        const size_t ui = (size_t)(tok0 + tt) * DI + d;
        float u = __bfloat162float(uhp[ui]) + __bfloat162float(ulp[ui]);

        const float* row = &dbc_s[tt * 49];
        float a0 = bias, a1 = 0.f, a2 = 0.f, a3 = 0.f;
#pragma unroll
        for (int k = 0; k < 32; k += 4) {
            a0 = fmaf(row[k + 0], w[k + 0], a0);
            a1 = fmaf(row[k + 1], w[k + 1], a1);
            a2 = fmaf(row[k + 2], w[k + 2], a2);
            a3 = fmaf(row[k + 3], w[k + 3], a3);
        }
        float v = (a0 + a1) + (a2 + a3);
        float dl = (v > 20.f) ? v : log1pf(__expf(v));
        delta_s[tt * 128 + t] = dl;
        float du = dl * u;
        if (uni) {
            S += dl;
            float e1 = __expf(dl * Av0);
            float an = 1.f;
#pragma unroll
            for (int n = 0; n < DS; n++) {
                an *= e1;
                h[n] = fmaf(an, h[n], du * row[32 + n]);
            }
        } else {
#pragma unroll
            for (int n = 0; n < DS; n++) {
                float a = __expf(dl * Av[n]);
                P[n] *= a;
                h[n] = fmaf(a, h[n], du * row[32 + n]);
            }
        }
    }
    if (uni) {
#pragma unroll
        for (int n = 0; n < DS; n++) P[n] = __expf(S * Av[n]);
    }

    // publish aggregate (P, Q), flag = 1
    const int cidx = chunk * NCHAN + b * DI + d;
    {
        *(float4*)(Pg + (size_t)cidx * 8)     = make_float4(P[0], P[1], P[2], P[3]);
        *(float4*)(Pg + (size_t)cidx * 8 + 4) = make_float4(P[4], P[5], P[6], P[7]);
        *(float4*)(Qg + (size_t)cidx * 8)     = make_float4(h[0], h[1], h[2], h[3]);
        *(float4*)(Qg + (size_t)cidx * 8 + 4) = make_float4(h[4], h[5], h[6], h[7]);
    }
    __threadfence();
    __syncthreads();
    const int fi = blockIdx.z * 16 + b * 4 + dg;
    if (t == 0 && chunk > 0) {
        asm volatile("st.global.release.gpu.b32 [%0], %1;" :: "l"(flags + fi), "r"(1) : "memory");
    }

    // decoupled lookback: stop at first predecessor with inclusive prefix
    float h0[DS], pref[DS];
#pragma unroll
    for (int n = 0; n < DS; n++) { h0[n] = 0.f; pref[n] = 1.f; }
    for (int j = chunk - 1; j >= 0; j--) {
        const int fj = (j * 2 + br) * 16 + b * 4 + dg;
        int f;
        do {
            asm volatile("ld.global.acquire.gpu.b32 %0, [%1];" : "=r"(f) : "l"(flags + fj) : "memory");
            if (!f) __nanosleep(64);
        } while (!f);
        const size_t idxj = (size_t)(j * NCHAN + b * DI + d) * 8;
        if (f == 2) {
            float4 ha = *(const float4*)(Hpg + idxj);
            float4 hb = *(const float4*)(Hpg + idxj + 4);
            float hv[DS] = { ha.x, ha.y, ha.z, ha.w, hb.x, hb.y, hb.z, hb.w };
#pragma unroll
            for (int n = 0; n < DS; n++)
                h0[n] = fmaf(pref[n], hv[n], h0[n]);
            break;
        }
        float4 qa = *(const float4*)(Qg + idxj);
        float4 qb = *(const float4*)(Qg + idxj + 4);
        float4 pa = *(const float4*)(Pg + idxj);
        float4 pb = *(const float4*)(Pg + idxj + 4);
        float qv[DS] = { qa.x, qa.y, qa.z, qa.w, qb.x, qb.y, qb.z, qb.w };
        float pv2[DS] = { pa.x, pa.y, pa.z, pa.w, pb.x, pb.y, pb.z, pb.w };
#pragma unroll
        for (int n = 0; n < DS; n++) {
            h0[n] = fmaf(pref[n], qv[n], h0[n]);
            pref[n] *= pv2[n];
        }
    }

    // publish inclusive prefix Hinc = h0*P + Q, flag = 2 (last chunk skips)
    if (chunk < NCH - 1) {
        float4 hia = make_float4(fmaf(h0[0], P[0], h[0]), fmaf(h0[1], P[1], h[1]),
                                 fmaf(h0[2], P[2], h[2]), fmaf(h0[3], P[3], h[3]));
        float4 hib = make_float4(fmaf(h0[4], P[4], h[4]), fmaf(h0[5], P[5], h[5]),
                                 fmaf(h0[6], P[6], h[6]), fmaf(h0[7], P[7], h[7]));
        *(float4*)(Hpg + (size_t)cidx * 8)     = hia;
        *(float4*)(Hpg + (size_t)cidx * 8 + 4) = hib;
        __threadfence();
        __syncthreads();
        if (t == 0) {
            asm volatile("st.global.release.gpu.b32 [%0], %1;" :: "l"(flags + fi), "r"(2) : "memory");
        }
    }

    // sweep 2: full recurrence from h0, emit y
#pragma unroll
    for (int n = 0; n < DS; n++) h[n] = h0[n];
    for (int tt = 0; tt < TCH; tt++) {
        const size_t ui = (size_t)(tok0 + tt) * DI + d;
        float u = __bfloat162float(uhp[ui]) + __bfloat162float(ulp[ui]);
        float dl = delta_s[tt * 128 + t];
        float du = dl * u;
        const float* row = &dbc_s[tt * 49];
        float yv = 0.f;
        if (uni) {
            float e1 = __expf(dl * Av0);
            float an = 1.f;
#pragma unroll
            for (int n = 0; n < DS; n++) {
                an *= e1;
                h[n] = fmaf(an, h[n], du * row[32 + n]);
                yv = fmaf(h[n], row[40 + n], yv);
            }
        } else {
#pragma unroll
            for (int n = 0; n < DS; n++) {
                float a = __expf(dl * Av[n]);
                h[n] = fmaf(a, h[n], du * row[32 + n]);
                yv = fmaf(h[n], row[40 + n], yv);
            }
        }
        y[(size_t)(tok0 + tt) * DI + d] = fmaf(u, Dd, yv);
    }
}

// ---------------- combine branches, gate, RMSNorm -> bf16 hi/lo ---------------
__global__ void k_rms(const float* __restrict__ yf, const float* __restrict__ yb,
                      const float* __restrict__ xz, const float* __restrict__ rw,
                      __nv_bfloat16* __restrict__ oh, __nv_bfloat16* __restrict__ ol)
{
    int tok  = blockIdx.x * 8 + (threadIdx.x >> 5);
    int lane = threadIdx.x & 31;
    int s    = tok & (LSEQ - 1);
    int rtok = tok - s + (LSEQ - 1 - s);

    float4 v[4];
    float ss = 0.f;
#pragma unroll
    for (int i = 0; i < 4; i++) {
        int d = i * 128 + lane * 4;
        float4 a = *(const float4*)(yf + (size_t)tok * DI + d);
        float4 c = *(const float4*)(yb + (size_t)rtok * DI + d);
        float4 z = *(const float4*)(xz + (size_t)tok * (2 * DI) + DI + d);
        float4 o;
        o.x = 0.5f * (a.x + c.x) * silu(z.x);
        o.y = 0.5f * (a.y + c.y) * silu(z.y);
        o.z = 0.5f * (a.z + c.z) * silu(z.z);
        o.w = 0.5f * (a.w + c.w) * silu(z.w);
        ss += o.x*o.x + o.y*o.y + o.z*o.z + o.w*o.w;
        v[i] = o;
    }
#pragma unroll
    for (int o = 16; o; o >>= 1) ss += __shfl_xor_sync(0xffffffffu, ss, o);
    float sc = rsqrtf(ss * (1.f / DI) + 1e-5f);

#pragma unroll
    for (int i = 0; i < 4; i++) {
        int d = i * 128 + lane * 4;
        float4 w4 = *(const float4*)(rw + d);
        float o4[4];
        o4[0] = v[i].x * sc * w4.x;
        o4[1] = v[i].y * sc * w4.y;
        o4[2] = v[i].z * sc * w4.z;
        o4[3] = v[i].w * sc * w4.w;
        __nv_bfloat16 hh[4], ll[4];
#pragma unroll
        for (int q = 0; q < 4; q++) {
            hh[q] = __float2bfloat16(o4[q]);
            ll[q] = __float2bfloat16(o4[q] - __bfloat162float(hh[q]));
        }
        *(uint2*)(oh + (size_t)tok * DI + d) = *(uint2*)hh;
        *(uint2*)(ol + (size_t)tok * DI + d) = *(uint2*)ll;
    }
}

// ---------------- host launch ----------------
extern "C" void kernel_launch(void* const* d_in, const int* in_sizes, int n_in,
                              void* d_out, int out_size)
{
    const float* x          = (const float*)d_in[0];
    const float* ln_w       = (const float*)d_in[1];
    const float* ln_b       = (const float*)d_in[2];
    const float* in_proj_w  = (const float*)d_in[3];
    const float* conv_w     = (const float*)d_in[4];
    const float* conv_b     = (const float*)d_in[5];
    const float* x_proj_w   = (const float*)d_in[6];
    const float* dt_proj_w  = (const float*)d_in[7];
    const float* dt_proj_b  = (const float*)d_in[8];
    const float* A_log      = (const float*)d_in[9];
    const float* Dp         = (const float*)d_in[10];
    const float* conv_w_b   = (const float*)d_in[11];
    const float* conv_b_b   = (const float*)d_in[12];
    const float* x_proj_w_b = (const float*)d_in[13];
    const float* dt_proj_w_b= (const float*)d_in[14];
    const float* dt_proj_b_b= (const float*)d_in[15];
    const float* A_log_b    = (const float*)d_in[16];
    const float* D_b        = (const float*)d_in[17];
    const float* rms_w      = (const float*)d_in[18];
    const float* out_proj_w = (const float*)d_in[19];
    float* out = (float*)d_out;

    __nv_bfloat16 *lnh, *lnl, *wih, *wil, *woh, *wol, *ynh, *ynl;
    __nv_bfloat16 *xwh0, *xwl0, *xwh1, *xwl1;
    __nv_bfloat16 *uh0, *ul0, *uh1, *ul1;
    float *xz, *dbc0, *dbc1, *y0, *y1;
    float *P0, *Q0, *Hp0, *P1, *Q1, *Hp1;
    int* flags;
    cudaGetSymbolAddress((void**)&lnh,  g_lnh);
    cudaGetSymbolAddress((void**)&lnl,  g_lnl);
    cudaGetSymbolAddress((void**)&wih,  g_wih);
    cudaGetSymbolAddress((void**)&wil,  g_wil);
    cudaGetSymbolAddress((void**)&woh,  g_woh);
    cudaGetSymbolAddress((void**)&wol,  g_wol);
    cudaGetSymbolAddress((void**)&xwh0, g_xwh0);
    cudaGetSymbolAddress((void**)&xwl0, g_xwl0);
    cudaGetSymbolAddress((void**)&xwh1, g_xwh1);
    cudaGetSymbolAddress((void**)&xwl1, g_xwl1);
    cudaGetSymbolAddress((void**)&uh0,  g_uh0);
    cudaGetSymbolAddress((void**)&ul0,  g_ul0);
    cudaGetSymbolAddress((void**)&uh1,  g_uh1);
    cudaGetSymbolAddress((void**)&ul1,  g_ul1);
    cudaGetSymbolAddress((void**)&ynh,  g_ynh);
    cudaGetSymbolAddress((void**)&ynl,  g_ynl);
    cudaGetSymbolAddress((void**)&xz,   g_xz);
    cudaGetSymbolAddress((void**)&dbc0, g_dbc0);
    cudaGetSymbolAddress((void**)&dbc1, g_dbc1);
    cudaGetSymbolAddress((void**)&y0,   g_y0);
    cudaGetSymbolAddress((void**)&y1,   g_y1);
    cudaGetSymbolAddress((void**)&P0,   g_P0);
    cudaGetSymbolAddress((void**)&Q0,   g_Q0);
    cudaGetSymbolAddress((void**)&Hp0,  g_Hp0);
    cudaGetSymbolAddress((void**)&P1,   g_P1);
    cudaGetSymbolAddress((void**)&Q1,   g_Q1);
    cudaGetSymbolAddress((void**)&Hp1,  g_Hp1);
    cudaGetSymbolAddress((void**)&flags, g_flags);

    cudaFuncSetAttribute(k_mma<false>, cudaFuncAttributeMaxDynamicSharedMemorySize, M2_SMEM);
    cudaFuncSetAttribute(k_mma<true>,  cudaFuncAttributeMaxDynamicSharedMemorySize, M2_SMEM);
    cudaFuncSetAttribute(k_xproj, cudaFuncAttributeMaxDynamicSharedMemorySize, XP_SMEM);
    cudaFuncSetAttribute(k_scan, cudaFuncAttributeMaxDynamicSharedMemorySize, SCAN_SMEM);

    // 0. convert weights to bf16 hi/lo (single launch)
    int ncvt = 2*DI*DM + DM*DI + DBCW*DI + DBCW*DI;
    k_cvt4<<<(ncvt + 255)/256, 256>>>(
        in_proj_w, wih, wil, 2*DI*DM,
        out_proj_w, woh, wol, DM*DI,
        x_proj_w,  xwh0, xwl0, DBCW*DI,
        x_proj_w_b, xwh1, xwl1, DBCW*DI);

    // 1. LayerNorm -> bf16 hi/lo
    k_layernorm<<<NTOK / 8, 256>>>(x, ln_w, ln_b, lnh, lnl);

    // 2. in_proj (mma.sync split-bf16, 128x64 tile, 2 CTAs/SM): -> xz fp32
    k_mma<false><<<dim3(2*DI/64, NTOK/128), 256, M2_SMEM>>>(lnh, lnl, wih, wil, xz, 2*DI, nullptr);

    // 3. conv + silu -> u (bf16 hi/lo, scan order, both branches), one pass
    k_conv<<<NTOK * 128 / 256, 256>>>(xz, conv_w, conv_b, conv_w_b, conv_b_b,
                                      uh0, ul0, uh1, ul1);

    // 4. x_proj: pure split-bf16 GEMM on precomputed u
    k_xproj<<<dim3(NTOK/128, 2), 256, XP_SMEM>>>(
        uh0, ul0, uh1, ul1, xwh0, xwl0, xwh1, xwl1, dbc0, dbc1);

    // 5. fused dt_proj + selective scan (decoupled lookback w/ prefix)
    k_zero<<<2, 1024>>>(flags);
    k_scan<<<dim3(DI/128, BATCH, NCH*2), 128, SCAN_SMEM>>>(
        uh0, ul0, uh1, ul1, dbc0, dbc1,
        A_log, A_log_b, dt_proj_w, dt_proj_w_b, dt_proj_b, dt_proj_b_b,
        Dp, D_b, y0, y1, P0, Q0, Hp0, P1, Q1, Hp1, flags);

    // 6. combine + silu(z) gate + RMSNorm -> bf16 hi/lo
    k_rms<<<NTOK / 8, 256>>>(y0, y1, xz, rms_w, ynh, ynl);

    // 7. out_proj (mma.sync split-bf16, 128x64 tile) + residual -> d_out
    k_mma<true><<<dim3(DM/64, NTOK/128), 256, M2_SMEM>>>(ynh, ynl, woh, wol, out, DM, x);
}